// round 1
// baseline (speedup 1.0000x reference)
#include <cuda_runtime.h>
#include <math.h>

// ---------------- problem constants ----------------
#define BB 8
#define LL 4096
#define DD 512
#define TOPK 8
#define NFFT 4096
static const size_t BLD = (size_t)BB * LL * DD;   // 16,777,216 floats

// ---------------- device scratch ----------------
__device__ float g_qn[(size_t)BB * LL * DD];   // q normal layout; reused as agg later
__device__ float g_kn[(size_t)BB * LL * DD];
__device__ float g_qT[(size_t)BB * DD * LL];
__device__ float g_kT[(size_t)BB * DD * LL];
__device__ float g_v [(size_t)BB * LL * DD];
__device__ float2 g_S[BB * NFFT];              // cross-spectrum per batch
__device__ float2 g_tw[NFFT / 2];              // twiddle LUT  W_N^j
__device__ float g_Wc[512 * 1536];             // conv weights re-laid [n][kk*512+i]
__device__ float g_w[BB * TOPK];
__device__ int   g_delay[BB * TOPK];

// ---------------- init kernels ----------------
__global__ void init_tw_kernel() {
    int j = blockIdx.x * 256 + threadIdx.x;
    if (j < NFFT / 2) {
        float s, c;
        sincospif(-2.0f * (float)j / (float)NFFT, &s, &c);
        g_tw[j] = make_float2(c, s);
    }
}

__global__ void build_wc_kernel(const float* __restrict__ Wconv) {
    int idx = blockIdx.x * 256 + threadIdx.x;   // over 512*1536
    if (idx < 512 * 1536) {
        int n = idx / 1536;
        int r = idx - n * 1536;
        int kk = r >> 9;
        int i = r & 511;
        g_Wc[idx] = Wconv[((size_t)n * 512 + i) * 3 + kk];
    }
}

__global__ void zero_S_kernel() {
    int i = blockIdx.x * 256 + threadIdx.x;
    if (i < BB * NFFT) g_S[i] = make_float2(0.f, 0.f);
}

// ---------------- SGEMM: C[m,n] = sum_k A[m,k]*Bw[n,k] (+bias[n]) (+res[m,n]) ----------------
// BM=BN=128, BK=8, 256 threads, 8x8 per thread.
// CONV mode: A is x_w [B,L,512]; logical K=1536 with segment kk in {0,1,2} meaning
// circular row shift t+kk-1 within each batch.
template <bool CONV, bool HAS_BIAS, bool HAS_RES>
__global__ void sgemm_nt(const float* __restrict__ A,
                         const float* __restrict__ Bw,
                         const float* __restrict__ bias,
                         const float* __restrict__ res,
                         float* __restrict__ C,
                         int M, int N, int K) {
    __shared__ float As[8][128];
    __shared__ float Bs[8][128];

    const int tid = threadIdx.x;
    const int m0 = blockIdx.y * 128;
    const int n0 = blockIdx.x * 128;
    const int tx = tid & 15;        // 0..15 -> n
    const int ty = tid >> 4;        // 0..15 -> m

    float acc[8][8];
#pragma unroll
    for (int i = 0; i < 8; ++i)
#pragma unroll
        for (int j = 0; j < 8; ++j) acc[i][j] = 0.f;

    const int lrow = tid >> 1;          // 0..127
    const int lcol = (tid & 1) * 4;     // 0 or 4

    for (int k0 = 0; k0 < K; k0 += 8) {
        // --- load A tile ---
        {
            int m = m0 + lrow;
            int kc = k0 + lcol;
            const float* src;
            if (CONV) {
                int kk = kc >> 9;           // 0..2
                int ii = kc & 511;
                int bidx = m >> 12;         // m / 4096
                int tt = ((m & 4095) + kk - 1) & 4095;
                src = A + (((size_t)(bidx << 12) + tt) << 9) + ii;
            } else {
                src = A + (size_t)m * K + kc;
            }
            float4 v = *(const float4*)src;
            As[lcol + 0][lrow] = v.x;
            As[lcol + 1][lrow] = v.y;
            As[lcol + 2][lrow] = v.z;
            As[lcol + 3][lrow] = v.w;
        }
        // --- load B tile ---
        {
            int n = n0 + lrow;
            int kc = k0 + lcol;
            float4 v = *(const float4*)(Bw + (size_t)n * K + kc);
            Bs[lcol + 0][lrow] = v.x;
            Bs[lcol + 1][lrow] = v.y;
            Bs[lcol + 2][lrow] = v.z;
            Bs[lcol + 3][lrow] = v.w;
        }
        __syncthreads();

#pragma unroll
        for (int kk = 0; kk < 8; ++kk) {
            float4 a0 = *(const float4*)&As[kk][ty * 8];
            float4 a1 = *(const float4*)&As[kk][ty * 8 + 4];
            float4 b0 = *(const float4*)&Bs[kk][tx * 8];
            float4 b1 = *(const float4*)&Bs[kk][tx * 8 + 4];
            float a[8] = {a0.x, a0.y, a0.z, a0.w, a1.x, a1.y, a1.z, a1.w};
            float b[8] = {b0.x, b0.y, b0.z, b0.w, b1.x, b1.y, b1.z, b1.w};
#pragma unroll
            for (int i = 0; i < 8; ++i)
#pragma unroll
                for (int j = 0; j < 8; ++j) acc[i][j] += a[i] * b[j];
        }
        __syncthreads();
    }

#pragma unroll
    for (int i = 0; i < 8; ++i) {
        size_t m = (size_t)(m0 + ty * 8 + i);
        size_t base = m * N + n0 + tx * 8;
#pragma unroll
        for (int j = 0; j < 8; ++j) {
            float cv = acc[i][j];
            if (HAS_BIAS) cv += bias[n0 + tx * 8 + j];
            if (HAS_RES)  cv += res[base + j];
            C[base + j] = cv;
        }
    }
}

// ---------------- transpose [B,L,D] -> [B,D,L] ----------------
__global__ void transpose_kernel(const float* __restrict__ in, float* __restrict__ out) {
    __shared__ float tile[32][33];
    int b = blockIdx.z;
    int l0 = blockIdx.x * 32;
    int d0 = blockIdx.y * 32;
    int x = threadIdx.x, y = threadIdx.y;   // 32 x 8
#pragma unroll
    for (int r = 0; r < 32; r += 8)
        tile[y + r][x] = in[(((size_t)b * LL + l0 + y + r) << 9) + d0 + x];
    __syncthreads();
#pragma unroll
    for (int r = 0; r < 32; r += 8)
        out[(((size_t)b * DD + d0 + y + r) << 12) + l0 + x] = tile[x][y + r];
}

// ---------------- shared radix-2 FFT stages (in-place, bit-reversed input) ----------------
__device__ __forceinline__ void fft_stages(float2* zs, const float2* tw, int tid) {
    for (int s = 1; s <= 12; ++s) {
        int halfm = 1 << (s - 1);
        int shift = 12 - s;
        for (int j = tid; j < 2048; j += 256) {
            int pos = j & (halfm - 1);
            int grp = j >> (s - 1);
            int i0 = (grp << s) + pos;
            int i1 = i0 + halfm;
            float2 w = tw[pos << shift];
            float2 u = zs[i0], v = zs[i1];
            float tr = w.x * v.x - w.y * v.y;
            float ti = w.x * v.y + w.y * v.x;
            zs[i0] = make_float2(u.x + tr, u.y + ti);
            zs[i1] = make_float2(u.x - tr, u.y - ti);
        }
        __syncthreads();
    }
}

// ---------------- cross-spectrum accumulation ----------------
// grid = BB * (DD/8) blocks, 256 threads. Each block: 8 channels of one batch.
// z = q + i*k packed FFT; extract Q,K; accumulate Q*conj(K) into smem, then atomics.
__global__ void fft_cross_kernel() {
    extern __shared__ float2 sm[];
    float2* zs  = sm;            // 4096
    float2* tw  = sm + 4096;     // 2048
    float2* acc = sm + 6144;     // 4096

    int tid = threadIdx.x;
    int b = blockIdx.x >> 6;
    int dg = (blockIdx.x & 63) << 3;

    for (int j = tid; j < 2048; j += 256) tw[j] = g_tw[j];
    for (int f = tid; f < 4096; f += 256) acc[f] = make_float2(0.f, 0.f);

    for (int c = 0; c < 8; ++c) {
        int d = dg + c;
        const float* qrow = g_qT + (((size_t)b * DD + d) << 12);
        const float* krow = g_kT + (((size_t)b * DD + d) << 12);
        __syncthreads();   // previous iter's readers of zs are done
        for (int t = tid; t < 4096; t += 256) {
            int r = (int)(__brev((unsigned)t) >> 20);
            zs[r] = make_float2(qrow[t], krow[t]);
        }
        __syncthreads();
        fft_stages(zs, tw, tid);
        for (int f = tid; f < 4096; f += 256) {
            float2 Zf = zs[f];
            float2 Zc = zs[(4096 - f) & 4095];
            float Qr = 0.5f * (Zf.x + Zc.x);
            float Qi = 0.5f * (Zf.y - Zc.y);
            float Kr = 0.5f * (Zf.y + Zc.y);
            float Ki = 0.5f * (Zc.x - Zf.x);
            float2 a2 = acc[f];
            a2.x += Qr * Kr + Qi * Ki;
            a2.y += Qi * Kr - Qr * Ki;
            acc[f] = a2;
        }
    }
    __syncthreads();
    for (int f = tid; f < 4096; f += 256) {
        atomicAdd(&g_S[(b << 12) + f].x, acc[f].x);
        atomicAdd(&g_S[(b << 12) + f].y, acc[f].y);
    }
}

// ---------------- inverse FFT + top-k + softmax (one block per batch) ----------------
__global__ void ifft_topk_kernel() {
    extern __shared__ float2 sm[];
    float2* zs = sm;                       // 4096
    float2* tw = sm + 4096;                // 2048
    float*  mv = (float*)(sm + 6144);      // 4096 floats

    __shared__ float red_v[256];
    __shared__ int   red_i[256];
    __shared__ float s_tv[TOPK];
    __shared__ int   s_ti[TOPK];

    int tid = threadIdx.x;
    int b = blockIdx.x;

    for (int j = tid; j < 2048; j += 256) tw[j] = g_tw[j];
    for (int f = tid; f < 4096; f += 256) {
        int r = (int)(__brev((unsigned)f) >> 20);
        float2 s = g_S[(b << 12) + f];
        zs[r] = make_float2(s.x, -s.y);    // conj -> IFFT via forward FFT
    }
    __syncthreads();
    fft_stages(zs, tw, tid);

    const float scale = 1.0f / (4096.0f * 512.0f);   // irfft 1/L and mean over H*E
    for (int n = tid; n < 4096; n += 256) mv[n] = zs[n].x * scale;
    __syncthreads();

    for (int it = 0; it < TOPK; ++it) {
        float bv = -3.402823e38f; int bi = 1 << 30;
        for (int n = tid; n < 4096; n += 256) {
            float v = mv[n];
            if (v > bv || (v == bv && n < bi)) { bv = v; bi = n; }
        }
        red_v[tid] = bv; red_i[tid] = bi;
        __syncthreads();
        for (int s = 128; s > 0; s >>= 1) {
            if (tid < s) {
                float v2 = red_v[tid + s]; int i2 = red_i[tid + s];
                if (v2 > red_v[tid] || (v2 == red_v[tid] && i2 < red_i[tid])) {
                    red_v[tid] = v2; red_i[tid] = i2;
                }
            }
            __syncthreads();
        }
        if (tid == 0) {
            s_tv[it] = red_v[0]; s_ti[it] = red_i[0];
            mv[red_i[0]] = -3.402823e38f;
        }
        __syncthreads();
    }

    if (tid == 0) {
        float mx = s_tv[0];
        float ex[TOPK]; float sum = 0.f;
        for (int i = 0; i < TOPK; ++i) { ex[i] = expf(s_tv[i] - mx); sum += ex[i]; }
        for (int i = 0; i < TOPK; ++i) {
            g_w[b * TOPK + i] = ex[i] / sum;
            g_delay[b * TOPK + i] = s_ti[i];
        }
    }
}

// ---------------- time-delay aggregation: agg[b,t,:] = sum_i w_i * v[b,(t+delay_i)%L,:] ----------------
__global__ void aggregate_kernel(const float* __restrict__ v, float* __restrict__ out) {
    size_t idx = (size_t)blockIdx.x * 256 + threadIdx.x;   // over B*L*(D/4)
    int c = (int)(idx & 127);          // float4 column
    size_t row = idx >> 7;             // b*L + t
    int b = (int)(row >> 12);
    int t = (int)(row & 4095);

    float wloc[TOPK]; int dloc[TOPK];
#pragma unroll
    for (int i = 0; i < TOPK; ++i) { wloc[i] = g_w[b * TOPK + i]; dloc[i] = g_delay[b * TOPK + i]; }

    float4 acc = make_float4(0.f, 0.f, 0.f, 0.f);
#pragma unroll
    for (int i = 0; i < TOPK; ++i) {
        int ts = (t + dloc[i]) & 4095;
        const float4 vv = *(const float4*)(v + (((size_t)(b << 12) + ts) << 9) + (c << 2));
        acc.x += wloc[i] * vv.x;
        acc.y += wloc[i] * vv.y;
        acc.z += wloc[i] * vv.z;
        acc.w += wloc[i] * vv.w;
    }
    *(float4*)(out + (row << 9) + (c << 2)) = acc;
}

// ---------------- host launch ----------------
extern "C" void kernel_launch(void* const* d_in, const int* in_sizes, int n_in,
                              void* d_out, int out_size) {
    const float* x_s   = (const float*)d_in[0];
    const float* x_w   = (const float*)d_in[1];
    const float* Wq    = (const float*)d_in[2];
    const float* bq    = (const float*)d_in[3];
    const float* Wk    = (const float*)d_in[4];
    const float* bk    = (const float*)d_in[5];
    const float* Wv    = (const float*)d_in[6];
    const float* bv    = (const float*)d_in[7];
    const float* Wo    = (const float*)d_in[8];
    const float* bo    = (const float*)d_in[9];
    const float* Wconv = (const float*)d_in[10];

    float* out_s = (float*)d_out;          // x_s_out
    float* out_w = out_s + BLD;            // x_w_out

    float *p_qn, *p_kn, *p_qT, *p_kT, *p_v, *p_Wc;
    cudaGetSymbolAddress((void**)&p_qn, g_qn);
    cudaGetSymbolAddress((void**)&p_kn, g_kn);
    cudaGetSymbolAddress((void**)&p_qT, g_qT);
    cudaGetSymbolAddress((void**)&p_kT, g_kT);
    cudaGetSymbolAddress((void**)&p_v,  g_v);
    cudaGetSymbolAddress((void**)&p_Wc, g_Wc);

    cudaFuncSetAttribute(fft_cross_kernel, cudaFuncAttributeMaxDynamicSharedMemorySize, 81920);
    cudaFuncSetAttribute(ifft_topk_kernel, cudaFuncAttributeMaxDynamicSharedMemorySize, 65536);

    // init (cheap, deterministic, re-run every call)
    init_tw_kernel<<<8, 256>>>();
    build_wc_kernel<<<3072, 256>>>(Wconv);
    zero_S_kernel<<<128, 256>>>();

    dim3 gg(4, 256);   // N/128 x M/128
    // q = x_w @ Wq^T + bq ; k/v from x_s
    sgemm_nt<false, true, false><<<gg, 256>>>(x_w, Wq, bq, nullptr, p_qn, BB * LL, DD, DD);
    sgemm_nt<false, true, false><<<gg, 256>>>(x_s, Wk, bk, nullptr, p_kn, BB * LL, DD, DD);
    sgemm_nt<false, true, false><<<gg, 256>>>(x_s, Wv, bv, nullptr, p_v,  BB * LL, DD, DD);

    transpose_kernel<<<dim3(128, 16, 8), dim3(32, 8)>>>(p_qn, p_qT);
    transpose_kernel<<<dim3(128, 16, 8), dim3(32, 8)>>>(p_kn, p_kT);

    fft_cross_kernel<<<512, 256, 81920>>>();
    ifft_topk_kernel<<<8, 256, 65536>>>();

    aggregate_kernel<<<16384, 256>>>(p_v, p_qn);   // reuse g_qn as agg buffer

    // x_s_out = x_s + agg @ Wo^T + bo
    sgemm_nt<false, true, true><<<gg, 256>>>(p_qn, Wo, bo, x_s, out_s, BB * LL, DD, DD);
    // x_w_out = circular conv1d(x_w)  as K=1536 GEMM with shifted-row A loads
    sgemm_nt<true, false, false><<<gg, 256>>>(x_w, p_Wc, nullptr, nullptr, out_w, BB * LL, DD, 1536);
}

// round 3
// speedup vs baseline: 2.3851x; 2.3851x over previous
#include <cuda_runtime.h>
#include <cuda_bf16.h>
#include <math.h>
#include <stdint.h>

// ---------------- problem constants ----------------
#define BB 8
#define LL 4096
#define DD 512
#define TOPK 8
#define NFFT 4096
static const size_t BLD = (size_t)BB * LL * DD;   // 16,777,216

// ---------------- device scratch ----------------
__device__ __nv_bfloat16 g_xs_h[(size_t)BB * LL * DD];
__device__ __nv_bfloat16 g_xs_l[(size_t)BB * LL * DD];
__device__ __nv_bfloat16 g_xw_h[(size_t)BB * LL * DD];
__device__ __nv_bfloat16 g_xw_l[(size_t)BB * LL * DD];
__device__ __nv_bfloat16 g_ag_h[(size_t)BB * LL * DD];
__device__ __nv_bfloat16 g_ag_l[(size_t)BB * LL * DD];
__device__ __nv_bfloat16 g_wq_h[DD * DD], g_wq_l[DD * DD];
__device__ __nv_bfloat16 g_wk_h[DD * DD], g_wk_l[DD * DD];
__device__ __nv_bfloat16 g_wv_h[DD * DD], g_wv_l[DD * DD];
__device__ __nv_bfloat16 g_wo_h[DD * DD], g_wo_l[DD * DD];
__device__ __nv_bfloat16 g_wc_h[DD * 1536], g_wc_l[DD * 1536];
__device__ float g_qT[(size_t)BB * DD * LL];
__device__ float g_kT[(size_t)BB * DD * LL];
__device__ float g_v [(size_t)BB * LL * DD];
__device__ float2 g_S[BB * NFFT];
__device__ float2 g_tw[NFFT / 2];
__device__ float g_w[BB * TOPK];
__device__ int   g_delay[BB * TOPK];

// ---------------- helpers ----------------
__device__ __forceinline__ uint32_t smem_u32(const void* p) {
    uint32_t a;
    asm("{ .reg .u64 t; cvta.to.shared.u64 t, %1; cvt.u32.u64 %0, t; }" : "=r"(a) : "l"(p));
    return a;
}

__device__ __forceinline__ void ldmx4(uint32_t* r, uint32_t addr) {
    asm volatile("ldmatrix.sync.aligned.m8n8.x4.shared.b16 {%0,%1,%2,%3}, [%4];"
                 : "=r"(r[0]), "=r"(r[1]), "=r"(r[2]), "=r"(r[3]) : "r"(addr));
}

__device__ __forceinline__ void mma16816(float* d, const uint32_t* a, uint32_t b0, uint32_t b1) {
    asm volatile(
        "mma.sync.aligned.m16n8k16.row.col.f32.bf16.bf16.f32 "
        "{%0,%1,%2,%3}, {%4,%5,%6,%7}, {%8,%9}, {%0,%1,%2,%3};"
        : "+f"(d[0]), "+f"(d[1]), "+f"(d[2]), "+f"(d[3])
        : "r"(a[0]), "r"(a[1]), "r"(a[2]), "r"(a[3]), "r"(b0), "r"(b1));
}

#define CP_ASYNC16(dst, src) \
    asm volatile("cp.async.cg.shared.global [%0], [%1], 16;" :: "r"(dst), "l"(src))
#define CP_COMMIT() asm volatile("cp.async.commit_group;")
#define CP_WAIT1()  asm volatile("cp.async.wait_group 1;")
#define CP_WAIT0()  asm volatile("cp.async.wait_group 0;")

__device__ __forceinline__ uint32_t sw128(uint32_t off) {
    return off ^ ((off >> 3) & 0x70);
}

// ---------------- init / split kernels ----------------
__global__ void init_tw_kernel() {
    int j = blockIdx.x * 256 + threadIdx.x;
    if (j < NFFT / 2) {
        float s, c;
        sincospif(-2.0f * (float)j / (float)NFFT, &s, &c);
        g_tw[j] = make_float2(c, s);
    }
}

__global__ void zero_S_kernel() {
    int i = blockIdx.x * 256 + threadIdx.x;
    if (i < BB * NFFT) g_S[i] = make_float2(0.f, 0.f);
}

__global__ void split4_kernel(const float4* __restrict__ x,
                              __nv_bfloat162* __restrict__ h,
                              __nv_bfloat162* __restrict__ l, int n4) {
    int i = blockIdx.x * 256 + threadIdx.x;
    if (i >= n4) return;
    float4 v = x[i];
    __nv_bfloat16 hx = __float2bfloat16(v.x), hy = __float2bfloat16(v.y);
    __nv_bfloat16 hz = __float2bfloat16(v.z), hw = __float2bfloat16(v.w);
    h[2 * i]     = __nv_bfloat162(hx, hy);
    h[2 * i + 1] = __nv_bfloat162(hz, hw);
    l[2 * i]     = __nv_bfloat162(__float2bfloat16(v.x - __bfloat162float(hx)),
                                  __float2bfloat16(v.y - __bfloat162float(hy)));
    l[2 * i + 1] = __nv_bfloat162(__float2bfloat16(v.z - __bfloat162float(hz)),
                                  __float2bfloat16(v.w - __bfloat162float(hw)));
}

// conv weights relaid to [n][kk*512+i] and split hi/lo
__global__ void build_wc_kernel(const float* __restrict__ Wconv) {
    int idx = blockIdx.x * 256 + threadIdx.x;   // over 512*1536
    if (idx < 512 * 1536) {
        int n = idx / 1536;
        int r = idx - n * 1536;
        int kk = r >> 9;
        int i = r & 511;
        float w = Wconv[((size_t)n * 512 + i) * 3 + kk];
        __nv_bfloat16 hi = __float2bfloat16(w);
        g_wc_h[idx] = hi;
        g_wc_l[idx] = __float2bfloat16(w - __bfloat162float(hi));
    }
}

// ---------------- mma.sync GEMM ----------------
// C[M=32768, N=512] = A @ B^T with bf16 hi/lo 3-pass split, fp32 accumulate.
// Block tile 128x128, 8 warps (2x4), warp tile 64x32, K chunk = 64 bf16.
// Stage layout: A 128x64 bf16 (16KB, SW128 rows of 128B) + B 128x64 (16KB) = 32KB; 2 stages.
// CONV mode: A rows are circular-shifted x_w rows (512-wide), logical K = 1536.
template <bool CONV>
__device__ __forceinline__ void load_chunk(
    int it, int stage, int KC, int K, int m0, int n0, int tid, uint32_t sbase,
    const __nv_bfloat16* __restrict__ Ah, const __nv_bfloat16* __restrict__ Al,
    const __nv_bfloat16* __restrict__ Bh, const __nv_bfloat16* __restrict__ Bl)
{
    int pass = it / KC;
    int c = it - pass * KC;
    int k0 = c << 6;
    const __nv_bfloat16* Ap = (pass < 2) ? Ah : Al;
    const __nv_bfloat16* Bp = (pass == 1) ? Bl : Bh;
    uint32_t sA = sbase + stage * 32768;
    uint32_t sB = sA + 16384;
#pragma unroll
    for (int i = 0; i < 4; ++i) {     // A: 128 rows x 8 x 16B granules
        int idx = tid + (i << 8);
        int r = idx >> 3, seg = idx & 7;
        const __nv_bfloat16* src;
        if (CONV) {
            int m = m0 + r;
            int kk = k0 >> 9;
            int ii = k0 & 511;
            int bb = m >> 12;
            int tt = ((m & 4095) + kk + 4095) & 4095;   // t + kk - 1 mod L
            src = Ap + (((size_t)(bb << 12) + tt) << 9) + ii + (seg << 3);
        } else {
            src = Ap + ((size_t)(m0 + r) << 9) + k0 + (seg << 3);
        }
        CP_ASYNC16(sA + sw128((r << 7) + (seg << 4)), src);
    }
#pragma unroll
    for (int i = 0; i < 4; ++i) {     // B: 128 rows x 8 x 16B granules
        int idx = tid + (i << 8);
        int r = idx >> 3, seg = idx & 7;
        const __nv_bfloat16* src = Bp + (size_t)(n0 + r) * K + k0 + (seg << 3);
        CP_ASYNC16(sB + sw128((r << 7) + (seg << 4)), src);
    }
    CP_COMMIT();
}

template <int TOUT, bool HAS_BIAS, bool HAS_RES, bool CONV>
__global__ void __launch_bounds__(256, 2) mma_gemm(
    const __nv_bfloat16* __restrict__ Ah, const __nv_bfloat16* __restrict__ Al,
    const __nv_bfloat16* __restrict__ Bh, const __nv_bfloat16* __restrict__ Bl,
    const float* __restrict__ bias, const float* __restrict__ res,
    float* __restrict__ C, int K)
{
    extern __shared__ char smraw[];
    uint32_t sbase = (smem_u32(smraw) + 1023u) & ~1023u;

    const int tid = threadIdx.x;
    const int wid = tid >> 5;
    const int lane = tid & 31;
    const int wm = wid >> 2;    // 0..1 -> m offset 64*wm
    const int wn = wid & 3;     // 0..3 -> n offset 32*wn
    const int m0 = blockIdx.y << 7;
    const int n0 = blockIdx.x << 7;
    const int KC = K >> 6;
    const int T = 3 * KC;

    float acc[4][4][4];
#pragma unroll
    for (int i = 0; i < 4; ++i)
#pragma unroll
        for (int j = 0; j < 4; ++j)
#pragma unroll
            for (int r = 0; r < 4; ++r) acc[i][j][r] = 0.f;

    load_chunk<CONV>(0, 0, KC, K, m0, n0, tid, sbase, Ah, Al, Bh, Bl);
    load_chunk<CONV>(1, 1, KC, K, m0, n0, tid, sbase, Ah, Al, Bh, Bl);

    const int lrow = lane & 15;
    const int lseg = lane >> 4;

    for (int it = 0; it < T; ++it) {
        int s = it & 1;
        if (it + 1 < T) { CP_WAIT1(); } else { CP_WAIT0(); }
        __syncthreads();

        uint32_t sA = sbase + s * 32768;
        uint32_t sB = sA + 16384;
#pragma unroll
        for (int ks = 0; ks < 4; ++ks) {
            int cseg = (ks << 1) + lseg;
            uint32_t a[4][4];
            uint32_t b2[2][4];
#pragma unroll
            for (int mt = 0; mt < 4; ++mt) {
                int row = (wm << 6) + (mt << 4) + lrow;
                ldmx4(a[mt], sA + sw128((row << 7) + (cseg << 4)));
            }
#pragma unroll
            for (int bt = 0; bt < 2; ++bt) {
                int row = (wn << 5) + (bt << 4) + lrow;
                ldmx4(b2[bt], sB + sw128((row << 7) + (cseg << 4)));
            }
#pragma unroll
            for (int mt = 0; mt < 4; ++mt)
#pragma unroll
                for (int nt = 0; nt < 4; ++nt)
                    mma16816(acc[mt][nt], a[mt],
                             b2[nt >> 1][nt & 1], b2[nt >> 1][(nt & 1) + 2]);
        }
        __syncthreads();
        if (it + 2 < T)
            load_chunk<CONV>(it + 2, s, KC, K, m0, n0, tid, sbase, Ah, Al, Bh, Bl);
    }

    // ---------------- epilogue ----------------
    const int er = lane >> 2;            // 0..7
    const int ec = (lane & 3) << 1;      // 0,2,4,6
#pragma unroll
    for (int mt = 0; mt < 4; ++mt) {
#pragma unroll
        for (int nt = 0; nt < 4; ++nt) {
            int r0 = m0 + (wm << 6) + (mt << 4) + er;
            int r1 = r0 + 8;
            int c0 = n0 + (wn << 5) + (nt << 3) + ec;
            float v0 = acc[mt][nt][0], v1 = acc[mt][nt][1];
            float v2 = acc[mt][nt][2], v3 = acc[mt][nt][3];
            if (HAS_BIAS) {
                float b0 = bias[c0], b1 = bias[c0 + 1];
                v0 += b0; v1 += b1; v2 += b0; v3 += b1;
            }
            if (TOUT == 1) {
                // transposed write into [B, D, L]
                int b0i = r0 >> 12, l0 = r0 & 4095;
                int b1i = r1 >> 12, l1 = r1 & 4095;
                C[(((size_t)(b0i << 9) + c0)     << 12) + l0] = v0;
                C[(((size_t)(b0i << 9) + c0 + 1) << 12) + l0] = v1;
                C[(((size_t)(b1i << 9) + c0)     << 12) + l1] = v2;
                C[(((size_t)(b1i << 9) + c0 + 1) << 12) + l1] = v3;
            } else {
                size_t o0 = ((size_t)r0 << 9) + c0;
                size_t o1 = ((size_t)r1 << 9) + c0;
                if (HAS_RES) {
                    const float2 q0 = *(const float2*)&res[o0];
                    const float2 q1 = *(const float2*)&res[o1];
                    v0 += q0.x; v1 += q0.y; v2 += q1.x; v3 += q1.y;
                }
                *(float2*)&C[o0] = make_float2(v0, v1);
                *(float2*)&C[o1] = make_float2(v2, v3);
            }
        }
    }
}

// ---------------- shared radix-2 FFT stages ----------------
__device__ __forceinline__ void fft_stages(float2* zs, const float2* tw, int tid) {
    for (int s = 1; s <= 12; ++s) {
        int halfm = 1 << (s - 1);
        int shift = 12 - s;
        for (int j = tid; j < 2048; j += 256) {
            int pos = j & (halfm - 1);
            int grp = j >> (s - 1);
            int i0 = (grp << s) + pos;
            int i1 = i0 + halfm;
            float2 w = tw[pos << shift];
            float2 u = zs[i0], v = zs[i1];
            float tr = w.x * v.x - w.y * v.y;
            float ti = w.x * v.y + w.y * v.x;
            zs[i0] = make_float2(u.x + tr, u.y + ti);
            zs[i1] = make_float2(u.x - tr, u.y - ti);
        }
        __syncthreads();
    }
}

// ---------------- cross-spectrum accumulation ----------------
__global__ void fft_cross_kernel() {
    extern __shared__ float2 sm[];
    float2* zs  = sm;            // 4096
    float2* tw  = sm + 4096;     // 2048
    float2* acc = sm + 6144;     // 4096

    int tid = threadIdx.x;
    int b = blockIdx.x >> 6;
    int dg = (blockIdx.x & 63) << 3;

    for (int j = tid; j < 2048; j += 256) tw[j] = g_tw[j];
    for (int f = tid; f < 4096; f += 256) acc[f] = make_float2(0.f, 0.f);

    for (int c = 0; c < 8; ++c) {
        int d = dg + c;
        const float* qrow = g_qT + (((size_t)b * DD + d) << 12);
        const float* krow = g_kT + (((size_t)b * DD + d) << 12);
        __syncthreads();
        for (int t = tid; t < 4096; t += 256) {
            int r = (int)(__brev((unsigned)t) >> 20);
            zs[r] = make_float2(qrow[t], krow[t]);
        }
        __syncthreads();
        fft_stages(zs, tw, tid);
        for (int f = tid; f < 4096; f += 256) {
            float2 Zf = zs[f];
            float2 Zc = zs[(4096 - f) & 4095];
            float Qr = 0.5f * (Zf.x + Zc.x);
            float Qi = 0.5f * (Zf.y - Zc.y);
            float Kr = 0.5f * (Zf.y + Zc.y);
            float Ki = 0.5f * (Zc.x - Zf.x);
            float2 a2 = acc[f];
            a2.x += Qr * Kr + Qi * Ki;
            a2.y += Qi * Kr - Qr * Ki;
            acc[f] = a2;
        }
    }
    __syncthreads();
    for (int f = tid; f < 4096; f += 256) {
        atomicAdd(&g_S[(b << 12) + f].x, acc[f].x);
        atomicAdd(&g_S[(b << 12) + f].y, acc[f].y);
    }
}

// ---------------- inverse FFT + top-k + softmax ----------------
__global__ void ifft_topk_kernel() {
    extern __shared__ float2 sm[];
    float2* zs = sm;                       // 4096
    float2* tw = sm + 4096;                // 2048
    float*  mv = (float*)(sm + 6144);      // 4096

    __shared__ float red_v[256];
    __shared__ int   red_i[256];
    __shared__ float s_tv[TOPK];
    __shared__ int   s_ti[TOPK];

    int tid = threadIdx.x;
    int b = blockIdx.x;

    for (int j = tid; j < 2048; j += 256) tw[j] = g_tw[j];
    for (int f = tid; f < 4096; f += 256) {
        int r = (int)(__brev((unsigned)f) >> 20);
        float2 s = g_S[(b << 12) + f];
        zs[r] = make_float2(s.x, -s.y);
    }
    __syncthreads();
    fft_stages(zs, tw, tid);

    const float scale = 1.0f / (4096.0f * 512.0f);
    for (int n = tid; n < 4096; n += 256) mv[n] = zs[n].x * scale;
    __syncthreads();

    for (int it = 0; it < TOPK; ++it) {
        float bv = -3.402823e38f; int bi = 1 << 30;
        for (int n = tid; n < 4096; n += 256) {
            float v = mv[n];
            if (v > bv || (v == bv && n < bi)) { bv = v; bi = n; }
        }
        red_v[tid] = bv; red_i[tid] = bi;
        __syncthreads();
        for (int s = 128; s > 0; s >>= 1) {
            if (tid < s) {
                float v2 = red_v[tid + s]; int i2 = red_i[tid + s];
                if (v2 > red_v[tid] || (v2 == red_v[tid] && i2 < red_i[tid])) {
                    red_v[tid] = v2; red_i[tid] = i2;
                }
            }
            __syncthreads();
        }
        if (tid == 0) {
            s_tv[it] = red_v[0]; s_ti[it] = red_i[0];
            mv[red_i[0]] = -3.402823e38f;
        }
        __syncthreads();
    }

    if (tid == 0) {
        float mx = s_tv[0];
        float ex[TOPK]; float sum = 0.f;
        for (int i = 0; i < TOPK; ++i) { ex[i] = expf(s_tv[i] - mx); sum += ex[i]; }
        for (int i = 0; i < TOPK; ++i) {
            g_w[b * TOPK + i] = ex[i] / sum;
            g_delay[b * TOPK + i] = s_ti[i];
        }
    }
}

// ---------------- aggregation (fused hi/lo split output) ----------------
__global__ void aggregate_kernel(const float* __restrict__ v,
                                 __nv_bfloat162* __restrict__ oh,
                                 __nv_bfloat162* __restrict__ ol) {
    size_t idx = (size_t)blockIdx.x * 256 + threadIdx.x;   // over B*L*(D/4)
    int c = (int)(idx & 127);
    size_t row = idx >> 7;
    int b = (int)(row >> 12);
    int t = (int)(row & 4095);

    float wloc[TOPK]; int dloc[TOPK];
#pragma unroll
    for (int i = 0; i < TOPK; ++i) { wloc[i] = g_w[b * TOPK + i]; dloc[i] = g_delay[b * TOPK + i]; }

    float4 acc = make_float4(0.f, 0.f, 0.f, 0.f);
#pragma unroll
    for (int i = 0; i < TOPK; ++i) {
        int ts = (t + dloc[i]) & 4095;
        const float4 vv = *(const float4*)(v + (((size_t)(b << 12) + ts) << 9) + (c << 2));
        acc.x += wloc[i] * vv.x;
        acc.y += wloc[i] * vv.y;
        acc.z += wloc[i] * vv.z;
        acc.w += wloc[i] * vv.w;
    }
    __nv_bfloat16 hx = __float2bfloat16(acc.x), hy = __float2bfloat16(acc.y);
    __nv_bfloat16 hz = __float2bfloat16(acc.z), hw = __float2bfloat16(acc.w);
    size_t p = (row << 8) + (c << 1);
    oh[p]     = __nv_bfloat162(hx, hy);
    oh[p + 1] = __nv_bfloat162(hz, hw);
    ol[p]     = __nv_bfloat162(__float2bfloat16(acc.x - __bfloat162float(hx)),
                               __float2bfloat16(acc.y - __bfloat162float(hy)));
    ol[p + 1] = __nv_bfloat162(__float2bfloat16(acc.z - __bfloat162float(hz)),
                               __float2bfloat16(acc.w - __bfloat162float(hw)));
}

// ---------------- host launch ----------------
extern "C" void kernel_launch(void* const* d_in, const int* in_sizes, int n_in,
                              void* d_out, int out_size) {
    const float* x_s   = (const float*)d_in[0];
    const float* x_w   = (const float*)d_in[1];
    const float* Wq    = (const float*)d_in[2];
    const float* bq    = (const float*)d_in[3];
    const float* Wk    = (const float*)d_in[4];
    const float* bk    = (const float*)d_in[5];
    const float* Wv    = (const float*)d_in[6];
    const float* bv    = (const float*)d_in[7];
    const float* Wo    = (const float*)d_in[8];
    const float* bo    = (const float*)d_in[9];
    const float* Wconv = (const float*)d_in[10];

    float* out_s = (float*)d_out;
    float* out_w = out_s + BLD;

    void *p_xs_h, *p_xs_l, *p_xw_h, *p_xw_l, *p_ag_h, *p_ag_l;
    void *p_wq_h, *p_wq_l, *p_wk_h, *p_wk_l, *p_wv_h, *p_wv_l, *p_wo_h, *p_wo_l;
    void *p_wc_h, *p_wc_l, *p_qT, *p_kT, *p_v;
    cudaGetSymbolAddress(&p_xs_h, g_xs_h); cudaGetSymbolAddress(&p_xs_l, g_xs_l);
    cudaGetSymbolAddress(&p_xw_h, g_xw_h); cudaGetSymbolAddress(&p_xw_l, g_xw_l);
    cudaGetSymbolAddress(&p_ag_h, g_ag_h); cudaGetSymbolAddress(&p_ag_l, g_ag_l);
    cudaGetSymbolAddress(&p_wq_h, g_wq_h); cudaGetSymbolAddress(&p_wq_l, g_wq_l);
    cudaGetSymbolAddress(&p_wk_h, g_wk_h); cudaGetSymbolAddress(&p_wk_l, g_wk_l);
    cudaGetSymbolAddress(&p_wv_h, g_wv_h); cudaGetSymbolAddress(&p_wv_l, g_wv_l);
    cudaGetSymbolAddress(&p_wo_h, g_wo_h); cudaGetSymbolAddress(&p_wo_l, g_wo_l);
    cudaGetSymbolAddress(&p_wc_h, g_wc_h); cudaGetSymbolAddress(&p_wc_l, g_wc_l);
    cudaGetSymbolAddress(&p_qT, g_qT); cudaGetSymbolAddress(&p_kT, g_kT);
    cudaGetSymbolAddress(&p_v, g_v);

    const int SMEM_DYN = 64 * 1024 + 1024;
    cudaFuncSetAttribute(mma_gemm<1, true,  false, false>, cudaFuncAttributeMaxDynamicSharedMemorySize, SMEM_DYN);
    cudaFuncSetAttribute(mma_gemm<0, true,  false, false>, cudaFuncAttributeMaxDynamicSharedMemorySize, SMEM_DYN);
    cudaFuncSetAttribute(mma_gemm<0, true,  true,  false>, cudaFuncAttributeMaxDynamicSharedMemorySize, SMEM_DYN);
    cudaFuncSetAttribute(mma_gemm<0, false, false, true >, cudaFuncAttributeMaxDynamicSharedMemorySize, SMEM_DYN);
    cudaFuncSetAttribute(fft_cross_kernel, cudaFuncAttributeMaxDynamicSharedMemorySize, 81920);
    cudaFuncSetAttribute(ifft_topk_kernel, cudaFuncAttributeMaxDynamicSharedMemorySize, 65536);

    // init + splits
    init_tw_kernel<<<8, 256>>>();
    zero_S_kernel<<<128, 256>>>();
    split4_kernel<<<16384, 256>>>((const float4*)x_s, (__nv_bfloat162*)p_xs_h, (__nv_bfloat162*)p_xs_l, 4194304);
    split4_kernel<<<16384, 256>>>((const float4*)x_w, (__nv_bfloat162*)p_xw_h, (__nv_bfloat162*)p_xw_l, 4194304);
    split4_kernel<<<256, 256>>>((const float4*)Wq, (__nv_bfloat162*)p_wq_h, (__nv_bfloat162*)p_wq_l, 65536);
    split4_kernel<<<256, 256>>>((const float4*)Wk, (__nv_bfloat162*)p_wk_h, (__nv_bfloat162*)p_wk_l, 65536);
    split4_kernel<<<256, 256>>>((const float4*)Wv, (__nv_bfloat162*)p_wv_h, (__nv_bfloat162*)p_wv_l, 65536);
    split4_kernel<<<256, 256>>>((const float4*)Wo, (__nv_bfloat162*)p_wo_h, (__nv_bfloat162*)p_wo_l, 65536);
    build_wc_kernel<<<3072, 256>>>(Wconv);

    dim3 gg(4, 256);   // N/128 x M/128
    // q = x_w @ Wq^T + bq  (transposed output -> [B,D,L])
    mma_gemm<1, true, false, false><<<gg, 256, SMEM_DYN>>>(
        (const __nv_bfloat16*)p_xw_h, (const __nv_bfloat16*)p_xw_l,
        (const __nv_bfloat16*)p_wq_h, (const __nv_bfloat16*)p_wq_l,
        bq, nullptr, (float*)p_qT, 512);
    // k = x_s @ Wk^T + bk  (transposed)
    mma_gemm<1, true, false, false><<<gg, 256, SMEM_DYN>>>(
        (const __nv_bfloat16*)p_xs_h, (const __nv_bfloat16*)p_xs_l,
        (const __nv_bfloat16*)p_wk_h, (const __nv_bfloat16*)p_wk_l,
        bk, nullptr, (float*)p_kT, 512);
    // v = x_s @ Wv^T + bv  (normal)
    mma_gemm<0, true, false, false><<<gg, 256, SMEM_DYN>>>(
        (const __nv_bfloat16*)p_xs_h, (const __nv_bfloat16*)p_xs_l,
        (const __nv_bfloat16*)p_wv_h, (const __nv_bfloat16*)p_wv_l,
        bv, nullptr, (float*)p_v, 512);

    fft_cross_kernel<<<512, 256, 81920>>>();
    ifft_topk_kernel<<<8, 256, 65536>>>();

    aggregate_kernel<<<16384, 256>>>((const float*)p_v, (__nv_bfloat162*)p_ag_h, (__nv_bfloat162*)p_ag_l);

    // x_s_out = x_s + agg @ Wo^T + bo
    mma_gemm<0, true, true, false><<<gg, 256, SMEM_DYN>>>(
        (const __nv_bfloat16*)p_ag_h, (const __nv_bfloat16*)p_ag_l,
        (const __nv_bfloat16*)p_wo_h, (const __nv_bfloat16*)p_wo_l,
        bo, x_s, out_s, 512);
    // x_w_out = circular conv1d(x_w) as K=1536 GEMM
    mma_gemm<0, false, false, true><<<gg, 256, SMEM_DYN>>>(
        (const __nv_bfloat16*)p_xw_h, (const __nv_bfloat16*)p_xw_l,
        (const __nv_bfloat16*)p_wc_h, (const __nv_bfloat16*)p_wc_l,
        nullptr, nullptr, out_w, 1536);
}

// round 4
// speedup vs baseline: 2.7779x; 1.1647x over previous
#include <cuda_runtime.h>
#include <cuda_bf16.h>
#include <math.h>
#include <stdint.h>

// ---------------- problem constants ----------------
#define BB 8
#define LL 4096
#define DD 512
#define TOPK 8
#define NFFT 4096
static const size_t BLD = (size_t)BB * LL * DD;   // 16,777,216

// ---------------- device scratch ----------------
__device__ __nv_bfloat16 g_xs_h[(size_t)BB * LL * DD];
__device__ __nv_bfloat16 g_xs_l[(size_t)BB * LL * DD];
__device__ __nv_bfloat16 g_xw_h[(size_t)BB * LL * DD];
__device__ __nv_bfloat16 g_xw_l[(size_t)BB * LL * DD];
__device__ __nv_bfloat16 g_ag_h[(size_t)BB * LL * DD];
__device__ __nv_bfloat16 g_ag_l[(size_t)BB * LL * DD];
__device__ __nv_bfloat16 g_wq_h[DD * DD], g_wq_l[DD * DD];
__device__ __nv_bfloat16 g_wk_h[DD * DD], g_wk_l[DD * DD];
__device__ __nv_bfloat16 g_wcb_h[DD * DD], g_wcb_l[DD * DD];
__device__ __nv_bfloat16 g_wc_h[DD * 1536], g_wc_l[DD * 1536];
__device__ float g_wcomb[DD * DD];     // Wo @ Wv (fp32)
__device__ float g_bcomb[DD];          // Wo @ bv + bo
__device__ float g_qT[(size_t)BB * DD * LL];
__device__ float g_kT[(size_t)BB * DD * LL];
__device__ float2 g_S[BB * NFFT];
__device__ float2 g_tw[NFFT / 2];
__device__ float g_w[BB * TOPK];
__device__ int   g_delay[BB * TOPK];

// ---------------- helpers ----------------
__device__ __forceinline__ uint32_t smem_u32(const void* p) {
    uint32_t a;
    asm("{ .reg .u64 t; cvta.to.shared.u64 t, %1; cvt.u32.u64 %0, t; }" : "=r"(a) : "l"(p));
    return a;
}

__device__ __forceinline__ void ldmx4(uint32_t* r, uint32_t addr) {
    asm volatile("ldmatrix.sync.aligned.m8n8.x4.shared.b16 {%0,%1,%2,%3}, [%4];"
                 : "=r"(r[0]), "=r"(r[1]), "=r"(r[2]), "=r"(r[3]) : "r"(addr));
}

__device__ __forceinline__ void mma16816(float* d, const uint32_t* a, uint32_t b0, uint32_t b1) {
    asm volatile(
        "mma.sync.aligned.m16n8k16.row.col.f32.bf16.bf16.f32 "
        "{%0,%1,%2,%3}, {%4,%5,%6,%7}, {%8,%9}, {%0,%1,%2,%3};"
        : "+f"(d[0]), "+f"(d[1]), "+f"(d[2]), "+f"(d[3])
        : "r"(a[0]), "r"(a[1]), "r"(a[2]), "r"(a[3]), "r"(b0), "r"(b1));
}

#define CP_ASYNC16(dst, src) \
    asm volatile("cp.async.cg.shared.global [%0], [%1], 16;" :: "r"(dst), "l"(src))
#define CP_COMMIT() asm volatile("cp.async.commit_group;")
#define CP_WAIT2()  asm volatile("cp.async.wait_group 2;")
#define CP_WAIT1()  asm volatile("cp.async.wait_group 1;")
#define CP_WAIT0()  asm volatile("cp.async.wait_group 0;")

__device__ __forceinline__ uint32_t sw128(uint32_t off) {
    return off ^ ((off >> 3) & 0x70);
}

// ---------------- init kernels ----------------
__global__ void init_tw_kernel() {
    int j = blockIdx.x * 256 + threadIdx.x;
    if (j < NFFT / 2) {
        float s, c;
        sincospif(-2.0f * (float)j / (float)NFFT, &s, &c);
        g_tw[j] = make_float2(c, s);
    }
}

__global__ void zero_S_kernel() {
    int i = blockIdx.x * 256 + threadIdx.x;
    if (i < BB * NFFT) g_S[i] = make_float2(0.f, 0.f);
}

// ---------------- Wcomb = Wo @ Wv (fp32 exact) ----------------
__global__ void wcomb_gemm(const float* __restrict__ Wo, const float* __restrict__ Wv) {
    __shared__ float As[32][33], Bs[32][33];
    int bi = blockIdx.y * 32, bj = blockIdx.x * 32;
    int tx = threadIdx.x, ty = threadIdx.y;   // 16 x 16
    float a00 = 0.f, a01 = 0.f, a10 = 0.f, a11 = 0.f;
    for (int m0 = 0; m0 < 512; m0 += 32) {
        for (int r = ty; r < 32; r += 16) {
            As[r][tx]      = Wo[(bi + r) * 512 + m0 + tx];
            As[r][tx + 16] = Wo[(bi + r) * 512 + m0 + tx + 16];
            Bs[r][tx]      = Wv[(m0 + r) * 512 + bj + tx];
            Bs[r][tx + 16] = Wv[(m0 + r) * 512 + bj + tx + 16];
        }
        __syncthreads();
#pragma unroll
        for (int m = 0; m < 32; ++m) {
            float x0 = As[ty][m], x1 = As[ty + 16][m];
            float y0 = Bs[m][tx], y1 = Bs[m][tx + 16];
            a00 += x0 * y0; a01 += x0 * y1; a10 += x1 * y0; a11 += x1 * y1;
        }
        __syncthreads();
    }
    g_wcomb[(bi + ty) * 512 + bj + tx]           = a00;
    g_wcomb[(bi + ty) * 512 + bj + tx + 16]      = a01;
    g_wcomb[(bi + ty + 16) * 512 + bj + tx]      = a10;
    g_wcomb[(bi + ty + 16) * 512 + bj + tx + 16] = a11;
}

__global__ void bcomb_kernel(const float* __restrict__ Wo,
                             const float* __restrict__ bv,
                             const float* __restrict__ bo) {
    int i = blockIdx.x * 256 + threadIdx.x;
    if (i < 512) {
        float s = bo[i];
        for (int m = 0; m < 512; ++m) s += Wo[i * 512 + m] * bv[m];
        g_bcomb[i] = s;
    }
}

// ---------------- mega split: all hi/lo splits + conv-weight relay ----------------
__device__ __forceinline__ void split_one4(const float4* __restrict__ x,
                                           __nv_bfloat162* __restrict__ h,
                                           __nv_bfloat162* __restrict__ l, int i) {
    float4 v = x[i];
    __nv_bfloat16 hx = __float2bfloat16(v.x), hy = __float2bfloat16(v.y);
    __nv_bfloat16 hz = __float2bfloat16(v.z), hw = __float2bfloat16(v.w);
    h[2 * i]     = __nv_bfloat162(hx, hy);
    h[2 * i + 1] = __nv_bfloat162(hz, hw);
    l[2 * i]     = __nv_bfloat162(__float2bfloat16(v.x - __bfloat162float(hx)),
                                  __float2bfloat16(v.y - __bfloat162float(hy)));
    l[2 * i + 1] = __nv_bfloat162(__float2bfloat16(v.z - __bfloat162float(hz)),
                                  __float2bfloat16(v.w - __bfloat162float(hw)));
}

__global__ void mega_split_kernel(const float4* __restrict__ xs,
                                  const float4* __restrict__ xw,
                                  const float4* __restrict__ Wq,
                                  const float4* __restrict__ Wk,
                                  const float* __restrict__ Wconv) {
    int bid = blockIdx.x;
    int tid = threadIdx.x;
    if (bid < 16384) {
        split_one4(xs, (__nv_bfloat162*)g_xs_h, (__nv_bfloat162*)g_xs_l, bid * 256 + tid);
    } else if (bid < 32768) {
        split_one4(xw, (__nv_bfloat162*)g_xw_h, (__nv_bfloat162*)g_xw_l, (bid - 16384) * 256 + tid);
    } else if (bid < 33024) {
        split_one4(Wq, (__nv_bfloat162*)g_wq_h, (__nv_bfloat162*)g_wq_l, (bid - 32768) * 256 + tid);
    } else if (bid < 33280) {
        split_one4(Wk, (__nv_bfloat162*)g_wk_h, (__nv_bfloat162*)g_wk_l, (bid - 33024) * 256 + tid);
    } else if (bid < 33536) {
        split_one4((const float4*)g_wcomb, (__nv_bfloat162*)g_wcb_h, (__nv_bfloat162*)g_wcb_l,
                   (bid - 33280) * 256 + tid);
    } else {
        int idx = (bid - 33536) * 256 + tid;     // over 512*1536
        int n = idx / 1536;
        int r = idx - n * 1536;
        int kk = r >> 9;
        int i = r & 511;
        float w = Wconv[((size_t)n * 512 + i) * 3 + kk];
        __nv_bfloat16 hi = __float2bfloat16(w);
        g_wc_h[idx] = hi;
        g_wc_l[idx] = __float2bfloat16(w - __bfloat162float(hi));
    }
}

// ---------------- mma.sync GEMM (3-stage pipeline) ----------------
template <bool CONV>
__device__ __forceinline__ void load_chunk(
    int it, int stage, int KC, int K, int m0, int n0, int tid, uint32_t sbase,
    const __nv_bfloat16* __restrict__ Ah, const __nv_bfloat16* __restrict__ Al,
    const __nv_bfloat16* __restrict__ Bh, const __nv_bfloat16* __restrict__ Bl)
{
    int pass = it / KC;
    int c = it - pass * KC;
    int k0 = c << 6;
    const __nv_bfloat16* Ap = (pass < 2) ? Ah : Al;
    const __nv_bfloat16* Bp = (pass == 1) ? Bl : Bh;
    uint32_t sA = sbase + stage * 32768;
    uint32_t sB = sA + 16384;
#pragma unroll
    for (int i = 0; i < 4; ++i) {     // A: 128 rows x 8 x 16B granules
        int idx = tid + (i << 8);
        int r = idx >> 3, seg = idx & 7;
        const __nv_bfloat16* src;
        if (CONV) {
            int m = m0 + r;
            int kk = k0 >> 9;
            int ii = k0 & 511;
            int bb = m >> 12;
            int tt = ((m & 4095) + kk + 4095) & 4095;   // t + kk - 1 mod L
            src = Ap + (((size_t)(bb << 12) + tt) << 9) + ii + (seg << 3);
        } else {
            src = Ap + ((size_t)(m0 + r) << 9) + k0 + (seg << 3);
        }
        CP_ASYNC16(sA + sw128((r << 7) + (seg << 4)), src);
    }
#pragma unroll
    for (int i = 0; i < 4; ++i) {     // B: 128 rows x 8 x 16B granules
        int idx = tid + (i << 8);
        int r = idx >> 3, seg = idx & 7;
        const __nv_bfloat16* src = Bp + (size_t)(n0 + r) * K + k0 + (seg << 3);
        CP_ASYNC16(sB + sw128((r << 7) + (seg << 4)), src);
    }
    CP_COMMIT();
}

template <int TOUT, bool HAS_BIAS, bool HAS_RES, bool CONV>
__global__ void __launch_bounds__(256, 2) mma_gemm(
    const __nv_bfloat16* __restrict__ Ah, const __nv_bfloat16* __restrict__ Al,
    const __nv_bfloat16* __restrict__ Bh, const __nv_bfloat16* __restrict__ Bl,
    const float* __restrict__ bias, const float* __restrict__ res,
    float* __restrict__ C, int K)
{
    extern __shared__ char smraw[];
    uint32_t sbase = (smem_u32(smraw) + 1023u) & ~1023u;

    const int tid = threadIdx.x;
    const int wid = tid >> 5;
    const int lane = tid & 31;
    const int wm = wid >> 2;    // 0..1 -> m offset 64*wm
    const int wn = wid & 3;     // 0..3 -> n offset 32*wn
    const int m0 = blockIdx.y << 7;
    const int n0 = blockIdx.x << 7;
    const int KC = K >> 6;
    const int T = 3 * KC;

    float acc[4][4][4];
#pragma unroll
    for (int i = 0; i < 4; ++i)
#pragma unroll
        for (int j = 0; j < 4; ++j)
#pragma unroll
            for (int r = 0; r < 4; ++r) acc[i][j][r] = 0.f;

    load_chunk<CONV>(0, 0, KC, K, m0, n0, tid, sbase, Ah, Al, Bh, Bl);
    load_chunk<CONV>(1, 1, KC, K, m0, n0, tid, sbase, Ah, Al, Bh, Bl);
    load_chunk<CONV>(2, 2, KC, K, m0, n0, tid, sbase, Ah, Al, Bh, Bl);

    const int lrow = lane & 15;
    const int lseg = lane >> 4;

    int s = 0;
    for (int it = 0; it < T; ++it) {
        int rem = T - 1 - it;
        if (rem >= 2) { CP_WAIT2(); } else if (rem == 1) { CP_WAIT1(); } else { CP_WAIT0(); }
        __syncthreads();

        uint32_t sA = sbase + s * 32768;
        uint32_t sB = sA + 16384;
#pragma unroll
        for (int ks = 0; ks < 4; ++ks) {
            int cseg = (ks << 1) + lseg;
            uint32_t a[4][4];
            uint32_t b2[2][4];
#pragma unroll
            for (int mt = 0; mt < 4; ++mt) {
                int row = (wm << 6) + (mt << 4) + lrow;
                ldmx4(a[mt], sA + sw128((row << 7) + (cseg << 4)));
            }
#pragma unroll
            for (int bt = 0; bt < 2; ++bt) {
                int row = (wn << 5) + (bt << 4) + lrow;
                ldmx4(b2[bt], sB + sw128((row << 7) + (cseg << 4)));
            }
#pragma unroll
            for (int mt = 0; mt < 4; ++mt)
#pragma unroll
                for (int nt = 0; nt < 4; ++nt)
                    mma16816(acc[mt][nt], a[mt],
                             b2[nt >> 1][nt & 1], b2[nt >> 1][(nt & 1) + 2]);
        }
        __syncthreads();
        if (it + 3 < T)
            load_chunk<CONV>(it + 3, s, KC, K, m0, n0, tid, sbase, Ah, Al, Bh, Bl);
        s = (s == 2) ? 0 : s + 1;
    }

    // ---------------- epilogue ----------------
    const int er = lane >> 2;            // 0..7
    const int ec = (lane & 3) << 1;      // 0,2,4,6
#pragma unroll
    for (int mt = 0; mt < 4; ++mt) {
#pragma unroll
        for (int nt = 0; nt < 4; ++nt) {
            int r0 = m0 + (wm << 6) + (mt << 4) + er;
            int r1 = r0 + 8;
            int c0 = n0 + (wn << 5) + (nt << 3) + ec;
            float v0 = acc[mt][nt][0], v1 = acc[mt][nt][1];
            float v2 = acc[mt][nt][2], v3 = acc[mt][nt][3];
            if (HAS_BIAS) {
                float b0 = bias[c0], b1 = bias[c0 + 1];
                v0 += b0; v1 += b1; v2 += b0; v3 += b1;
            }
            if (TOUT == 1) {
                // transposed write into [B, D, L]
                int b0i = r0 >> 12, l0 = r0 & 4095;
                int b1i = r1 >> 12, l1 = r1 & 4095;
                C[(((size_t)(b0i << 9) + c0)     << 12) + l0] = v0;
                C[(((size_t)(b0i << 9) + c0 + 1) << 12) + l0] = v1;
                C[(((size_t)(b1i << 9) + c0)     << 12) + l1] = v2;
                C[(((size_t)(b1i << 9) + c0 + 1) << 12) + l1] = v3;
            } else {
                size_t o0 = ((size_t)r0 << 9) + c0;
                size_t o1 = ((size_t)r1 << 9) + c0;
                if (HAS_RES) {
                    const float2 q0 = *(const float2*)&res[o0];
                    const float2 q1 = *(const float2*)&res[o1];
                    v0 += q0.x; v1 += q0.y; v2 += q1.x; v3 += q1.y;
                }
                *(float2*)&C[o0] = make_float2(v0, v1);
                *(float2*)&C[o1] = make_float2(v2, v3);
            }
        }
    }
}

// ---------------- fused radix-4 FFT stages (6 passes over 12 radix-2 stages) ----------------
__device__ __forceinline__ float2 cmulf(float2 w, float2 z) {
    return make_float2(w.x * z.x - w.y * z.y, w.x * z.y + w.y * z.x);
}

__device__ __forceinline__ void fft_stages_r4(float2* zs, const float2* tw, int tid) {
#pragma unroll
    for (int p = 0; p < 6; ++p) {
        const int h = 1 << (2 * p);
#pragma unroll
        for (int jj = 0; jj < 4; ++jj) {
            int j = tid + (jj << 8);
            int pos = j & (h - 1);
            int grp = j >> (2 * p);
            int base = (grp << (2 * p + 2)) + pos;
            float2 a = zs[base], b = zs[base + h], c = zs[base + 2 * h], d = zs[base + 3 * h];
            float2 w1 = tw[pos << (11 - 2 * p)];
            float2 w2 = tw[pos << (10 - 2 * p)];
            float2 wb = cmulf(w1, b), wd = cmulf(w1, d);
            float2 a1 = make_float2(a.x + wb.x, a.y + wb.y);
            float2 b1 = make_float2(a.x - wb.x, a.y - wb.y);
            float2 c1 = make_float2(c.x + wd.x, c.y + wd.y);
            float2 d1 = make_float2(c.x - wd.x, c.y - wd.y);
            float2 wc2 = cmulf(w2, c1), wd2 = cmulf(w2, d1);
            zs[base]         = make_float2(a1.x + wc2.x, a1.y + wc2.y);
            zs[base + 2 * h] = make_float2(a1.x - wc2.x, a1.y - wc2.y);
            zs[base + h]     = make_float2(b1.x + wd2.y, b1.y - wd2.x);   // b1 + (-i)wd2
            zs[base + 3 * h] = make_float2(b1.x - wd2.y, b1.y + wd2.x);   // b1 - (-i)wd2
        }
        __syncthreads();
    }
}

// ---------------- cross-spectrum accumulation ----------------
__global__ void fft_cross_kernel() {
    extern __shared__ float2 sm[];
    float2* zs  = sm;            // 4096
    float2* tw  = sm + 4096;     // 2048
    float2* acc = sm + 6144;     // 4096

    int tid = threadIdx.x;
    int b = blockIdx.x >> 6;
    int dg = (blockIdx.x & 63) << 3;

    for (int j = tid; j < 2048; j += 256) tw[j] = g_tw[j];
    for (int f = tid; f < 4096; f += 256) acc[f] = make_float2(0.f, 0.f);

    for (int c = 0; c < 8; ++c) {
        int d = dg + c;
        const float* qrow = g_qT + (((size_t)b * DD + d) << 12);
        const float* krow = g_kT + (((size_t)b * DD + d) << 12);
        __syncthreads();
        for (int t = tid; t < 4096; t += 256) {
            int r = (int)(__brev((unsigned)t) >> 20);
            zs[r] = make_float2(qrow[t], krow[t]);
        }
        __syncthreads();
        fft_stages_r4(zs, tw, tid);
        for (int f = tid; f < 4096; f += 256) {
            float2 Zf = zs[f];
            float2 Zc = zs[(4096 - f) & 4095];
            float Qr = 0.5f * (Zf.x + Zc.x);
            float Qi = 0.5f * (Zf.y - Zc.y);
            float Kr = 0.5f * (Zf.y + Zc.y);
            float Ki = 0.5f * (Zc.x - Zf.x);
            float2 a2 = acc[f];
            a2.x += Qr * Kr + Qi * Ki;
            a2.y += Qi * Kr - Qr * Ki;
            acc[f] = a2;
        }
    }
    __syncthreads();
    for (int f = tid; f < 4096; f += 256) {
        atomicAdd(&g_S[(b << 12) + f].x, acc[f].x);
        atomicAdd(&g_S[(b << 12) + f].y, acc[f].y);
    }
}

// ---------------- inverse FFT + top-k + softmax ----------------
__global__ void ifft_topk_kernel() {
    extern __shared__ float2 sm[];
    float2* zs = sm;                       // 4096
    float2* tw = sm + 4096;                // 2048
    float*  mv = (float*)(sm + 6144);      // 4096

    __shared__ float red_v[256];
    __shared__ int   red_i[256];
    __shared__ float s_tv[TOPK];
    __shared__ int   s_ti[TOPK];

    int tid = threadIdx.x;
    int b = blockIdx.x;

    for (int j = tid; j < 2048; j += 256) tw[j] = g_tw[j];
    for (int f = tid; f < 4096; f += 256) {
        int r = (int)(__brev((unsigned)f) >> 20);
        float2 s = g_S[(b << 12) + f];
        zs[r] = make_float2(s.x, -s.y);
    }
    __syncthreads();
    fft_stages_r4(zs, tw, tid);

    const float scale = 1.0f / (4096.0f * 512.0f);
    for (int n = tid; n < 4096; n += 256) mv[n] = zs[n].x * scale;
    __syncthreads();

    for (int it = 0; it < TOPK; ++it) {
        float bv = -3.402823e38f; int bi = 1 << 30;
        for (int n = tid; n < 4096; n += 256) {
            float v = mv[n];
            if (v > bv || (v == bv && n < bi)) { bv = v; bi = n; }
        }
        red_v[tid] = bv; red_i[tid] = bi;
        __syncthreads();
        for (int s = 128; s > 0; s >>= 1) {
            if (tid < s) {
                float v2 = red_v[tid + s]; int i2 = red_i[tid + s];
                if (v2 > red_v[tid] || (v2 == red_v[tid] && i2 < red_i[tid])) {
                    red_v[tid] = v2; red_i[tid] = i2;
                }
            }
            __syncthreads();
        }
        if (tid == 0) {
            s_tv[it] = red_v[0]; s_ti[it] = red_i[0];
            mv[red_i[0]] = -3.402823e38f;
        }
        __syncthreads();
    }

    if (tid == 0) {
        float mx = s_tv[0];
        float ex[TOPK]; float sum = 0.f;
        for (int i = 0; i < TOPK; ++i) { ex[i] = expf(s_tv[i] - mx); sum += ex[i]; }
        for (int i = 0; i < TOPK; ++i) {
            g_w[b * TOPK + i] = ex[i] / sum;
            g_delay[b * TOPK + i] = s_ti[i];
        }
    }
}

// ---------------- aggregation on x_s (pre-projection; fused hi/lo split output) ----------------
__global__ void aggregate_kernel(const float* __restrict__ v,
                                 __nv_bfloat162* __restrict__ oh,
                                 __nv_bfloat162* __restrict__ ol) {
    size_t idx = (size_t)blockIdx.x * 256 + threadIdx.x;   // over B*L*(D/4)
    int c = (int)(idx & 127);
    size_t row = idx >> 7;
    int b = (int)(row >> 12);
    int t = (int)(row & 4095);

    float wloc[TOPK]; int dloc[TOPK];
#pragma unroll
    for (int i = 0; i < TOPK; ++i) { wloc[i] = g_w[b * TOPK + i]; dloc[i] = g_delay[b * TOPK + i]; }

    float4 acc = make_float4(0.f, 0.f, 0.f, 0.f);
#pragma unroll
    for (int i = 0; i < TOPK; ++i) {
        int ts = (t + dloc[i]) & 4095;
        const float4 vv = *(const float4*)(v + (((size_t)(b << 12) + ts) << 9) + (c << 2));
        acc.x += wloc[i] * vv.x;
        acc.y += wloc[i] * vv.y;
        acc.z += wloc[i] * vv.z;
        acc.w += wloc[i] * vv.w;
    }
    __nv_bfloat16 hx = __float2bfloat16(acc.x), hy = __float2bfloat16(acc.y);
    __nv_bfloat16 hz = __float2bfloat16(acc.z), hw = __float2bfloat16(acc.w);
    size_t p = (row << 8) + (c << 1);
    oh[p]     = __nv_bfloat162(hx, hy);
    oh[p + 1] = __nv_bfloat162(hz, hw);
    ol[p]     = __nv_bfloat162(__float2bfloat16(acc.x - __bfloat162float(hx)),
                               __float2bfloat16(acc.y - __bfloat162float(hy)));
    ol[p + 1] = __nv_bfloat162(__float2bfloat16(acc.z - __bfloat162float(hz)),
                               __float2bfloat16(acc.w - __bfloat162float(hw)));
}

// ---------------- host launch ----------------
extern "C" void kernel_launch(void* const* d_in, const int* in_sizes, int n_in,
                              void* d_out, int out_size) {
    const float* x_s   = (const float*)d_in[0];
    const float* x_w   = (const float*)d_in[1];
    const float* Wq    = (const float*)d_in[2];
    const float* bq    = (const float*)d_in[3];
    const float* Wk    = (const float*)d_in[4];
    const float* bk    = (const float*)d_in[5];
    const float* Wv    = (const float*)d_in[6];
    const float* bv    = (const float*)d_in[7];
    const float* Wo    = (const float*)d_in[8];
    const float* bo    = (const float*)d_in[9];
    const float* Wconv = (const float*)d_in[10];

    float* out_s = (float*)d_out;
    float* out_w = out_s + BLD;

    void *p_xs_h, *p_xs_l, *p_xw_h, *p_xw_l, *p_ag_h, *p_ag_l;
    void *p_wq_h, *p_wq_l, *p_wk_h, *p_wk_l, *p_wcb_h, *p_wcb_l;
    void *p_wc_h, *p_wc_l, *p_qT, *p_kT, *p_bcomb;
    cudaGetSymbolAddress(&p_xs_h, g_xs_h); cudaGetSymbolAddress(&p_xs_l, g_xs_l);
    cudaGetSymbolAddress(&p_xw_h, g_xw_h); cudaGetSymbolAddress(&p_xw_l, g_xw_l);
    cudaGetSymbolAddress(&p_ag_h, g_ag_h); cudaGetSymbolAddress(&p_ag_l, g_ag_l);
    cudaGetSymbolAddress(&p_wq_h, g_wq_h); cudaGetSymbolAddress(&p_wq_l, g_wq_l);
    cudaGetSymbolAddress(&p_wk_h, g_wk_h); cudaGetSymbolAddress(&p_wk_l, g_wk_l);
    cudaGetSymbolAddress(&p_wcb_h, g_wcb_h); cudaGetSymbolAddress(&p_wcb_l, g_wcb_l);
    cudaGetSymbolAddress(&p_wc_h, g_wc_h); cudaGetSymbolAddress(&p_wc_l, g_wc_l);
    cudaGetSymbolAddress(&p_qT, g_qT); cudaGetSymbolAddress(&p_kT, g_kT);
    cudaGetSymbolAddress(&p_bcomb, g_bcomb);

    const int SMEM_DYN = 3 * 32768 + 1024;
    cudaFuncSetAttribute(mma_gemm<1, true,  false, false>, cudaFuncAttributeMaxDynamicSharedMemorySize, SMEM_DYN);
    cudaFuncSetAttribute(mma_gemm<0, true,  true,  false>, cudaFuncAttributeMaxDynamicSharedMemorySize, SMEM_DYN);
    cudaFuncSetAttribute(mma_gemm<0, false, false, true >, cudaFuncAttributeMaxDynamicSharedMemorySize, SMEM_DYN);
    cudaFuncSetAttribute(fft_cross_kernel, cudaFuncAttributeMaxDynamicSharedMemorySize, 81920);
    cudaFuncSetAttribute(ifft_topk_kernel, cudaFuncAttributeMaxDynamicSharedMemorySize, 65536);

    // 1-5: init + weight combine + splits
    init_tw_kernel<<<8, 256>>>();
    zero_S_kernel<<<128, 256>>>();
    wcomb_gemm<<<dim3(16, 16), dim3(16, 16)>>>(Wo, Wv);
    bcomb_kernel<<<2, 256>>>(Wo, bv, bo);
    mega_split_kernel<<<36608, 256>>>((const float4*)x_s, (const float4*)x_w,
                                      (const float4*)Wq, (const float4*)Wk, Wconv);

    dim3 gg(4, 256);   // N/128 x M/128
    // 6: q = x_w @ Wq^T + bq  (transposed output -> [B,D,L])   <- ncu -s 5 captures this
    mma_gemm<1, true, false, false><<<gg, 256, SMEM_DYN>>>(
        (const __nv_bfloat16*)p_xw_h, (const __nv_bfloat16*)p_xw_l,
        (const __nv_bfloat16*)p_wq_h, (const __nv_bfloat16*)p_wq_l,
        bq, nullptr, (float*)p_qT, 512);
    // 7: k = x_s @ Wk^T + bk  (transposed)
    mma_gemm<1, true, false, false><<<gg, 256, SMEM_DYN>>>(
        (const __nv_bfloat16*)p_xs_h, (const __nv_bfloat16*)p_xs_l,
        (const __nv_bfloat16*)p_wk_h, (const __nv_bfloat16*)p_wk_l,
        bk, nullptr, (float*)p_kT, 512);

    // 8-9: correlation spectrum + top-k delays
    fft_cross_kernel<<<512, 256, 81920>>>();
    ifft_topk_kernel<<<8, 256, 65536>>>();

    // 10: aggregate x_s by delays (V/O projections commute with the convex roll combo)
    aggregate_kernel<<<16384, 256>>>(x_s, (__nv_bfloat162*)p_ag_h, (__nv_bfloat162*)p_ag_l);

    // 11: x_s_out = x_s + xagg @ (Wo Wv)^T + (Wo bv + bo)
    mma_gemm<0, true, true, false><<<gg, 256, SMEM_DYN>>>(
        (const __nv_bfloat16*)p_ag_h, (const __nv_bfloat16*)p_ag_l,
        (const __nv_bfloat16*)p_wcb_h, (const __nv_bfloat16*)p_wcb_l,
        (const float*)p_bcomb, x_s, out_s, 512);
    // 12: x_w_out = circular conv1d(x_w) as K=1536 GEMM
    mma_gemm<0, false, false, true><<<gg, 256, SMEM_DYN>>>(
        (const __nv_bfloat16*)p_xw_h, (const __nv_bfloat16*)p_xw_l,
        (const __nv_bfloat16*)p_wc_h, (const __nv_bfloat16*)p_wc_l,
        nullptr, nullptr, out_w, 1536);
}

// round 5
// speedup vs baseline: 2.8951x; 1.0422x over previous
#include <cuda_runtime.h>
#include <cuda_bf16.h>
#include <math.h>
#include <stdint.h>

// ---------------- problem constants ----------------
#define BB 8
#define LL 4096
#define DD 512
#define TOPK 8
#define NFFT 4096
static const size_t BLD = (size_t)BB * LL * DD;   // 16,777,216

// ---------------- device scratch ----------------
__device__ __nv_bfloat16 g_xs_h[(size_t)BB * LL * DD];
__device__ __nv_bfloat16 g_xs_l[(size_t)BB * LL * DD];
__device__ __nv_bfloat16 g_xw_h[(size_t)BB * LL * DD];
__device__ __nv_bfloat16 g_xw_l[(size_t)BB * LL * DD];
__device__ __nv_bfloat16 g_ag_h[(size_t)BB * LL * DD];
__device__ __nv_bfloat16 g_ag_l[(size_t)BB * LL * DD];
__device__ __nv_bfloat16 g_wq_h[DD * DD], g_wq_l[DD * DD];
__device__ __nv_bfloat16 g_wk_h[DD * DD], g_wk_l[DD * DD];
__device__ __nv_bfloat16 g_wcb_h[DD * DD], g_wcb_l[DD * DD];
__device__ __nv_bfloat16 g_wc_h[DD * 1536], g_wc_l[DD * 1536];
__device__ float g_wcomb[DD * DD];     // Wo @ Wv (fp32)
__device__ float g_bcomb[DD];          // Wo @ bv + bo
__device__ float g_qT[(size_t)BB * DD * LL];
__device__ float g_kT[(size_t)BB * DD * LL];
__device__ float2 g_S[BB * NFFT];
__device__ float2 g_tw[NFFT / 2];
__device__ float g_w[BB * TOPK];
__device__ int   g_delay[BB * TOPK];

// ---------------- helpers ----------------
__device__ __forceinline__ uint32_t smem_u32(const void* p) {
    uint32_t a;
    asm("{ .reg .u64 t; cvta.to.shared.u64 t, %1; cvt.u32.u64 %0, t; }" : "=r"(a) : "l"(p));
    return a;
}

__device__ __forceinline__ void ldmx4(uint32_t* r, uint32_t addr) {
    asm volatile("ldmatrix.sync.aligned.m8n8.x4.shared.b16 {%0,%1,%2,%3}, [%4];"
                 : "=r"(r[0]), "=r"(r[1]), "=r"(r[2]), "=r"(r[3]) : "r"(addr));
}

__device__ __forceinline__ void mma16816(float* d, const uint32_t* a, uint32_t b0, uint32_t b1) {
    asm volatile(
        "mma.sync.aligned.m16n8k16.row.col.f32.bf16.bf16.f32 "
        "{%0,%1,%2,%3}, {%4,%5,%6,%7}, {%8,%9}, {%0,%1,%2,%3};"
        : "+f"(d[0]), "+f"(d[1]), "+f"(d[2]), "+f"(d[3])
        : "r"(a[0]), "r"(a[1]), "r"(a[2]), "r"(a[3]), "r"(b0), "r"(b1));
}

#define CP_ASYNC16(dst, src) \
    asm volatile("cp.async.cg.shared.global [%0], [%1], 16;" :: "r"(dst), "l"(src))
#define CP_COMMIT() asm volatile("cp.async.commit_group;")
#define CP_WAIT2()  asm volatile("cp.async.wait_group 2;")
#define CP_WAIT1()  asm volatile("cp.async.wait_group 1;")
#define CP_WAIT0()  asm volatile("cp.async.wait_group 0;")

// 64-byte-row swizzle (Swizzle<2,4,3>): XOR bits[5:4] with bits[8:7]
__device__ __forceinline__ uint32_t sw64(uint32_t off) {
    return off ^ ((off >> 3) & 0x30);
}

// ---------------- init kernels ----------------
__global__ void init_tw_kernel() {
    int j = blockIdx.x * 256 + threadIdx.x;
    if (j < NFFT / 2) {
        float s, c;
        sincospif(-2.0f * (float)j / (float)NFFT, &s, &c);
        g_tw[j] = make_float2(c, s);
    }
}

__global__ void zero_S_kernel() {
    int i = blockIdx.x * 256 + threadIdx.x;
    if (i < BB * NFFT) g_S[i] = make_float2(0.f, 0.f);
}

// ---------------- Wcomb = Wo @ Wv (fp32 exact) ----------------
__global__ void wcomb_gemm(const float* __restrict__ Wo, const float* __restrict__ Wv) {
    __shared__ float As[32][33], Bs[32][33];
    int bi = blockIdx.y * 32, bj = blockIdx.x * 32;
    int tx = threadIdx.x, ty = threadIdx.y;   // 16 x 16
    float a00 = 0.f, a01 = 0.f, a10 = 0.f, a11 = 0.f;
    for (int m0 = 0; m0 < 512; m0 += 32) {
        for (int r = ty; r < 32; r += 16) {
            As[r][tx]      = Wo[(bi + r) * 512 + m0 + tx];
            As[r][tx + 16] = Wo[(bi + r) * 512 + m0 + tx + 16];
            Bs[r][tx]      = Wv[(m0 + r) * 512 + bj + tx];
            Bs[r][tx + 16] = Wv[(m0 + r) * 512 + bj + tx + 16];
        }
        __syncthreads();
#pragma unroll
        for (int m = 0; m < 32; ++m) {
            float x0 = As[ty][m], x1 = As[ty + 16][m];
            float y0 = Bs[m][tx], y1 = Bs[m][tx + 16];
            a00 += x0 * y0; a01 += x0 * y1; a10 += x1 * y0; a11 += x1 * y1;
        }
        __syncthreads();
    }
    g_wcomb[(bi + ty) * 512 + bj + tx]           = a00;
    g_wcomb[(bi + ty) * 512 + bj + tx + 16]      = a01;
    g_wcomb[(bi + ty + 16) * 512 + bj + tx]      = a10;
    g_wcomb[(bi + ty + 16) * 512 + bj + tx + 16] = a11;
}

// warp-per-output reduction: g_bcomb[i] = bo[i] + sum_m Wo[i,m]*bv[m]
__global__ void bcomb_kernel(const float* __restrict__ Wo,
                             const float* __restrict__ bv,
                             const float* __restrict__ bo) {
    int o = blockIdx.x * 8 + (threadIdx.x >> 5);
    int lane = threadIdx.x & 31;
    float s = 0.f;
    for (int m = lane; m < 512; m += 32) s += Wo[o * 512 + m] * bv[m];
#pragma unroll
    for (int off = 16; off; off >>= 1) s += __shfl_xor_sync(0xFFFFFFFFu, s, off);
    if (lane == 0) g_bcomb[o] = s + bo[o];
}

// ---------------- mega split: all hi/lo splits + conv-weight relay ----------------
__device__ __forceinline__ void split_one4(const float4* __restrict__ x,
                                           __nv_bfloat162* __restrict__ h,
                                           __nv_bfloat162* __restrict__ l, int i) {
    float4 v = x[i];
    __nv_bfloat16 hx = __float2bfloat16(v.x), hy = __float2bfloat16(v.y);
    __nv_bfloat16 hz = __float2bfloat16(v.z), hw = __float2bfloat16(v.w);
    h[2 * i]     = __nv_bfloat162(hx, hy);
    h[2 * i + 1] = __nv_bfloat162(hz, hw);
    l[2 * i]     = __nv_bfloat162(__float2bfloat16(v.x - __bfloat162float(hx)),
                                  __float2bfloat16(v.y - __bfloat162float(hy)));
    l[2 * i + 1] = __nv_bfloat162(__float2bfloat16(v.z - __bfloat162float(hz)),
                                  __float2bfloat16(v.w - __bfloat162float(hw)));
}

__global__ void mega_split_kernel(const float4* __restrict__ xs,
                                  const float4* __restrict__ xw,
                                  const float4* __restrict__ Wq,
                                  const float4* __restrict__ Wk,
                                  const float* __restrict__ Wconv) {
    int bid = blockIdx.x;
    int tid = threadIdx.x;
    if (bid < 16384) {
        split_one4(xs, (__nv_bfloat162*)g_xs_h, (__nv_bfloat162*)g_xs_l, bid * 256 + tid);
    } else if (bid < 32768) {
        split_one4(xw, (__nv_bfloat162*)g_xw_h, (__nv_bfloat162*)g_xw_l, (bid - 16384) * 256 + tid);
    } else if (bid < 33024) {
        split_one4(Wq, (__nv_bfloat162*)g_wq_h, (__nv_bfloat162*)g_wq_l, (bid - 32768) * 256 + tid);
    } else if (bid < 33280) {
        split_one4(Wk, (__nv_bfloat162*)g_wk_h, (__nv_bfloat162*)g_wk_l, (bid - 33024) * 256 + tid);
    } else if (bid < 33536) {
        split_one4((const float4*)g_wcomb, (__nv_bfloat162*)g_wcb_h, (__nv_bfloat162*)g_wcb_l,
                   (bid - 33280) * 256 + tid);
    } else {
        int idx = (bid - 33536) * 256 + tid;     // over 512*1536
        int n = idx / 1536;
        int r = idx - n * 1536;
        int kk = r >> 9;
        int i = r & 511;
        float w = Wconv[((size_t)n * 512 + i) * 3 + kk];
        __nv_bfloat16 hi = __float2bfloat16(w);
        g_wc_h[idx] = hi;
        g_wc_l[idx] = __float2bfloat16(w - __bfloat162float(hi));
    }
}

// ---------------- mma.sync GEMM (fused 3-product chunks, 3-stage pipeline) ----------------
// K chunk = 32 bf16 = 64B rows. Stage layout (32KB):
//   sAh +0 (8KB), sAl +8192, sBh +16384, sBl +24576.
template <bool CONV>
__device__ __forceinline__ void load_chunk(
    int ch, int stage, int K, int m0, int n0, int tid, uint32_t sbase,
    const __nv_bfloat16* __restrict__ Ah, const __nv_bfloat16* __restrict__ Al,
    const __nv_bfloat16* __restrict__ Bh, const __nv_bfloat16* __restrict__ Bl)
{
    int k0 = ch << 5;
    uint32_t st = sbase + stage * 32768;
    // A: 2 pieces (hi/lo) x 128 rows x 4 segs(16B) = 1024 granules
#pragma unroll
    for (int i = 0; i < 4; ++i) {
        int idx = tid + (i << 8);
        int piece = idx >> 9;
        int rem = idx & 511;
        int r = rem >> 2, seg = rem & 3;
        const __nv_bfloat16* Ap = piece ? Al : Ah;
        const __nv_bfloat16* src;
        if (CONV) {
            int m = m0 + r;
            int kk = k0 >> 9;
            int ii = k0 & 511;
            int bb = m >> 12;
            int tt = ((m & 4095) + kk + 4095) & 4095;   // t + kk - 1 mod L
            src = Ap + (((size_t)(bb << 12) + tt) << 9) + ii + (seg << 3);
        } else {
            src = Ap + ((size_t)(m0 + r) << 9) + k0 + (seg << 3);
        }
        CP_ASYNC16(st + piece * 8192 + sw64((r << 6) + (seg << 4)), src);
    }
    // B: 2 pieces x 128 rows x 4 segs
#pragma unroll
    for (int i = 0; i < 4; ++i) {
        int idx = tid + (i << 8);
        int piece = idx >> 9;
        int rem = idx & 511;
        int r = rem >> 2, seg = rem & 3;
        const __nv_bfloat16* Bp = piece ? Bl : Bh;
        const __nv_bfloat16* src = Bp + (size_t)(n0 + r) * K + k0 + (seg << 3);
        CP_ASYNC16(st + 16384 + piece * 8192 + sw64((r << 6) + (seg << 4)), src);
    }
    CP_COMMIT();
}

template <int TOUT, bool HAS_BIAS, bool HAS_RES, bool CONV>
__global__ void __launch_bounds__(256, 2) mma_gemm(
    const __nv_bfloat16* __restrict__ Ah, const __nv_bfloat16* __restrict__ Al,
    const __nv_bfloat16* __restrict__ Bh, const __nv_bfloat16* __restrict__ Bl,
    const float* __restrict__ bias, const float* __restrict__ res,
    float* __restrict__ C, int K)
{
    extern __shared__ char smraw[];
    uint32_t sbase = (smem_u32(smraw) + 1023u) & ~1023u;

    const int tid = threadIdx.x;
    const int wid = tid >> 5;
    const int lane = tid & 31;
    const int wm = wid >> 2;    // 0..1 -> m offset 64*wm
    const int wn = wid & 3;     // 0..3 -> n offset 32*wn
    const int m0 = blockIdx.y << 7;
    const int n0 = blockIdx.x << 7;
    const int T = K >> 5;       // logical K (1536 for conv) / 32

    float acc[4][4][4];
#pragma unroll
    for (int i = 0; i < 4; ++i)
#pragma unroll
        for (int j = 0; j < 4; ++j)
#pragma unroll
            for (int r = 0; r < 4; ++r) acc[i][j][r] = 0.f;

    load_chunk<CONV>(0, 0, K, m0, n0, tid, sbase, Ah, Al, Bh, Bl);
    load_chunk<CONV>(1, 1, K, m0, n0, tid, sbase, Ah, Al, Bh, Bl);
    load_chunk<CONV>(2, 2, K, m0, n0, tid, sbase, Ah, Al, Bh, Bl);

    const int lrow = lane & 15;
    const int lseg = lane >> 4;

    int s = 0;
    for (int it = 0; it < T; ++it) {
        int rem = T - 1 - it;
        if (rem >= 2) { CP_WAIT2(); } else if (rem == 1) { CP_WAIT1(); } else { CP_WAIT0(); }
        __syncthreads();

        uint32_t st = sbase + s * 32768;
#pragma unroll
        for (int ks = 0; ks < 2; ++ks) {
            int cseg = (ks << 1) + lseg;
            uint32_t ah[4][4], al[4][4], b2[2][4];
#pragma unroll
            for (int mt = 0; mt < 4; ++mt) {
                int row = (wm << 6) + (mt << 4) + lrow;
                ldmx4(ah[mt], st + sw64((row << 6) + (cseg << 4)));
            }
#pragma unroll
            for (int bt = 0; bt < 2; ++bt) {
                int row = (wn << 5) + (bt << 4) + lrow;
                ldmx4(b2[bt], st + 16384 + sw64((row << 6) + (cseg << 4)));
            }
#pragma unroll
            for (int mt = 0; mt < 4; ++mt)
#pragma unroll
                for (int nt = 0; nt < 4; ++nt)
                    mma16816(acc[mt][nt], ah[mt],
                             b2[nt >> 1][nt & 1], b2[nt >> 1][(nt & 1) + 2]);
#pragma unroll
            for (int mt = 0; mt < 4; ++mt) {
                int row = (wm << 6) + (mt << 4) + lrow;
                ldmx4(al[mt], st + 8192 + sw64((row << 6) + (cseg << 4)));
            }
#pragma unroll
            for (int mt = 0; mt < 4; ++mt)
#pragma unroll
                for (int nt = 0; nt < 4; ++nt)
                    mma16816(acc[mt][nt], al[mt],
                             b2[nt >> 1][nt & 1], b2[nt >> 1][(nt & 1) + 2]);
#pragma unroll
            for (int bt = 0; bt < 2; ++bt) {
                int row = (wn << 5) + (bt << 4) + lrow;
                ldmx4(b2[bt], st + 24576 + sw64((row << 6) + (cseg << 4)));
            }
#pragma unroll
            for (int mt = 0; mt < 4; ++mt)
#pragma unroll
                for (int nt = 0; nt < 4; ++nt)
                    mma16816(acc[mt][nt], ah[mt],
                             b2[nt >> 1][nt & 1], b2[nt >> 1][(nt & 1) + 2]);
        }
        __syncthreads();
        if (it + 3 < T)
            load_chunk<CONV>(it + 3, s, K, m0, n0, tid, sbase, Ah, Al, Bh, Bl);
        s = (s == 2) ? 0 : s + 1;
    }

    // ---------------- epilogue ----------------
    const int er = lane >> 2;            // 0..7
    const int ec = (lane & 3) << 1;      // 0,2,4,6
    if (TOUT == 1) {
        // transpose through smem, then coalesced rows into [B, D, L]
        float* st = (float*)(size_t)(smraw + ((sbase + 1023u) - smem_u32(smraw) & 0u));
        float* stf = (float*)smraw;   // reuse pipeline smem (raw base is fine for fp32)
#pragma unroll
        for (int mt = 0; mt < 4; ++mt)
#pragma unroll
            for (int nt = 0; nt < 4; ++nt) {
                int r0 = (wm << 6) + (mt << 4) + er;
                int c0 = (wn << 5) + (nt << 3) + ec;
                stf[c0 * 130 + r0]            = acc[mt][nt][0];
                stf[(c0 + 1) * 130 + r0]      = acc[mt][nt][1];
                stf[c0 * 130 + r0 + 8]        = acc[mt][nt][2];
                stf[(c0 + 1) * 130 + r0 + 8]  = acc[mt][nt][3];
            }
        __syncthreads();
        int bb = m0 >> 12, l0 = m0 & 4095;
#pragma unroll
        for (int i = 0; i < 16; ++i) {
            int idx = tid + (i << 8);
            int c = idx >> 5;            // 0..127
            int rq = (idx & 31) << 2;    // 0..124 step 4
            float4 v;
            v.x = stf[c * 130 + rq];
            v.y = stf[c * 130 + rq + 1];
            v.z = stf[c * 130 + rq + 2];
            v.w = stf[c * 130 + rq + 3];
            if (HAS_BIAS) {
                float bval = bias[n0 + c];
                v.x += bval; v.y += bval; v.z += bval; v.w += bval;
            }
            *(float4*)&C[(((size_t)(bb << 9) + n0 + c) << 12) + l0 + rq] = v;
        }
        (void)st;
    } else {
#pragma unroll
        for (int mt = 0; mt < 4; ++mt) {
#pragma unroll
            for (int nt = 0; nt < 4; ++nt) {
                int r0 = m0 + (wm << 6) + (mt << 4) + er;
                int r1 = r0 + 8;
                int c0 = n0 + (wn << 5) + (nt << 3) + ec;
                float v0 = acc[mt][nt][0], v1 = acc[mt][nt][1];
                float v2 = acc[mt][nt][2], v3 = acc[mt][nt][3];
                if (HAS_BIAS) {
                    float b0 = bias[c0], b1 = bias[c0 + 1];
                    v0 += b0; v1 += b1; v2 += b0; v3 += b1;
                }
                size_t o0 = ((size_t)r0 << 9) + c0;
                size_t o1 = ((size_t)r1 << 9) + c0;
                if (HAS_RES) {
                    const float2 q0 = *(const float2*)&res[o0];
                    const float2 q1 = *(const float2*)&res[o1];
                    v0 += q0.x; v1 += q0.y; v2 += q1.x; v3 += q1.y;
                }
                *(float2*)&C[o0] = make_float2(v0, v1);
                *(float2*)&C[o1] = make_float2(v2, v3);
            }
        }
    }
}

// ---------------- fused radix-4 FFT stages ----------------
__device__ __forceinline__ float2 cmulf(float2 w, float2 z) {
    return make_float2(w.x * z.x - w.y * z.y, w.x * z.y + w.y * z.x);
}

__device__ __forceinline__ void fft_stages_r4(float2* zs, const float2* tw, int tid) {
#pragma unroll
    for (int p = 0; p < 6; ++p) {
        const int h = 1 << (2 * p);
#pragma unroll
        for (int jj = 0; jj < 4; ++jj) {
            int j = tid + (jj << 8);
            int pos = j & (h - 1);
            int grp = j >> (2 * p);
            int base = (grp << (2 * p + 2)) + pos;
            float2 a = zs[base], b = zs[base + h], c = zs[base + 2 * h], d = zs[base + 3 * h];
            float2 w1 = tw[pos << (11 - 2 * p)];
            float2 w2 = tw[pos << (10 - 2 * p)];
            float2 wb = cmulf(w1, b), wd = cmulf(w1, d);
            float2 a1 = make_float2(a.x + wb.x, a.y + wb.y);
            float2 b1 = make_float2(a.x - wb.x, a.y - wb.y);
            float2 c1 = make_float2(c.x + wd.x, c.y + wd.y);
            float2 d1 = make_float2(c.x - wd.x, c.y - wd.y);
            float2 wc2 = cmulf(w2, c1), wd2 = cmulf(w2, d1);
            zs[base]         = make_float2(a1.x + wc2.x, a1.y + wc2.y);
            zs[base + 2 * h] = make_float2(a1.x - wc2.x, a1.y - wc2.y);
            zs[base + h]     = make_float2(b1.x + wd2.y, b1.y - wd2.x);
            zs[base + 3 * h] = make_float2(b1.x - wd2.y, b1.y + wd2.x);
        }
        __syncthreads();
    }
}

// ---------------- cross-spectrum accumulation ----------------
__global__ void fft_cross_kernel() {
    extern __shared__ float2 sm[];
    float2* zs  = sm;            // 4096
    float2* tw  = sm + 4096;     // 2048
    float2* acc = sm + 6144;     // 4096

    int tid = threadIdx.x;
    int b = blockIdx.x >> 6;
    int dg = (blockIdx.x & 63) << 3;

    for (int j = tid; j < 2048; j += 256) tw[j] = g_tw[j];
    for (int f = tid; f < 4096; f += 256) acc[f] = make_float2(0.f, 0.f);

    for (int c = 0; c < 8; ++c) {
        int d = dg + c;
        const float* qrow = g_qT + (((size_t)b * DD + d) << 12);
        const float* krow = g_kT + (((size_t)b * DD + d) << 12);
        __syncthreads();
        for (int t = tid; t < 4096; t += 256) {
            int r = (int)(__brev((unsigned)t) >> 20);
            zs[r] = make_float2(qrow[t], krow[t]);
        }
        __syncthreads();
        fft_stages_r4(zs, tw, tid);
        for (int f = tid; f < 4096; f += 256) {
            float2 Zf = zs[f];
            float2 Zc = zs[(4096 - f) & 4095];
            float Qr = 0.5f * (Zf.x + Zc.x);
            float Qi = 0.5f * (Zf.y - Zc.y);
            float Kr = 0.5f * (Zf.y + Zc.y);
            float Ki = 0.5f * (Zc.x - Zf.x);
            float2 a2 = acc[f];
            a2.x += Qr * Kr + Qi * Ki;
            a2.y += Qi * Kr - Qr * Ki;
            acc[f] = a2;
        }
    }
    __syncthreads();
    for (int f = tid; f < 4096; f += 256) {
        atomicAdd(&g_S[(b << 12) + f].x, acc[f].x);
        atomicAdd(&g_S[(b << 12) + f].y, acc[f].y);
    }
}

// ---------------- inverse FFT + top-k + softmax ----------------
__global__ void ifft_topk_kernel() {
    extern __shared__ float2 sm[];
    float2* zs = sm;                       // 4096
    float2* tw = sm + 4096;                // 2048
    float*  mv = (float*)(sm + 6144);      // 4096

    __shared__ float red_v[256];
    __shared__ int   red_i[256];
    __shared__ float s_tv[TOPK];
    __shared__ int   s_ti[TOPK];

    int tid = threadIdx.x;
    int b = blockIdx.x;

    for (int j = tid; j < 2048; j += 256) tw[j] = g_tw[j];
    for (int f = tid; f < 4096; f += 256) {
        int r = (int)(__brev((unsigned)f) >> 20);
        float2 s = g_S[(b << 12) + f];
        zs[r] = make_float2(s.x, -s.y);
    }
    __syncthreads();
    fft_stages_r4(zs, tw, tid);

    const float scale = 1.0f / (4096.0f * 512.0f);
    for (int n = tid; n < 4096; n += 256) mv[n] = zs[n].x * scale;
    __syncthreads();

    for (int it = 0; it < TOPK; ++it) {
        float bv = -3.402823e38f; int bi = 1 << 30;
        for (int n = tid; n < 4096; n += 256) {
            float v = mv[n];
            if (v > bv || (v == bv && n < bi)) { bv = v; bi = n; }
        }
        red_v[tid] = bv; red_i[tid] = bi;
        __syncthreads();
        for (int s = 128; s > 0; s >>= 1) {
            if (tid < s) {
                float v2 = red_v[tid + s]; int i2 = red_i[tid + s];
                if (v2 > red_v[tid] || (v2 == red_v[tid] && i2 < red_i[tid])) {
                    red_v[tid] = v2; red_i[tid] = i2;
                }
            }
            __syncthreads();
        }
        if (tid == 0) {
            s_tv[it] = red_v[0]; s_ti[it] = red_i[0];
            mv[red_i[0]] = -3.402823e38f;
        }
        __syncthreads();
    }

    if (tid == 0) {
        float mx = s_tv[0];
        float ex[TOPK]; float sum = 0.f;
        for (int i = 0; i < TOPK; ++i) { ex[i] = expf(s_tv[i] - mx); sum += ex[i]; }
        for (int i = 0; i < TOPK; ++i) {
            g_w[b * TOPK + i] = ex[i] / sum;
            g_delay[b * TOPK + i] = s_ti[i];
        }
    }
}

// ---------------- aggregation on x_s (pre-projection; fused hi/lo split output) ----------------
__global__ void aggregate_kernel(const float* __restrict__ v,
                                 __nv_bfloat162* __restrict__ oh,
                                 __nv_bfloat162* __restrict__ ol) {
    size_t idx = (size_t)blockIdx.x * 256 + threadIdx.x;   // over B*L*(D/4)
    int c = (int)(idx & 127);
    size_t row = idx >> 7;
    int b = (int)(row >> 12);
    int t = (int)(row & 4095);

    float wloc[TOPK]; int dloc[TOPK];
#pragma unroll
    for (int i = 0; i < TOPK; ++i) { wloc[i] = g_w[b * TOPK + i]; dloc[i] = g_delay[b * TOPK + i]; }

    float4 acc = make_float4(0.f, 0.f, 0.f, 0.f);
#pragma unroll
    for (int i = 0; i < TOPK; ++i) {
        int ts = (t + dloc[i]) & 4095;
        const float4 vv = *(const float4*)(v + (((size_t)(b << 12) + ts) << 9) + (c << 2));
        acc.x += wloc[i] * vv.x;
        acc.y += wloc[i] * vv.y;
        acc.z += wloc[i] * vv.z;
        acc.w += wloc[i] * vv.w;
    }
    __nv_bfloat16 hx = __float2bfloat16(acc.x), hy = __float2bfloat16(acc.y);
    __nv_bfloat16 hz = __float2bfloat16(acc.z), hw = __float2bfloat16(acc.w);
    size_t p = (row << 8) + (c << 1);
    oh[p]     = __nv_bfloat162(hx, hy);
    oh[p + 1] = __nv_bfloat162(hz, hw);
    ol[p]     = __nv_bfloat162(__float2bfloat16(acc.x - __bfloat162float(hx)),
                               __float2bfloat16(acc.y - __bfloat162float(hy)));
    ol[p + 1] = __nv_bfloat162(__float2bfloat16(acc.z - __bfloat162float(hz)),
                               __float2bfloat16(acc.w - __bfloat162float(hw)));
}

// ---------------- host launch ----------------
extern "C" void kernel_launch(void* const* d_in, const int* in_sizes, int n_in,
                              void* d_out, int out_size) {
    const float* x_s   = (const float*)d_in[0];
    const float* x_w   = (const float*)d_in[1];
    const float* Wq    = (const float*)d_in[2];
    const float* bq    = (const float*)d_in[3];
    const float* Wk    = (const float*)d_in[4];
    const float* bk    = (const float*)d_in[5];
    const float* Wv    = (const float*)d_in[6];
    const float* bv    = (const float*)d_in[7];
    const float* Wo    = (const float*)d_in[8];
    const float* bo    = (const float*)d_in[9];
    const float* Wconv = (const float*)d_in[10];

    float* out_s = (float*)d_out;
    float* out_w = out_s + BLD;

    void *p_xs_h, *p_xs_l, *p_xw_h, *p_xw_l, *p_ag_h, *p_ag_l;
    void *p_wq_h, *p_wq_l, *p_wk_h, *p_wk_l, *p_wcb_h, *p_wcb_l;
    void *p_wc_h, *p_wc_l, *p_qT, *p_kT, *p_bcomb;
    cudaGetSymbolAddress(&p_xs_h, g_xs_h); cudaGetSymbolAddress(&p_xs_l, g_xs_l);
    cudaGetSymbolAddress(&p_xw_h, g_xw_h); cudaGetSymbolAddress(&p_xw_l, g_xw_l);
    cudaGetSymbolAddress(&p_ag_h, g_ag_h); cudaGetSymbolAddress(&p_ag_l, g_ag_l);
    cudaGetSymbolAddress(&p_wq_h, g_wq_h); cudaGetSymbolAddress(&p_wq_l, g_wq_l);
    cudaGetSymbolAddress(&p_wk_h, g_wk_h); cudaGetSymbolAddress(&p_wk_l, g_wk_l);
    cudaGetSymbolAddress(&p_wcb_h, g_wcb_h); cudaGetSymbolAddress(&p_wcb_l, g_wcb_l);
    cudaGetSymbolAddress(&p_wc_h, g_wc_h); cudaGetSymbolAddress(&p_wc_l, g_wc_l);
    cudaGetSymbolAddress(&p_qT, g_qT); cudaGetSymbolAddress(&p_kT, g_kT);
    cudaGetSymbolAddress(&p_bcomb, g_bcomb);

    const int SMEM_DYN = 3 * 32768 + 1024;
    cudaFuncSetAttribute(mma_gemm<1, true,  false, false>, cudaFuncAttributeMaxDynamicSharedMemorySize, SMEM_DYN);
    cudaFuncSetAttribute(mma_gemm<0, true,  true,  false>, cudaFuncAttributeMaxDynamicSharedMemorySize, SMEM_DYN);
    cudaFuncSetAttribute(mma_gemm<0, false, false, true >, cudaFuncAttributeMaxDynamicSharedMemorySize, SMEM_DYN);
    cudaFuncSetAttribute(fft_cross_kernel, cudaFuncAttributeMaxDynamicSharedMemorySize, 81920);
    cudaFuncSetAttribute(ifft_topk_kernel, cudaFuncAttributeMaxDynamicSharedMemorySize, 65536);

    // 1-5: init + weight combine + splits
    init_tw_kernel<<<8, 256>>>();
    zero_S_kernel<<<128, 256>>>();
    wcomb_gemm<<<dim3(16, 16), dim3(16, 16)>>>(Wo, Wv);
    bcomb_kernel<<<64, 256>>>(Wo, bv, bo);
    mega_split_kernel<<<36608, 256>>>((const float4*)x_s, (const float4*)x_w,
                                      (const float4*)Wq, (const float4*)Wk, Wconv);

    dim3 gg(4, 256);   // N/128 x M/128
    // 6: q = x_w @ Wq^T + bq  (transposed output -> [B,D,L])
    mma_gemm<1, true, false, false><<<gg, 256, SMEM_DYN>>>(
        (const __nv_bfloat16*)p_xw_h, (const __nv_bfloat16*)p_xw_l,
        (const __nv_bfloat16*)p_wq_h, (const __nv_bfloat16*)p_wq_l,
        bq, nullptr, (float*)p_qT, 512);
    // 7: k = x_s @ Wk^T + bk  (transposed)
    mma_gemm<1, true, false, false><<<gg, 256, SMEM_DYN>>>(
        (const __nv_bfloat16*)p_xs_h, (const __nv_bfloat16*)p_xs_l,
        (const __nv_bfloat16*)p_wk_h, (const __nv_bfloat16*)p_wk_l,
        bk, nullptr, (float*)p_kT, 512);

    // 8-9: correlation spectrum + top-k delays
    fft_cross_kernel<<<512, 256, 81920>>>();
    ifft_topk_kernel<<<8, 256, 65536>>>();

    // 10: aggregate x_s by delays (V/O projections commute with the convex roll combo)
    aggregate_kernel<<<16384, 256>>>(x_s, (__nv_bfloat162*)p_ag_h, (__nv_bfloat162*)p_ag_l);

    // 11: x_s_out = x_s + xagg @ (Wo Wv)^T + (Wo bv + bo)
    mma_gemm<0, true, true, false><<<gg, 256, SMEM_DYN>>>(
        (const __nv_bfloat16*)p_ag_h, (const __nv_bfloat16*)p_ag_l,
        (const __nv_bfloat16*)p_wcb_h, (const __nv_bfloat16*)p_wcb_l,
        (const float*)p_bcomb, x_s, out_s, 512);
    // 12: x_w_out = circular conv1d(x_w) as K=1536 GEMM
    mma_gemm<0, false, false, true><<<gg, 256, SMEM_DYN>>>(
        (const __nv_bfloat16*)p_xw_h, (const __nv_bfloat16*)p_xw_l,
        (const __nv_bfloat16*)p_wc_h, (const __nv_bfloat16*)p_wc_l,
        nullptr, nullptr, out_w, 1536);
}

// round 6
// speedup vs baseline: 3.7182x; 1.2843x over previous
#include <cuda_runtime.h>
#include <cuda_bf16.h>
#include <cuda_fp16.h>
#include <math.h>
#include <stdint.h>

// ---------------- problem constants ----------------
#define BB 8
#define LL 4096
#define DD 512
#define TOPK 8
#define NFFT 4096
static const size_t BLD = (size_t)BB * LL * DD;   // 16,777,216

// ---------------- device scratch ----------------
// bf16 hi/lo pairs for the precision-critical q/k GEMMs
__device__ __nv_bfloat16 g_xs_h[(size_t)BB * LL * DD];
__device__ __nv_bfloat16 g_xs_l[(size_t)BB * LL * DD];
__device__ __nv_bfloat16 g_xw_h[(size_t)BB * LL * DD];
__device__ __nv_bfloat16 g_xw_l[(size_t)BB * LL * DD];
__device__ __nv_bfloat16 g_wq_h[DD * DD], g_wq_l[DD * DD];
__device__ __nv_bfloat16 g_wk_h[DD * DD], g_wk_l[DD * DD];
// fp16 single copies for the loose-tolerance O/conv GEMMs
__device__ __half g_xsf[(size_t)BB * LL * DD];
__device__ __half g_xwf[(size_t)BB * LL * DD];
__device__ __half g_ag [(size_t)BB * LL * DD];
__device__ __half g_wcb[DD * DD];          // fp16(Wo @ Wv)
__device__ __half g_wc [DD * 1536];        // conv weights relaid [n][kk*512+i]
__device__ float g_wcomb[DD * DD];         // Wo @ Wv (fp32)
__device__ float g_bcomb[DD];              // Wo @ bv + bo
__device__ float g_qT[(size_t)BB * DD * LL];
__device__ float g_kT[(size_t)BB * DD * LL];
__device__ float2 g_S[BB * NFFT];
__device__ float2 g_tw[NFFT / 2];
__device__ float g_w[BB * TOPK];
__device__ int   g_delay[BB * TOPK];

// ---------------- helpers ----------------
__device__ __forceinline__ uint32_t smem_u32(const void* p) {
    uint32_t a;
    asm("{ .reg .u64 t; cvta.to.shared.u64 t, %1; cvt.u32.u64 %0, t; }" : "=r"(a) : "l"(p));
    return a;
}

__device__ __forceinline__ void ldmx4(uint32_t* r, uint32_t addr) {
    asm volatile("ldmatrix.sync.aligned.m8n8.x4.shared.b16 {%0,%1,%2,%3}, [%4];"
                 : "=r"(r[0]), "=r"(r[1]), "=r"(r[2]), "=r"(r[3]) : "r"(addr));
}

template <bool F16>
__device__ __forceinline__ void mma16816(float* d, const uint32_t* a, uint32_t b0, uint32_t b1) {
    if constexpr (F16) {
        asm volatile(
            "mma.sync.aligned.m16n8k16.row.col.f32.f16.f16.f32 "
            "{%0,%1,%2,%3}, {%4,%5,%6,%7}, {%8,%9}, {%0,%1,%2,%3};"
            : "+f"(d[0]), "+f"(d[1]), "+f"(d[2]), "+f"(d[3])
            : "r"(a[0]), "r"(a[1]), "r"(a[2]), "r"(a[3]), "r"(b0), "r"(b1));
    } else {
        asm volatile(
            "mma.sync.aligned.m16n8k16.row.col.f32.bf16.bf16.f32 "
            "{%0,%1,%2,%3}, {%4,%5,%6,%7}, {%8,%9}, {%0,%1,%2,%3};"
            : "+f"(d[0]), "+f"(d[1]), "+f"(d[2]), "+f"(d[3])
            : "r"(a[0]), "r"(a[1]), "r"(a[2]), "r"(a[3]), "r"(b0), "r"(b1));
    }
}

#define CP_ASYNC16(dst, src) \
    asm volatile("cp.async.cg.shared.global [%0], [%1], 16;" :: "r"(dst), "l"(src))
#define CP_COMMIT() asm volatile("cp.async.commit_group;")
#define CP_WAIT2()  asm volatile("cp.async.wait_group 2;")
#define CP_WAIT1()  asm volatile("cp.async.wait_group 1;")
#define CP_WAIT0()  asm volatile("cp.async.wait_group 0;")

// 64-byte-row swizzle (Swizzle<2,4,3>)
__device__ __forceinline__ uint32_t sw64(uint32_t off) {
    return off ^ ((off >> 3) & 0x30);
}

// ---------------- init kernels ----------------
__global__ void init_tw_kernel() {
    int j = blockIdx.x * 256 + threadIdx.x;
    if (j < NFFT / 2) {
        float s, c;
        sincospif(-2.0f * (float)j / (float)NFFT, &s, &c);
        g_tw[j] = make_float2(c, s);
    }
}

__global__ void zero_S_kernel() {
    int i = blockIdx.x * 256 + threadIdx.x;
    if (i < BB * NFFT) g_S[i] = make_float2(0.f, 0.f);
}

// ---------------- Wcomb = Wo @ Wv (fp32 exact) ----------------
__global__ void wcomb_gemm(const float* __restrict__ Wo, const float* __restrict__ Wv) {
    __shared__ float As[32][33], Bs[32][33];
    int bi = blockIdx.y * 32, bj = blockIdx.x * 32;
    int tx = threadIdx.x, ty = threadIdx.y;   // 16 x 16
    float a00 = 0.f, a01 = 0.f, a10 = 0.f, a11 = 0.f;
    for (int m0 = 0; m0 < 512; m0 += 32) {
        for (int r = ty; r < 32; r += 16) {
            As[r][tx]      = Wo[(bi + r) * 512 + m0 + tx];
            As[r][tx + 16] = Wo[(bi + r) * 512 + m0 + tx + 16];
            Bs[r][tx]      = Wv[(m0 + r) * 512 + bj + tx];
            Bs[r][tx + 16] = Wv[(m0 + r) * 512 + bj + tx + 16];
        }
        __syncthreads();
#pragma unroll
        for (int m = 0; m < 32; ++m) {
            float x0 = As[ty][m], x1 = As[ty + 16][m];
            float y0 = Bs[m][tx], y1 = Bs[m][tx + 16];
            a00 += x0 * y0; a01 += x0 * y1; a10 += x1 * y0; a11 += x1 * y1;
        }
        __syncthreads();
    }
    g_wcomb[(bi + ty) * 512 + bj + tx]           = a00;
    g_wcomb[(bi + ty) * 512 + bj + tx + 16]      = a01;
    g_wcomb[(bi + ty + 16) * 512 + bj + tx]      = a10;
    g_wcomb[(bi + ty + 16) * 512 + bj + tx + 16] = a11;
}

// warp-per-output reduction: g_bcomb[i] = bo[i] + sum_m Wo[i,m]*bv[m]
__global__ void bcomb_kernel(const float* __restrict__ Wo,
                             const float* __restrict__ bv,
                             const float* __restrict__ bo) {
    int o = blockIdx.x * 8 + (threadIdx.x >> 5);
    int lane = threadIdx.x & 31;
    float s = 0.f;
    for (int m = lane; m < 512; m += 32) s += Wo[o * 512 + m] * bv[m];
#pragma unroll
    for (int off = 16; off; off >>= 1) s += __shfl_xor_sync(0xFFFFFFFFu, s, off);
    if (lane == 0) g_bcomb[o] = s + bo[o];
}

// ---------------- mega split ----------------
// bf16 hi/lo split, plus optional fp16 copy
__device__ __forceinline__ void split_bf_f16(const float4* __restrict__ x,
                                             __nv_bfloat162* __restrict__ h,
                                             __nv_bfloat162* __restrict__ l,
                                             __half2* __restrict__ f, int i) {
    float4 v = x[i];
    __nv_bfloat16 hx = __float2bfloat16(v.x), hy = __float2bfloat16(v.y);
    __nv_bfloat16 hz = __float2bfloat16(v.z), hw = __float2bfloat16(v.w);
    h[2 * i]     = __nv_bfloat162(hx, hy);
    h[2 * i + 1] = __nv_bfloat162(hz, hw);
    l[2 * i]     = __nv_bfloat162(__float2bfloat16(v.x - __bfloat162float(hx)),
                                  __float2bfloat16(v.y - __bfloat162float(hy)));
    l[2 * i + 1] = __nv_bfloat162(__float2bfloat16(v.z - __bfloat162float(hz)),
                                  __float2bfloat16(v.w - __bfloat162float(hw)));
    if (f) {
        f[2 * i]     = __floats2half2_rn(v.x, v.y);
        f[2 * i + 1] = __floats2half2_rn(v.z, v.w);
    }
}

__global__ void mega_split_kernel(const float4* __restrict__ xs,
                                  const float4* __restrict__ xw,
                                  const float4* __restrict__ Wq,
                                  const float4* __restrict__ Wk,
                                  const float* __restrict__ Wconv) {
    int bid = blockIdx.x;
    int tid = threadIdx.x;
    if (bid < 16384) {
        split_bf_f16(xs, (__nv_bfloat162*)g_xs_h, (__nv_bfloat162*)g_xs_l,
                     (__half2*)g_xsf, bid * 256 + tid);
    } else if (bid < 32768) {
        split_bf_f16(xw, (__nv_bfloat162*)g_xw_h, (__nv_bfloat162*)g_xw_l,
                     (__half2*)g_xwf, (bid - 16384) * 256 + tid);
    } else if (bid < 33024) {
        split_bf_f16(Wq, (__nv_bfloat162*)g_wq_h, (__nv_bfloat162*)g_wq_l,
                     nullptr, (bid - 32768) * 256 + tid);
    } else if (bid < 33280) {
        split_bf_f16(Wk, (__nv_bfloat162*)g_wk_h, (__nv_bfloat162*)g_wk_l,
                     nullptr, (bid - 33024) * 256 + tid);
    } else if (bid < 33536) {
        int i = (bid - 33280) * 256 + tid;           // fp32 wcomb -> fp16
        float4 v = ((const float4*)g_wcomb)[i];
        ((__half2*)g_wcb)[2 * i]     = __floats2half2_rn(v.x, v.y);
        ((__half2*)g_wcb)[2 * i + 1] = __floats2half2_rn(v.z, v.w);
    } else {
        int idx = (bid - 33536) * 256 + tid;         // conv relay, fp16
        int n = idx / 1536;
        int r = idx - n * 1536;
        int kk = r >> 9;
        int i = r & 511;
        g_wc[idx] = __float2half_rn(Wconv[((size_t)n * 512 + i) * 3 + kk]);
    }
}

// ---------------- mma.sync GEMM ----------------
// NPASS=3: Ah*Bh + Al*Bh + Ah*Bl (bf16 hi/lo); NPASS=1: Ah*Bh (fp16).
// K chunk = 32 elems = 64B rows. Stage layout (32KB stride):
//   sAh +0 (8KB), sAl +8192, sBh +16384, sBl +24576.
template <int NPASS, bool CONV>
__device__ __forceinline__ void load_chunk(
    int ch, int stage, int K, int m0, int n0, int tid, uint32_t sbase,
    const uint16_t* __restrict__ Ah, const uint16_t* __restrict__ Al,
    const uint16_t* __restrict__ Bh, const uint16_t* __restrict__ Bl)
{
    int k0 = ch << 5;
    uint32_t st = sbase + stage * 32768;
    int r = tid >> 1;                 // 0..127
    int seg0 = (tid & 1) << 1;        // 0 or 2

    // A row offset (elements)
    size_t aoff;
    if (CONV) {
        int m = m0 + r;
        int kk = k0 >> 9;
        int ii = k0 & 511;
        int bb = m >> 12;
        int tt = ((m & 4095) + kk + 4095) & 4095;   // t + kk - 1 mod L
        aoff = (((size_t)(bb << 12) + tt) << 9) + ii;
    } else {
        aoff = ((size_t)(m0 + r) << 9) + k0;
    }
    size_t boff = (size_t)(n0 + r) * K + k0;

#pragma unroll
    for (int s2 = 0; s2 < 2; ++s2) {
        int seg = seg0 + s2;
        uint32_t soff = sw64((r << 6) + (seg << 4));
        CP_ASYNC16(st + soff, Ah + aoff + (seg << 3));
        CP_ASYNC16(st + 16384 + soff, Bh + boff + (seg << 3));
        if (NPASS >= 2) CP_ASYNC16(st + 8192 + soff, Al + aoff + (seg << 3));
        if (NPASS == 3) CP_ASYNC16(st + 24576 + soff, Bl + boff + (seg << 3));
    }
    CP_COMMIT();
}

template <int NPASS, bool F16, int TOUT, bool HAS_BIAS, bool HAS_RES, bool CONV>
__global__ void __launch_bounds__(256, 2) mma_gemm(
    const uint16_t* __restrict__ Ah, const uint16_t* __restrict__ Al,
    const uint16_t* __restrict__ Bh, const uint16_t* __restrict__ Bl,
    const float* __restrict__ bias, const float* __restrict__ res,
    float* __restrict__ C, int K)
{
    extern __shared__ char smraw[];
    uint32_t sbase = (smem_u32(smraw) + 1023u) & ~1023u;

    const int tid = threadIdx.x;
    const int wid = tid >> 5;
    const int lane = tid & 31;
    const int wm = wid >> 2;    // 0..1 -> m offset 64*wm
    const int wn = wid & 3;     // 0..3 -> n offset 32*wn
    const int m0 = blockIdx.y << 7;
    const int n0 = blockIdx.x << 7;
    const int T = K >> 5;

    float acc[4][4][4];
#pragma unroll
    for (int i = 0; i < 4; ++i)
#pragma unroll
        for (int j = 0; j < 4; ++j)
#pragma unroll
            for (int r = 0; r < 4; ++r) acc[i][j][r] = 0.f;

    load_chunk<NPASS, CONV>(0, 0, K, m0, n0, tid, sbase, Ah, Al, Bh, Bl);
    load_chunk<NPASS, CONV>(1, 1, K, m0, n0, tid, sbase, Ah, Al, Bh, Bl);
    load_chunk<NPASS, CONV>(2, 2, K, m0, n0, tid, sbase, Ah, Al, Bh, Bl);

    const int lrow = lane & 15;
    const int lseg = lane >> 4;

    int s = 0;
    for (int it = 0; it < T; ++it) {
        int rem = T - 1 - it;
        if (rem >= 2) { CP_WAIT2(); } else if (rem == 1) { CP_WAIT1(); } else { CP_WAIT0(); }
        __syncthreads();

        uint32_t st = sbase + s * 32768;
#pragma unroll
        for (int ks = 0; ks < 2; ++ks) {
            int cseg = (ks << 1) + lseg;
            uint32_t ah[4][4], b2[2][4];
#pragma unroll
            for (int mt = 0; mt < 4; ++mt) {
                int row = (wm << 6) + (mt << 4) + lrow;
                ldmx4(ah[mt], st + sw64((row << 6) + (cseg << 4)));
            }
#pragma unroll
            for (int bt = 0; bt < 2; ++bt) {
                int row = (wn << 5) + (bt << 4) + lrow;
                ldmx4(b2[bt], st + 16384 + sw64((row << 6) + (cseg << 4)));
            }
#pragma unroll
            for (int mt = 0; mt < 4; ++mt)
#pragma unroll
                for (int nt = 0; nt < 4; ++nt)
                    mma16816<F16>(acc[mt][nt], ah[mt],
                                  b2[nt >> 1][nt & 1], b2[nt >> 1][(nt & 1) + 2]);
            if (NPASS >= 2) {
                uint32_t al[4][4];
#pragma unroll
                for (int mt = 0; mt < 4; ++mt) {
                    int row = (wm << 6) + (mt << 4) + lrow;
                    ldmx4(al[mt], st + 8192 + sw64((row << 6) + (cseg << 4)));
                }
#pragma unroll
                for (int mt = 0; mt < 4; ++mt)
#pragma unroll
                    for (int nt = 0; nt < 4; ++nt)
                        mma16816<F16>(acc[mt][nt], al[mt],
                                      b2[nt >> 1][nt & 1], b2[nt >> 1][(nt & 1) + 2]);
            }
            if (NPASS == 3) {
#pragma unroll
                for (int bt = 0; bt < 2; ++bt) {
                    int row = (wn << 5) + (bt << 4) + lrow;
                    ldmx4(b2[bt], st + 24576 + sw64((row << 6) + (cseg << 4)));
                }
#pragma unroll
                for (int mt = 0; mt < 4; ++mt)
#pragma unroll
                    for (int nt = 0; nt < 4; ++nt)
                        mma16816<F16>(acc[mt][nt], ah[mt],
                                      b2[nt >> 1][nt & 1], b2[nt >> 1][(nt & 1) + 2]);
            }
        }
        __syncthreads();
        if (it + 3 < T)
            load_chunk<NPASS, CONV>(it + 3, s, K, m0, n0, tid, sbase, Ah, Al, Bh, Bl);
        s = (s == 2) ? 0 : s + 1;
    }

    // ---------------- epilogue ----------------
    const int er = lane >> 2;            // 0..7
    const int ec = (lane & 3) << 1;      // 0,2,4,6
    if (TOUT == 1) {
        // transpose through smem, then coalesced rows into [B, D, L]
        float* stf = (float*)smraw;
#pragma unroll
        for (int mt = 0; mt < 4; ++mt)
#pragma unroll
            for (int nt = 0; nt < 4; ++nt) {
                int r0 = (wm << 6) + (mt << 4) + er;
                int c0 = (wn << 5) + (nt << 3) + ec;
                stf[c0 * 130 + r0]            = acc[mt][nt][0];
                stf[(c0 + 1) * 130 + r0]      = acc[mt][nt][1];
                stf[c0 * 130 + r0 + 8]        = acc[mt][nt][2];
                stf[(c0 + 1) * 130 + r0 + 8]  = acc[mt][nt][3];
            }
        __syncthreads();
        int bb = m0 >> 12, l0 = m0 & 4095;
#pragma unroll
        for (int i = 0; i < 16; ++i) {
            int idx = tid + (i << 8);
            int c = idx >> 5;            // 0..127
            int rq = (idx & 31) << 2;    // 0..124 step 4
            float4 v;
            v.x = stf[c * 130 + rq];
            v.y = stf[c * 130 + rq + 1];
            v.z = stf[c * 130 + rq + 2];
            v.w = stf[c * 130 + rq + 3];
            if (HAS_BIAS) {
                float bval = bias[n0 + c];
                v.x += bval; v.y += bval; v.z += bval; v.w += bval;
            }
            *(float4*)&C[(((size_t)(bb << 9) + n0 + c) << 12) + l0 + rq] = v;
        }
    } else {
#pragma unroll
        for (int mt = 0; mt < 4; ++mt) {
#pragma unroll
            for (int nt = 0; nt < 4; ++nt) {
                int r0 = m0 + (wm << 6) + (mt << 4) + er;
                int r1 = r0 + 8;
                int c0 = n0 + (wn << 5) + (nt << 3) + ec;
                float v0 = acc[mt][nt][0], v1 = acc[mt][nt][1];
                float v2 = acc[mt][nt][2], v3 = acc[mt][nt][3];
                if (HAS_BIAS) {
                    float b0 = bias[c0], b1 = bias[c0 + 1];
                    v0 += b0; v1 += b1; v2 += b0; v3 += b1;
                }
                size_t o0 = ((size_t)r0 << 9) + c0;
                size_t o1 = ((size_t)r1 << 9) + c0;
                if (HAS_RES) {
                    const float2 q0 = *(const float2*)&res[o0];
                    const float2 q1 = *(const float2*)&res[o1];
                    v0 += q0.x; v1 += q0.y; v2 += q1.x; v3 += q1.y;
                }
                *(float2*)&C[o0] = make_float2(v0, v1);
                *(float2*)&C[o1] = make_float2(v2, v3);
            }
        }
    }
}

// ---------------- fused radix-4 FFT stages ----------------
__device__ __forceinline__ float2 cmulf(float2 w, float2 z) {
    return make_float2(w.x * z.x - w.y * z.y, w.x * z.y + w.y * z.x);
}

__device__ __forceinline__ void fft_stages_r4(float2* zs, const float2* tw, int tid) {
#pragma unroll
    for (int p = 0; p < 6; ++p) {
        const int h = 1 << (2 * p);
#pragma unroll
        for (int jj = 0; jj < 4; ++jj) {
            int j = tid + (jj << 8);
            int pos = j & (h - 1);
            int grp = j >> (2 * p);
            int base = (grp << (2 * p + 2)) + pos;
            float2 a = zs[base], b = zs[base + h], c = zs[base + 2 * h], d = zs[base + 3 * h];
            float2 w1 = tw[pos << (11 - 2 * p)];
            float2 w2 = tw[pos << (10 - 2 * p)];
            float2 wb = cmulf(w1, b), wd = cmulf(w1, d);
            float2 a1 = make_float2(a.x + wb.x, a.y + wb.y);
            float2 b1 = make_float2(a.x - wb.x, a.y - wb.y);
            float2 c1 = make_float2(c.x + wd.x, c.y + wd.y);
            float2 d1 = make_float2(c.x - wd.x, c.y - wd.y);
            float2 wc2 = cmulf(w2, c1), wd2 = cmulf(w2, d1);
            zs[base]         = make_float2(a1.x + wc2.x, a1.y + wc2.y);
            zs[base + 2 * h] = make_float2(a1.x - wc2.x, a1.y - wc2.y);
            zs[base + h]     = make_float2(b1.x + wd2.y, b1.y - wd2.x);
            zs[base + 3 * h] = make_float2(b1.x - wd2.y, b1.y + wd2.x);
        }
        __syncthreads();
    }
}

// ---------------- cross-spectrum accumulation ----------------
__global__ void fft_cross_kernel() {
    extern __shared__ float2 sm[];
    float2* zs  = sm;            // 4096
    float2* tw  = sm + 4096;     // 2048
    float2* acc = sm + 6144;     // 4096

    int tid = threadIdx.x;
    int b = blockIdx.x >> 6;
    int dg = (blockIdx.x & 63) << 3;

    for (int j = tid; j < 2048; j += 256) tw[j] = g_tw[j];
    for (int f = tid; f < 4096; f += 256) acc[f] = make_float2(0.f, 0.f);

    for (int c = 0; c < 8; ++c) {
        int d = dg + c;
        const float* qrow = g_qT + (((size_t)b * DD + d) << 12);
        const float* krow = g_kT + (((size_t)b * DD + d) << 12);
        __syncthreads();
        for (int t = tid; t < 4096; t += 256) {
            int r = (int)(__brev((unsigned)t) >> 20);
            zs[r] = make_float2(qrow[t], krow[t]);
        }
        __syncthreads();
        fft_stages_r4(zs, tw, tid);
        for (int f = tid; f < 4096; f += 256) {
            float2 Zf = zs[f];
            float2 Zc = zs[(4096 - f) & 4095];
            float Qr = 0.5f * (Zf.x + Zc.x);
            float Qi = 0.5f * (Zf.y - Zc.y);
            float Kr = 0.5f * (Zf.y + Zc.y);
            float Ki = 0.5f * (Zc.x - Zf.x);
            float2 a2 = acc[f];
            a2.x += Qr * Kr + Qi * Ki;
            a2.y += Qi * Kr - Qr * Ki;
            acc[f] = a2;
        }
    }
    __syncthreads();
    for (int f = tid; f < 4096; f += 256) {
        atomicAdd(&g_S[(b << 12) + f].x, acc[f].x);
        atomicAdd(&g_S[(b << 12) + f].y, acc[f].y);
    }
}

// ---------------- inverse FFT + top-k + softmax ----------------
__global__ void ifft_topk_kernel() {
    extern __shared__ float2 sm[];
    float2* zs = sm;                       // 4096
    float2* tw = sm + 4096;                // 2048
    float*  mv = (float*)(sm + 6144);      // 4096

    __shared__ float red_v[256];
    __shared__ int   red_i[256];
    __shared__ float s_tv[TOPK];
    __shared__ int   s_ti[TOPK];

    int tid = threadIdx.x;
    int b = blockIdx.x;

    for (int j = tid; j < 2048; j += 256) tw[j] = g_tw[j];
    for (int f = tid; f < 4096; f += 256) {
        int r = (int)(__brev((unsigned)f) >> 20);
        float2 s = g_S[(b << 12) + f];
        zs[r] = make_float2(s.x, -s.y);
    }
    __syncthreads();
    fft_stages_r4(zs, tw, tid);

    const float scale = 1.0f / (4096.0f * 512.0f);
    for (int n = tid; n < 4096; n += 256) mv[n] = zs[n].x * scale;
    __syncthreads();

    for (int it = 0; it < TOPK; ++it) {
        float bv = -3.402823e38f; int bi = 1 << 30;
        for (int n = tid; n < 4096; n += 256) {
            float v = mv[n];
            if (v > bv || (v == bv && n < bi)) { bv = v; bi = n; }
        }
        red_v[tid] = bv; red_i[tid] = bi;
        __syncthreads();
        for (int s = 128; s > 0; s >>= 1) {
            if (tid < s) {
                float v2 = red_v[tid + s]; int i2 = red_i[tid + s];
                if (v2 > red_v[tid] || (v2 == red_v[tid] && i2 < red_i[tid])) {
                    red_v[tid] = v2; red_i[tid] = i2;
                }
            }
            __syncthreads();
        }
        if (tid == 0) {
            s_tv[it] = red_v[0]; s_ti[it] = red_i[0];
            mv[red_i[0]] = -3.402823e38f;
        }
        __syncthreads();
    }

    if (tid == 0) {
        float mx = s_tv[0];
        float ex[TOPK]; float sum = 0.f;
        for (int i = 0; i < TOPK; ++i) { ex[i] = expf(s_tv[i] - mx); sum += ex[i]; }
        for (int i = 0; i < TOPK; ++i) {
            g_w[b * TOPK + i] = ex[i] / sum;
            g_delay[b * TOPK + i] = s_ti[i];
        }
    }
}

// ---------------- aggregation on fp16 x_s (L2-resident, single fp16 output) ----------------
__global__ void aggregate_kernel() {
    size_t idx = (size_t)blockIdx.x * 256 + threadIdx.x;   // over 32768 rows x 64 groups
    int grp = (int)(idx & 63);        // 8-half group
    size_t row = idx >> 6;
    int b = (int)(row >> 12);
    int t = (int)(row & 4095);

    float wloc[TOPK]; int dloc[TOPK];
#pragma unroll
    for (int i = 0; i < TOPK; ++i) { wloc[i] = g_w[b * TOPK + i]; dloc[i] = g_delay[b * TOPK + i]; }

    float acc[8];
#pragma unroll
    for (int j = 0; j < 8; ++j) acc[j] = 0.f;

#pragma unroll
    for (int i = 0; i < TOPK; ++i) {
        int ts = (t + dloc[i]) & 4095;
        const uint4 raw = *(const uint4*)(g_xsf + (((size_t)(b << 12) + ts) << 9) + (grp << 3));
        const __half2* p = (const __half2*)&raw;
        float w = wloc[i];
#pragma unroll
        for (int j = 0; j < 4; ++j) {
            float2 f = __half22float2(p[j]);
            acc[2 * j]     += w * f.x;
            acc[2 * j + 1] += w * f.y;
        }
    }
    uint4 out;
    __half2* po = (__half2*)&out;
#pragma unroll
    for (int j = 0; j < 4; ++j) po[j] = __floats2half2_rn(acc[2 * j], acc[2 * j + 1]);
    *(uint4*)(g_ag + (row << 9) + (grp << 3)) = out;
}

// ---------------- host launch ----------------
extern "C" void kernel_launch(void* const* d_in, const int* in_sizes, int n_in,
                              void* d_out, int out_size) {
    const float* x_s   = (const float*)d_in[0];
    const float* x_w   = (const float*)d_in[1];
    const float* Wq    = (const float*)d_in[2];
    const float* bq    = (const float*)d_in[3];
    const float* Wk    = (const float*)d_in[4];
    const float* bk    = (const float*)d_in[5];
    const float* Wv    = (const float*)d_in[6];
    const float* bv    = (const float*)d_in[7];
    const float* Wo    = (const float*)d_in[8];
    const float* bo    = (const float*)d_in[9];
    const float* Wconv = (const float*)d_in[10];

    float* out_s = (float*)d_out;
    float* out_w = out_s + BLD;

    void *p_xs_h, *p_xs_l, *p_xw_h, *p_xw_l;
    void *p_wq_h, *p_wq_l, *p_wk_h, *p_wk_l;
    void *p_xwf, *p_ag, *p_wcb, *p_wc, *p_qT, *p_kT, *p_bcomb;
    cudaGetSymbolAddress(&p_xs_h, g_xs_h); cudaGetSymbolAddress(&p_xs_l, g_xs_l);
    cudaGetSymbolAddress(&p_xw_h, g_xw_h); cudaGetSymbolAddress(&p_xw_l, g_xw_l);
    cudaGetSymbolAddress(&p_wq_h, g_wq_h); cudaGetSymbolAddress(&p_wq_l, g_wq_l);
    cudaGetSymbolAddress(&p_wk_h, g_wk_h); cudaGetSymbolAddress(&p_wk_l, g_wk_l);
    cudaGetSymbolAddress(&p_xwf, g_xwf); cudaGetSymbolAddress(&p_ag, g_ag);
    cudaGetSymbolAddress(&p_wcb, g_wcb); cudaGetSymbolAddress(&p_wc, g_wc);
    cudaGetSymbolAddress(&p_qT, g_qT); cudaGetSymbolAddress(&p_kT, g_kT);
    cudaGetSymbolAddress(&p_bcomb, g_bcomb);

    const int SMEM_DYN = 3 * 32768 + 1024;
    cudaFuncSetAttribute(mma_gemm<3, false, 1, true,  false, false>, cudaFuncAttributeMaxDynamicSharedMemorySize, SMEM_DYN);
    cudaFuncSetAttribute(mma_gemm<1, true,  0, true,  true,  false>, cudaFuncAttributeMaxDynamicSharedMemorySize, SMEM_DYN);
    cudaFuncSetAttribute(mma_gemm<1, true,  0, false, false, true >, cudaFuncAttributeMaxDynamicSharedMemorySize, SMEM_DYN);
    cudaFuncSetAttribute(fft_cross_kernel, cudaFuncAttributeMaxDynamicSharedMemorySize, 81920);
    cudaFuncSetAttribute(ifft_topk_kernel, cudaFuncAttributeMaxDynamicSharedMemorySize, 65536);

    // 1-5: init + weight combine + splits
    init_tw_kernel<<<8, 256>>>();
    zero_S_kernel<<<128, 256>>>();
    wcomb_gemm<<<dim3(16, 16), dim3(16, 16)>>>(Wo, Wv);
    bcomb_kernel<<<64, 256>>>(Wo, bv, bo);
    mega_split_kernel<<<36608, 256>>>((const float4*)x_s, (const float4*)x_w,
                                      (const float4*)Wq, (const float4*)Wk, Wconv);

    dim3 gg(4, 256);   // N/128 x M/128
    // 6: q = x_w @ Wq^T + bq  (3-pass bf16, transposed output -> [B,D,L])
    mma_gemm<3, false, 1, true, false, false><<<gg, 256, SMEM_DYN>>>(
        (const uint16_t*)p_xw_h, (const uint16_t*)p_xw_l,
        (const uint16_t*)p_wq_h, (const uint16_t*)p_wq_l,
        bq, nullptr, (float*)p_qT, 512);
    // 7: k = x_s @ Wk^T + bk  (3-pass bf16, transposed)
    mma_gemm<3, false, 1, true, false, false><<<gg, 256, SMEM_DYN>>>(
        (const uint16_t*)p_xs_h, (const uint16_t*)p_xs_l,
        (const uint16_t*)p_wk_h, (const uint16_t*)p_wk_l,
        bk, nullptr, (float*)p_kT, 512);

    // 8-9: correlation spectrum + top-k delays
    fft_cross_kernel<<<512, 256, 81920>>>();
    ifft_topk_kernel<<<8, 256, 65536>>>();

    // 10: aggregate fp16 x_s by delays (V/O projections commute with the convex roll combo)
    aggregate_kernel<<<8192, 256>>>();

    // 11: x_s_out = x_s + xagg @ (Wo Wv)^T + (Wo bv + bo)   (1-pass fp16)
    mma_gemm<1, true, 0, true, true, false><<<gg, 256, SMEM_DYN>>>(
        (const uint16_t*)p_ag, nullptr,
        (const uint16_t*)p_wcb, nullptr,
        (const float*)p_bcomb, x_s, out_s, 512);
    // 12: x_w_out = circular conv1d(x_w) as K=1536 GEMM   (1-pass fp16)
    mma_gemm<1, true, 0, false, false, true><<<gg, 256, SMEM_DYN>>>(
        (const uint16_t*)p_xwf, nullptr,
        (const uint16_t*)p_wc, nullptr,
        nullptr, nullptr, out_w, 1536);
}

// round 7
// speedup vs baseline: 4.6628x; 1.2541x over previous
#include <cuda_runtime.h>
#include <cuda_bf16.h>
#include <cuda_fp16.h>
#include <math.h>
#include <stdint.h>

// ---------------- problem constants ----------------
#define BB 8
#define LL 4096
#define DD 512
#define TOPK 8
#define NFFT 4096
static const size_t BLD = (size_t)BB * LL * DD;   // 16,777,216

// ---------------- device scratch (all GEMMs 1-pass fp16) ----------------
__device__ __half g_xsf[(size_t)BB * LL * DD];
__device__ __half g_xwf[(size_t)BB * LL * DD];
__device__ __half g_ag [(size_t)BB * LL * DD];
__device__ __half g_wqf[DD * DD];
__device__ __half g_wkf[DD * DD];
__device__ __half g_wcb[DD * DD];          // fp16(Wo @ Wv)
__device__ __half g_wc [DD * 1536];        // conv weights relaid [n][kk*512+i]
__device__ float g_wcomb[DD * DD];         // Wo @ Wv (fp32)
__device__ float g_bcomb[DD];              // Wo @ bv + bo
__device__ float g_qT[(size_t)BB * DD * LL];
__device__ float g_kT[(size_t)BB * DD * LL];
__device__ float2 g_S[BB * NFFT];
__device__ float2 g_tw[NFFT / 2];
__device__ float g_w[BB * TOPK];
__device__ int   g_delay[BB * TOPK];

// ---------------- helpers ----------------
__device__ __forceinline__ uint32_t smem_u32(const void* p) {
    uint32_t a;
    asm("{ .reg .u64 t; cvta.to.shared.u64 t, %1; cvt.u32.u64 %0, t; }" : "=r"(a) : "l"(p));
    return a;
}

__device__ __forceinline__ void ldmx4(uint32_t* r, uint32_t addr) {
    asm volatile("ldmatrix.sync.aligned.m8n8.x4.shared.b16 {%0,%1,%2,%3}, [%4];"
                 : "=r"(r[0]), "=r"(r[1]), "=r"(r[2]), "=r"(r[3]) : "r"(addr));
}

__device__ __forceinline__ void mma16816(float* d, const uint32_t* a, uint32_t b0, uint32_t b1) {
    asm volatile(
        "mma.sync.aligned.m16n8k16.row.col.f32.f16.f16.f32 "
        "{%0,%1,%2,%3}, {%4,%5,%6,%7}, {%8,%9}, {%0,%1,%2,%3};"
        : "+f"(d[0]), "+f"(d[1]), "+f"(d[2]), "+f"(d[3])
        : "r"(a[0]), "r"(a[1]), "r"(a[2]), "r"(a[3]), "r"(b0), "r"(b1));
}

#define CP_ASYNC16(dst, src) \
    asm volatile("cp.async.cg.shared.global [%0], [%1], 16;" :: "r"(dst), "l"(src))
#define CP_COMMIT() asm volatile("cp.async.commit_group;")
#define CP_WAIT2()  asm volatile("cp.async.wait_group 2;")
#define CP_WAIT1()  asm volatile("cp.async.wait_group 1;")
#define CP_WAIT0()  asm volatile("cp.async.wait_group 0;")

// 64-byte-row swizzle (Swizzle<2,4,3>)
__device__ __forceinline__ uint32_t sw64(uint32_t off) {
    return off ^ ((off >> 3) & 0x30);
}

// ---------------- init kernels ----------------
__global__ void init_tw_kernel() {
    int j = blockIdx.x * 256 + threadIdx.x;
    if (j < NFFT / 2) {
        float s, c;
        sincospif(-2.0f * (float)j / (float)NFFT, &s, &c);
        g_tw[j] = make_float2(c, s);
    }
}

__global__ void zero_S_kernel() {
    int i = blockIdx.x * 256 + threadIdx.x;
    if (i < BB * NFFT) g_S[i] = make_float2(0.f, 0.f);
}

// ---------------- Wcomb = Wo @ Wv (fp32) + fp16 copy + bcomb, one kernel ----------------
__global__ void wcomb_gemm(const float* __restrict__ Wo, const float* __restrict__ Wv,
                           const float* __restrict__ bv, const float* __restrict__ bo) {
    int blk = blockIdx.x;
    int tid = threadIdx.x;
    if (blk >= 256) {
        // bcomb: warp-per-output
        int o = (blk - 256) * 8 + (tid >> 5);
        int lane = tid & 31;
        float s = 0.f;
        for (int m = lane; m < 512; m += 32) s += Wo[o * 512 + m] * bv[m];
#pragma unroll
        for (int off = 16; off; off >>= 1) s += __shfl_xor_sync(0xFFFFFFFFu, s, off);
        if (lane == 0) g_bcomb[o] = s + bo[o];
        return;
    }
    __shared__ float As[32][33], Bs[32][33];
    int bi = (blk >> 4) * 32, bj = (blk & 15) * 32;
    int tx = tid & 15, ty = tid >> 4;
    float a00 = 0.f, a01 = 0.f, a10 = 0.f, a11 = 0.f;
    for (int m0 = 0; m0 < 512; m0 += 32) {
        for (int r = ty; r < 32; r += 16) {
            As[r][tx]      = Wo[(bi + r) * 512 + m0 + tx];
            As[r][tx + 16] = Wo[(bi + r) * 512 + m0 + tx + 16];
            Bs[r][tx]      = Wv[(m0 + r) * 512 + bj + tx];
            Bs[r][tx + 16] = Wv[(m0 + r) * 512 + bj + tx + 16];
        }
        __syncthreads();
#pragma unroll
        for (int m = 0; m < 32; ++m) {
            float x0 = As[ty][m], x1 = As[ty + 16][m];
            float y0 = Bs[m][tx], y1 = Bs[m][tx + 16];
            a00 += x0 * y0; a01 += x0 * y1; a10 += x1 * y0; a11 += x1 * y1;
        }
        __syncthreads();
    }
    int i00 = (bi + ty) * 512 + bj + tx;
    int i10 = (bi + ty + 16) * 512 + bj + tx;
    g_wcomb[i00] = a00;      g_wcomb[i00 + 16] = a01;
    g_wcomb[i10] = a10;      g_wcomb[i10 + 16] = a11;
    g_wcb[i00] = __float2half_rn(a00);      g_wcb[i00 + 16] = __float2half_rn(a01);
    g_wcb[i10] = __float2half_rn(a10);      g_wcb[i10 + 16] = __float2half_rn(a11);
}

// ---------------- mega convert: fp32 -> fp16 for xs, xw, Wq, Wk + conv relay ----------------
__device__ __forceinline__ void cvt_one4(const float4* __restrict__ x,
                                         __half2* __restrict__ f, int i) {
    float4 v = x[i];
    f[2 * i]     = __floats2half2_rn(v.x, v.y);
    f[2 * i + 1] = __floats2half2_rn(v.z, v.w);
}

__global__ void mega_split_kernel(const float4* __restrict__ xs,
                                  const float4* __restrict__ xw,
                                  const float4* __restrict__ Wq,
                                  const float4* __restrict__ Wk,
                                  const float* __restrict__ Wconv) {
    int bid = blockIdx.x;
    int tid = threadIdx.x;
    if (bid < 4096) {
        // 4 float4 per thread
        int base = bid * 1024 + tid;
#pragma unroll
        for (int j = 0; j < 4; ++j) cvt_one4(xs, (__half2*)g_xsf, base + j * 256);
    } else if (bid < 8192) {
        int base = (bid - 4096) * 1024 + tid;
#pragma unroll
        for (int j = 0; j < 4; ++j) cvt_one4(xw, (__half2*)g_xwf, base + j * 256);
    } else if (bid < 8448) {
        cvt_one4(Wq, (__half2*)g_wqf, (bid - 8192) * 256 + tid);
    } else if (bid < 8704) {
        cvt_one4(Wk, (__half2*)g_wkf, (bid - 8448) * 256 + tid);
    } else {
        int idx = (bid - 8704) * 256 + tid;         // conv relay, fp16; over 512*1536
        int n = idx / 1536;
        int r = idx - n * 1536;
        int kk = r >> 9;
        int i = r & 511;
        g_wc[idx] = __float2half_rn(Wconv[((size_t)n * 512 + i) * 3 + kk]);
    }
}

// ---------------- mma.sync fp16 GEMM (1-pass, 3-stage cp.async pipeline) ----------------
// K chunk = 32 halves = 64B rows. Stage stride 16KB: A +0 (8KB), B +8192.
template <bool CONV>
__device__ __forceinline__ void load_chunk(
    int ch, int stage, int K, int m0, int n0, int tid, uint32_t sbase,
    const __half* __restrict__ A, const __half* __restrict__ B)
{
    int k0 = ch << 5;
    uint32_t st = sbase + stage * 16384;
    int r = tid >> 1;                 // 0..127
    int seg0 = (tid & 1) << 1;        // 0 or 2

    size_t aoff;
    if (CONV) {
        int m = m0 + r;
        int kk = k0 >> 9;
        int ii = k0 & 511;
        int bb = m >> 12;
        int tt = ((m & 4095) + kk + 4095) & 4095;   // t + kk - 1 mod L
        aoff = (((size_t)(bb << 12) + tt) << 9) + ii;
    } else {
        aoff = ((size_t)(m0 + r) << 9) + k0;
    }
    size_t boff = (size_t)(n0 + r) * K + k0;

#pragma unroll
    for (int s2 = 0; s2 < 2; ++s2) {
        int seg = seg0 + s2;
        uint32_t soff = sw64((r << 6) + (seg << 4));
        CP_ASYNC16(st + soff, A + aoff + (seg << 3));
        CP_ASYNC16(st + 8192 + soff, B + boff + (seg << 3));
    }
    CP_COMMIT();
}

template <int TOUT, bool HAS_BIAS, bool HAS_RES, bool CONV>
__global__ void __launch_bounds__(256, 2) mma_gemm(
    const __half* __restrict__ A, const __half* __restrict__ B,
    const float* __restrict__ bias, const float* __restrict__ res,
    float* __restrict__ C, int K)
{
    extern __shared__ char smraw[];
    uint32_t sbase = (smem_u32(smraw) + 1023u) & ~1023u;

    const int tid = threadIdx.x;
    const int wid = tid >> 5;
    const int lane = tid & 31;
    const int wm = wid >> 2;    // 0..1 -> m offset 64*wm
    const int wn = wid & 3;     // 0..3 -> n offset 32*wn
    const int m0 = blockIdx.y << 7;
    const int n0 = blockIdx.x << 7;
    const int T = K >> 5;

    float acc[4][4][4];
#pragma unroll
    for (int i = 0; i < 4; ++i)
#pragma unroll
        for (int j = 0; j < 4; ++j)
#pragma unroll
            for (int r = 0; r < 4; ++r) acc[i][j][r] = 0.f;

    load_chunk<CONV>(0, 0, K, m0, n0, tid, sbase, A, B);
    load_chunk<CONV>(1, 1, K, m0, n0, tid, sbase, A, B);
    load_chunk<CONV>(2, 2, K, m0, n0, tid, sbase, A, B);

    const int lrow = lane & 15;
    const int lseg = lane >> 4;

    int s = 0;
    for (int it = 0; it < T; ++it) {
        int rem = T - 1 - it;
        if (rem >= 2) { CP_WAIT2(); } else if (rem == 1) { CP_WAIT1(); } else { CP_WAIT0(); }
        __syncthreads();

        uint32_t st = sbase + s * 16384;
#pragma unroll
        for (int ks = 0; ks < 2; ++ks) {
            int cseg = (ks << 1) + lseg;
            uint32_t a[4][4], b2[2][4];
#pragma unroll
            for (int mt = 0; mt < 4; ++mt) {
                int row = (wm << 6) + (mt << 4) + lrow;
                ldmx4(a[mt], st + sw64((row << 6) + (cseg << 4)));
            }
#pragma unroll
            for (int bt = 0; bt < 2; ++bt) {
                int row = (wn << 5) + (bt << 4) + lrow;
                ldmx4(b2[bt], st + 8192 + sw64((row << 6) + (cseg << 4)));
            }
#pragma unroll
            for (int mt = 0; mt < 4; ++mt)
#pragma unroll
                for (int nt = 0; nt < 4; ++nt)
                    mma16816(acc[mt][nt], a[mt],
                             b2[nt >> 1][nt & 1], b2[nt >> 1][(nt & 1) + 2]);
        }
        __syncthreads();
        if (it + 3 < T)
            load_chunk<CONV>(it + 3, s, K, m0, n0, tid, sbase, A, B);
        s = (s == 2) ? 0 : s + 1;
    }

    // ---------------- epilogue ----------------
    const int er = lane >> 2;            // 0..7
    const int ec = (lane & 3) << 1;      // 0,2,4,6
    if (TOUT == 1) {
        // transpose through smem, then coalesced rows into [B, D, L]
        float* stf = (float*)smraw;
#pragma unroll
        for (int mt = 0; mt < 4; ++mt)
#pragma unroll
            for (int nt = 0; nt < 4; ++nt) {
                int r0 = (wm << 6) + (mt << 4) + er;
                int c0 = (wn << 5) + (nt << 3) + ec;
                stf[c0 * 130 + r0]            = acc[mt][nt][0];
                stf[(c0 + 1) * 130 + r0]      = acc[mt][nt][1];
                stf[c0 * 130 + r0 + 8]        = acc[mt][nt][2];
                stf[(c0 + 1) * 130 + r0 + 8]  = acc[mt][nt][3];
            }
        __syncthreads();
        int bb = m0 >> 12, l0 = m0 & 4095;
#pragma unroll
        for (int i = 0; i < 16; ++i) {
            int idx = tid + (i << 8);
            int c = idx >> 5;            // 0..127
            int rq = (idx & 31) << 2;    // 0..124 step 4
            float4 v;
            v.x = stf[c * 130 + rq];
            v.y = stf[c * 130 + rq + 1];
            v.z = stf[c * 130 + rq + 2];
            v.w = stf[c * 130 + rq + 3];
            if (HAS_BIAS) {
                float bval = bias[n0 + c];
                v.x += bval; v.y += bval; v.z += bval; v.w += bval;
            }
            *(float4*)&C[(((size_t)(bb << 9) + n0 + c) << 12) + l0 + rq] = v;
        }
    } else {
#pragma unroll
        for (int mt = 0; mt < 4; ++mt) {
#pragma unroll
            for (int nt = 0; nt < 4; ++nt) {
                int r0 = m0 + (wm << 6) + (mt << 4) + er;
                int r1 = r0 + 8;
                int c0 = n0 + (wn << 5) + (nt << 3) + ec;
                float v0 = acc[mt][nt][0], v1 = acc[mt][nt][1];
                float v2 = acc[mt][nt][2], v3 = acc[mt][nt][3];
                if (HAS_BIAS) {
                    float b0 = bias[c0], b1 = bias[c0 + 1];
                    v0 += b0; v1 += b1; v2 += b0; v3 += b1;
                }
                size_t o0 = ((size_t)r0 << 9) + c0;
                size_t o1 = ((size_t)r1 << 9) + c0;
                if (HAS_RES) {
                    const float2 q0 = *(const float2*)&res[o0];
                    const float2 q1 = *(const float2*)&res[o1];
                    v0 += q0.x; v1 += q0.y; v2 += q1.x; v3 += q1.y;
                }
                *(float2*)&C[o0] = make_float2(v0, v1);
                *(float2*)&C[o1] = make_float2(v2, v3);
            }
        }
    }
}

// ---------------- fused radix-4 FFT stages ----------------
__device__ __forceinline__ float2 cmulf(float2 w, float2 z) {
    return make_float2(w.x * z.x - w.y * z.y, w.x * z.y + w.y * z.x);
}

__device__ __forceinline__ void fft_stages_r4(float2* zs, const float2* tw, int tid) {
#pragma unroll
    for (int p = 0; p < 6; ++p) {
        const int h = 1 << (2 * p);
#pragma unroll
        for (int jj = 0; jj < 4; ++jj) {
            int j = tid + (jj << 8);
            int pos = j & (h - 1);
            int grp = j >> (2 * p);
            int base = (grp << (2 * p + 2)) + pos;
            float2 a = zs[base], b = zs[base + h], c = zs[base + 2 * h], d = zs[base + 3 * h];
            float2 w1 = tw[pos << (11 - 2 * p)];
            float2 w2 = tw[pos << (10 - 2 * p)];
            float2 wb = cmulf(w1, b), wd = cmulf(w1, d);
            float2 a1 = make_float2(a.x + wb.x, a.y + wb.y);
            float2 b1 = make_float2(a.x - wb.x, a.y - wb.y);
            float2 c1 = make_float2(c.x + wd.x, c.y + wd.y);
            float2 d1 = make_float2(c.x - wd.x, c.y - wd.y);
            float2 wc2 = cmulf(w2, c1), wd2 = cmulf(w2, d1);
            zs[base]         = make_float2(a1.x + wc2.x, a1.y + wc2.y);
            zs[base + 2 * h] = make_float2(a1.x - wc2.x, a1.y - wc2.y);
            zs[base + h]     = make_float2(b1.x + wd2.y, b1.y - wd2.x);
            zs[base + 3 * h] = make_float2(b1.x - wd2.y, b1.y + wd2.x);
        }
        __syncthreads();
    }
}

// ---------------- cross-spectrum accumulation ----------------
__global__ void fft_cross_kernel() {
    extern __shared__ float2 sm[];
    float2* zs  = sm;            // 4096
    float2* tw  = sm + 4096;     // 2048
    float2* acc = sm + 6144;     // 4096

    int tid = threadIdx.x;
    int b = blockIdx.x >> 6;
    int dg = (blockIdx.x & 63) << 3;

    for (int j = tid; j < 2048; j += 256) tw[j] = g_tw[j];
    for (int f = tid; f < 4096; f += 256) acc[f] = make_float2(0.f, 0.f);

    for (int c = 0; c < 8; ++c) {
        int d = dg + c;
        const float* qrow = g_qT + (((size_t)b * DD + d) << 12);
        const float* krow = g_kT + (((size_t)b * DD + d) << 12);
        __syncthreads();
        for (int t = tid; t < 4096; t += 256) {
            int r = (int)(__brev((unsigned)t) >> 20);
            zs[r] = make_float2(qrow[t], krow[t]);
        }
        __syncthreads();
        fft_stages_r4(zs, tw, tid);
        for (int f = tid; f < 4096; f += 256) {
            float2 Zf = zs[f];
            float2 Zc = zs[(4096 - f) & 4095];
            float Qr = 0.5f * (Zf.x + Zc.x);
            float Qi = 0.5f * (Zf.y - Zc.y);
            float Kr = 0.5f * (Zf.y + Zc.y);
            float Ki = 0.5f * (Zc.x - Zf.x);
            float2 a2 = acc[f];
            a2.x += Qr * Kr + Qi * Ki;
            a2.y += Qi * Kr - Qr * Ki;
            acc[f] = a2;
        }
    }
    __syncthreads();
    for (int f = tid; f < 4096; f += 256) {
        atomicAdd(&g_S[(b << 12) + f].x, acc[f].x);
        atomicAdd(&g_S[(b << 12) + f].y, acc[f].y);
    }
}

// ---------------- inverse FFT + top-k + softmax ----------------
__global__ void ifft_topk_kernel() {
    extern __shared__ float2 sm[];
    float2* zs = sm;                       // 4096
    float2* tw = sm + 4096;                // 2048
    float*  mv = (float*)(sm + 6144);      // 4096

    __shared__ float red_v[256];
    __shared__ int   red_i[256];
    __shared__ float s_tv[TOPK];
    __shared__ int   s_ti[TOPK];

    int tid = threadIdx.x;
    int b = blockIdx.x;

    for (int j = tid; j < 2048; j += 256) tw[j] = g_tw[j];
    for (int f = tid; f < 4096; f += 256) {
        int r = (int)(__brev((unsigned)f) >> 20);
        float2 s = g_S[(b << 12) + f];
        zs[r] = make_float2(s.x, -s.y);
    }
    __syncthreads();
    fft_stages_r4(zs, tw, tid);

    const float scale = 1.0f / (4096.0f * 512.0f);
    for (int n = tid; n < 4096; n += 256) mv[n] = zs[n].x * scale;
    __syncthreads();

    for (int it = 0; it < TOPK; ++it) {
        float bv = -3.402823e38f; int bi = 1 << 30;
        for (int n = tid; n < 4096; n += 256) {
            float v = mv[n];
            if (v > bv || (v == bv && n < bi)) { bv = v; bi = n; }
        }
        red_v[tid] = bv; red_i[tid] = bi;
        __syncthreads();
        for (int s = 128; s > 0; s >>= 1) {
            if (tid < s) {
                float v2 = red_v[tid + s]; int i2 = red_i[tid + s];
                if (v2 > red_v[tid] || (v2 == red_v[tid] && i2 < red_i[tid])) {
                    red_v[tid] = v2; red_i[tid] = i2;
                }
            }
            __syncthreads();
        }
        if (tid == 0) {
            s_tv[it] = red_v[0]; s_ti[it] = red_i[0];
            mv[red_i[0]] = -3.402823e38f;
        }
        __syncthreads();
    }

    if (tid == 0) {
        float mx = s_tv[0];
        float ex[TOPK]; float sum = 0.f;
        for (int i = 0; i < TOPK; ++i) { ex[i] = expf(s_tv[i] - mx); sum += ex[i]; }
        for (int i = 0; i < TOPK; ++i) {
            g_w[b * TOPK + i] = ex[i] / sum;
            g_delay[b * TOPK + i] = s_ti[i];
        }
    }
}

// ---------------- aggregation on fp16 x_s ----------------
__global__ void aggregate_kernel() {
    size_t idx = (size_t)blockIdx.x * 256 + threadIdx.x;   // over 32768 rows x 64 groups
    int grp = (int)(idx & 63);        // 8-half group
    size_t row = idx >> 6;
    int b = (int)(row >> 12);
    int t = (int)(row & 4095);

    float wloc[TOPK]; int dloc[TOPK];
#pragma unroll
    for (int i = 0; i < TOPK; ++i) { wloc[i] = g_w[b * TOPK + i]; dloc[i] = g_delay[b * TOPK + i]; }

    float acc[8];
#pragma unroll
    for (int j = 0; j < 8; ++j) acc[j] = 0.f;

#pragma unroll
    for (int i = 0; i < TOPK; ++i) {
        int ts = (t + dloc[i]) & 4095;
        const uint4 raw = *(const uint4*)(g_xsf + (((size_t)(b << 12) + ts) << 9) + (grp << 3));
        const __half2* p = (const __half2*)&raw;
        float w = wloc[i];
#pragma unroll
        for (int j = 0; j < 4; ++j) {
            float2 f = __half22float2(p[j]);
            acc[2 * j]     += w * f.x;
            acc[2 * j + 1] += w * f.y;
        }
    }
    uint4 out;
    __half2* po = (__half2*)&out;
#pragma unroll
    for (int j = 0; j < 4; ++j) po[j] = __floats2half2_rn(acc[2 * j], acc[2 * j + 1]);
    *(uint4*)(g_ag + (row << 9) + (grp << 3)) = out;
}

// ---------------- host launch ----------------
extern "C" void kernel_launch(void* const* d_in, const int* in_sizes, int n_in,
                              void* d_out, int out_size) {
    const float* x_s   = (const float*)d_in[0];
    const float* x_w   = (const float*)d_in[1];
    const float* Wq    = (const float*)d_in[2];
    const float* bq    = (const float*)d_in[3];
    const float* Wk    = (const float*)d_in[4];
    const float* bk    = (const float*)d_in[5];
    const float* Wv    = (const float*)d_in[6];
    const float* bv    = (const float*)d_in[7];
    const float* Wo    = (const float*)d_in[8];
    const float* bo    = (const float*)d_in[9];
    const float* Wconv = (const float*)d_in[10];

    float* out_s = (float*)d_out;
    float* out_w = out_s + BLD;

    void *p_xsf, *p_xwf, *p_ag, *p_wqf, *p_wkf, *p_wcb, *p_wc, *p_qT, *p_kT, *p_bcomb;
    cudaGetSymbolAddress(&p_xsf, g_xsf); cudaGetSymbolAddress(&p_xwf, g_xwf);
    cudaGetSymbolAddress(&p_ag, g_ag);
    cudaGetSymbolAddress(&p_wqf, g_wqf); cudaGetSymbolAddress(&p_wkf, g_wkf);
    cudaGetSymbolAddress(&p_wcb, g_wcb); cudaGetSymbolAddress(&p_wc, g_wc);
    cudaGetSymbolAddress(&p_qT, g_qT); cudaGetSymbolAddress(&p_kT, g_kT);
    cudaGetSymbolAddress(&p_bcomb, g_bcomb);

    const int SMEM_DYN = 3 * 16384 + 1024 + 2048;   // 3 pipeline stages + align pad (>=66KB for epi transpose: 130*128*4=66560... see below)
    // TOUT=1 epilogue needs 128*130*4 = 66560 B of smem; pipeline needs 3*16384+1024 = 50176.
    const int SMEM_USE = 68608;
    cudaFuncSetAttribute(mma_gemm<1, true,  false, false>, cudaFuncAttributeMaxDynamicSharedMemorySize, SMEM_USE);
    cudaFuncSetAttribute(mma_gemm<0, true,  true,  false>, cudaFuncAttributeMaxDynamicSharedMemorySize, SMEM_USE);
    cudaFuncSetAttribute(mma_gemm<0, false, false, true >, cudaFuncAttributeMaxDynamicSharedMemorySize, SMEM_USE);
    cudaFuncSetAttribute(fft_cross_kernel, cudaFuncAttributeMaxDynamicSharedMemorySize, 81920);
    cudaFuncSetAttribute(ifft_topk_kernel, cudaFuncAttributeMaxDynamicSharedMemorySize, 65536);
    (void)SMEM_DYN;

    // 1-4: init + weight combine + fp16 conversions
    init_tw_kernel<<<8, 256>>>();
    zero_S_kernel<<<128, 256>>>();
    wcomb_gemm<<<320, 256>>>(Wo, Wv, bv, bo);
    mega_split_kernel<<<11776, 256>>>((const float4*)x_s, (const float4*)x_w,
                                      (const float4*)Wq, (const float4*)Wk, Wconv);

    dim3 gg(4, 256);   // N/128 x M/128
    // 5: q = x_w @ Wq^T + bq  (fp16, transposed output -> [B,D,L])
    mma_gemm<1, true, false, false><<<gg, 256, SMEM_USE>>>(
        (const __half*)p_xwf, (const __half*)p_wqf, bq, nullptr, (float*)p_qT, 512);
    // 6: k = x_s @ Wk^T + bk  (fp16, transposed)
    mma_gemm<1, true, false, false><<<gg, 256, SMEM_USE>>>(
        (const __half*)p_xsf, (const __half*)p_wkf, bk, nullptr, (float*)p_kT, 512);

    // 7-8: correlation spectrum + top-k delays
    fft_cross_kernel<<<512, 256, 81920>>>();
    ifft_topk_kernel<<<8, 256, 65536>>>();

    // 9: aggregate fp16 x_s by delays (V/O projections commute with the convex roll combo)
    aggregate_kernel<<<8192, 256>>>();

    // 10: x_s_out = x_s + xagg @ (Wo Wv)^T + (Wo bv + bo)
    mma_gemm<0, true, true, false><<<gg, 256, SMEM_USE>>>(
        (const __half*)p_ag, (const __half*)p_wcb, (const float*)p_bcomb, x_s, out_s, 512);
    // 11: x_w_out = circular conv1d(x_w) as K=1536 GEMM
    mma_gemm<0, false, false, true><<<gg, 256, SMEM_USE>>>(
        (const __half*)p_xwf, (const __half*)p_wc, nullptr, nullptr, out_w, 1536);
}

// round 8
// speedup vs baseline: 5.2170x; 1.1188x over previous
#include <cuda_runtime.h>
#include <cuda_fp16.h>
#include <math.h>
#include <stdint.h>

// ---------------- problem constants ----------------
#define BB 8
#define LL 4096
#define DD 512
#define TOPK 8
#define NFFT 4096
static const size_t BLD = (size_t)BB * LL * DD;   // 16,777,216

// ---------------- device scratch ----------------
__device__ __half g_xsf[(size_t)BB * LL * DD];
__device__ __half g_xwf[(size_t)BB * LL * DD];
__device__ __half g_P  [(size_t)BB * LL * DD];      // x_s @ (Wo Wv)^T, fp16, normal layout
__device__ __half g_qTh[(size_t)BB * DD * LL];      // q transposed [B,D,L] fp16
__device__ __half g_kTh[(size_t)BB * DD * LL];
__device__ __half g_wqf[DD * DD];
__device__ __half g_wkf[DD * DD];
__device__ __half g_wcb[DD * DD];          // fp16(Wo @ Wv)
__device__ __half g_wc [DD * 1536];        // conv weights relaid [n][kk*512+i]
__device__ float g_wcomb[DD * DD];         // Wo @ Wv (fp32)
__device__ float g_bcomb[DD];              // Wo @ bv + bo
__device__ float2 g_S[BB * 2049];          // Hermitian half-spectrum per batch
__device__ float2 g_tw[NFFT / 2];
__device__ float g_w[BB * TOPK];
__device__ int   g_delay[BB * TOPK];

// ---------------- helpers ----------------
__device__ __forceinline__ uint32_t smem_u32(const void* p) {
    uint32_t a;
    asm("{ .reg .u64 t; cvta.to.shared.u64 t, %1; cvt.u32.u64 %0, t; }" : "=r"(a) : "l"(p));
    return a;
}

__device__ __forceinline__ void ldmx4(uint32_t* r, uint32_t addr) {
    asm volatile("ldmatrix.sync.aligned.m8n8.x4.shared.b16 {%0,%1,%2,%3}, [%4];"
                 : "=r"(r[0]), "=r"(r[1]), "=r"(r[2]), "=r"(r[3]) : "r"(addr));
}

__device__ __forceinline__ void mma16816(float* d, const uint32_t* a, uint32_t b0, uint32_t b1) {
    asm volatile(
        "mma.sync.aligned.m16n8k16.row.col.f32.f16.f16.f32 "
        "{%0,%1,%2,%3}, {%4,%5,%6,%7}, {%8,%9}, {%0,%1,%2,%3};"
        : "+f"(d[0]), "+f"(d[1]), "+f"(d[2]), "+f"(d[3])
        : "r"(a[0]), "r"(a[1]), "r"(a[2]), "r"(a[3]), "r"(b0), "r"(b1));
}

#define CP_ASYNC16(dst, src) \
    asm volatile("cp.async.cg.shared.global [%0], [%1], 16;" :: "r"(dst), "l"(src))
#define CP_COMMIT() asm volatile("cp.async.commit_group;")
#define CP_WAIT2()  asm volatile("cp.async.wait_group 2;")
#define CP_WAIT1()  asm volatile("cp.async.wait_group 1;")
#define CP_WAIT0()  asm volatile("cp.async.wait_group 0;")

__device__ __forceinline__ uint32_t sw64(uint32_t off) {
    return off ^ ((off >> 3) & 0x30);
}

// ---------------- init kernels ----------------
__global__ void init_tw_kernel() {
    int j = blockIdx.x * 256 + threadIdx.x;
    if (j < NFFT / 2) {
        float s, c;
        sincospif(-2.0f * (float)j / (float)NFFT, &s, &c);
        g_tw[j] = make_float2(c, s);
    }
}

__global__ void zero_S_kernel() {
    int i = blockIdx.x * 256 + threadIdx.x;
    if (i < BB * 2049) g_S[i] = make_float2(0.f, 0.f);
}

// ---------------- Wcomb = Wo @ Wv (fp32) + fp16 copy + bcomb ----------------
__global__ void wcomb_gemm(const float* __restrict__ Wo, const float* __restrict__ Wv,
                           const float* __restrict__ bv, const float* __restrict__ bo) {
    int blk = blockIdx.x;
    int tid = threadIdx.x;
    if (blk >= 256) {
        int o = (blk - 256) * 8 + (tid >> 5);
        int lane = tid & 31;
        float s = 0.f;
        for (int m = lane; m < 512; m += 32) s += Wo[o * 512 + m] * bv[m];
#pragma unroll
        for (int off = 16; off; off >>= 1) s += __shfl_xor_sync(0xFFFFFFFFu, s, off);
        if (lane == 0) g_bcomb[o] = s + bo[o];
        return;
    }
    __shared__ float As[32][33], Bs[32][33];
    int bi = (blk >> 4) * 32, bj = (blk & 15) * 32;
    int tx = tid & 15, ty = tid >> 4;
    float a00 = 0.f, a01 = 0.f, a10 = 0.f, a11 = 0.f;
    for (int m0 = 0; m0 < 512; m0 += 32) {
        for (int r = ty; r < 32; r += 16) {
            As[r][tx]      = Wo[(bi + r) * 512 + m0 + tx];
            As[r][tx + 16] = Wo[(bi + r) * 512 + m0 + tx + 16];
            Bs[r][tx]      = Wv[(m0 + r) * 512 + bj + tx];
            Bs[r][tx + 16] = Wv[(m0 + r) * 512 + bj + tx + 16];
        }
        __syncthreads();
#pragma unroll
        for (int m = 0; m < 32; ++m) {
            float x0 = As[ty][m], x1 = As[ty + 16][m];
            float y0 = Bs[m][tx], y1 = Bs[m][tx + 16];
            a00 += x0 * y0; a01 += x0 * y1; a10 += x1 * y0; a11 += x1 * y1;
        }
        __syncthreads();
    }
    int i00 = (bi + ty) * 512 + bj + tx;
    int i10 = (bi + ty + 16) * 512 + bj + tx;
    g_wcomb[i00] = a00;      g_wcomb[i00 + 16] = a01;
    g_wcomb[i10] = a10;      g_wcomb[i10 + 16] = a11;
    g_wcb[i00] = __float2half_rn(a00);      g_wcb[i00 + 16] = __float2half_rn(a01);
    g_wcb[i10] = __float2half_rn(a10);      g_wcb[i10 + 16] = __float2half_rn(a11);
}

// ---------------- mega convert: fp32 -> fp16 ----------------
__device__ __forceinline__ void cvt_one4(const float4* __restrict__ x,
                                         __half2* __restrict__ f, int i) {
    float4 v = x[i];
    f[2 * i]     = __floats2half2_rn(v.x, v.y);
    f[2 * i + 1] = __floats2half2_rn(v.z, v.w);
}

__global__ void mega_split_kernel(const float4* __restrict__ xs,
                                  const float4* __restrict__ xw,
                                  const float4* __restrict__ Wq,
                                  const float4* __restrict__ Wk,
                                  const float* __restrict__ Wconv) {
    int bid = blockIdx.x;
    int tid = threadIdx.x;
    if (bid < 4096) {
        int base = bid * 1024 + tid;
#pragma unroll
        for (int j = 0; j < 4; ++j) cvt_one4(xs, (__half2*)g_xsf, base + j * 256);
    } else if (bid < 8192) {
        int base = (bid - 4096) * 1024 + tid;
#pragma unroll
        for (int j = 0; j < 4; ++j) cvt_one4(xw, (__half2*)g_xwf, base + j * 256);
    } else if (bid < 8448) {
        cvt_one4(Wq, (__half2*)g_wqf, (bid - 8192) * 256 + tid);
    } else if (bid < 8704) {
        cvt_one4(Wk, (__half2*)g_wkf, (bid - 8448) * 256 + tid);
    } else {
        int idx = (bid - 8704) * 256 + tid;         // conv relay; over 512*1536
        int n = idx / 1536;
        int r = idx - n * 1536;
        int kk = r >> 9;
        int i = r & 511;
        g_wc[idx] = __float2half_rn(Wconv[((size_t)n * 512 + i) * 3 + kk]);
    }
}

// ---------------- mega GEMM: conv + q + k + P in one launch ----------------
// mode 0: out_w = conv(x_w)         [K=1536, CONV addressing, fp32 normal out]
// mode 1: qT = x_w @ Wq^T + bq      [fp16 transposed out]
// mode 2: kT = x_s @ Wk^T + bk      [fp16 transposed out]
// mode 3: P  = x_s @ Wcomb^T        [fp16 normal out]
__device__ __forceinline__ void load_chunk_rt(
    int ch, int stage, int K, bool conv, int m0, int n0, int tid, uint32_t sbase,
    const __half* __restrict__ A, const __half* __restrict__ B)
{
    int k0 = ch << 5;
    uint32_t st = sbase + stage * 16384;
    int r = tid >> 1;
    int seg0 = (tid & 1) << 1;

    size_t aoff;
    if (conv) {
        int m = m0 + r;
        int kk = k0 >> 9;
        int ii = k0 & 511;
        int bb = m >> 12;
        int tt = ((m & 4095) + kk + 4095) & 4095;   // t + kk - 1 mod L
        aoff = (((size_t)(bb << 12) + tt) << 9) + ii;
    } else {
        aoff = ((size_t)(m0 + r) << 9) + k0;
    }
    size_t boff = (size_t)(n0 + r) * K + k0;

#pragma unroll
    for (int s2 = 0; s2 < 2; ++s2) {
        int seg = seg0 + s2;
        uint32_t soff = sw64((r << 6) + (seg << 4));
        CP_ASYNC16(st + soff, A + aoff + (seg << 3));
        CP_ASYNC16(st + 8192 + soff, B + boff + (seg << 3));
    }
    CP_COMMIT();
}

__global__ void __launch_bounds__(256, 2) mega_gemm(
    const __half* __restrict__ xsf, const __half* __restrict__ xwf,
    const __half* __restrict__ wq, const __half* __restrict__ wk,
    const __half* __restrict__ wcb, const __half* __restrict__ wc,
    const float* __restrict__ bq, const float* __restrict__ bk,
    float* __restrict__ out_w, __half* __restrict__ qT, __half* __restrict__ kT,
    __half* __restrict__ P)
{
    extern __shared__ char smraw[];
    uint32_t sbase = (smem_u32(smraw) + 1023u) & ~1023u;

    const int id = blockIdx.x;
    const int mode = id >> 10;          // 0 conv, 1 q, 2 k, 3 P
    const int rr = id & 1023;
    const int m0 = (rr >> 2) << 7;
    const int n0 = (rr & 3) << 7;
    const __half* A = (mode <= 1) ? ((mode == 1) ? xwf : xwf) : xsf;  // conv & q use xw
    const __half* B = (mode == 0) ? wc : (mode == 1) ? wq : (mode == 2) ? wk : wcb;
    const int K = (mode == 0) ? 1536 : 512;
    const bool conv = (mode == 0);
    const int T = K >> 5;

    const int tid = threadIdx.x;
    const int wid = tid >> 5;
    const int lane = tid & 31;
    const int wm = wid >> 2;
    const int wn = wid & 3;

    float acc[4][4][4];
#pragma unroll
    for (int i = 0; i < 4; ++i)
#pragma unroll
        for (int j = 0; j < 4; ++j)
#pragma unroll
            for (int r = 0; r < 4; ++r) acc[i][j][r] = 0.f;

    load_chunk_rt(0, 0, K, conv, m0, n0, tid, sbase, A, B);
    load_chunk_rt(1, 1, K, conv, m0, n0, tid, sbase, A, B);
    load_chunk_rt(2, 2, K, conv, m0, n0, tid, sbase, A, B);

    const int lrow = lane & 15;
    const int lseg = lane >> 4;

    int s = 0;
    for (int it = 0; it < T; ++it) {
        int rem = T - 1 - it;
        if (rem >= 2) { CP_WAIT2(); } else if (rem == 1) { CP_WAIT1(); } else { CP_WAIT0(); }
        __syncthreads();

        uint32_t st = sbase + s * 16384;
#pragma unroll
        for (int ks = 0; ks < 2; ++ks) {
            int cseg = (ks << 1) + lseg;
            uint32_t a[4][4], b2[2][4];
#pragma unroll
            for (int mt = 0; mt < 4; ++mt) {
                int row = (wm << 6) + (mt << 4) + lrow;
                ldmx4(a[mt], st + sw64((row << 6) + (cseg << 4)));
            }
#pragma unroll
            for (int bt = 0; bt < 2; ++bt) {
                int row = (wn << 5) + (bt << 4) + lrow;
                ldmx4(b2[bt], st + 8192 + sw64((row << 6) + (cseg << 4)));
            }
#pragma unroll
            for (int mt = 0; mt < 4; ++mt)
#pragma unroll
                for (int nt = 0; nt < 4; ++nt)
                    mma16816(acc[mt][nt], a[mt],
                             b2[nt >> 1][nt & 1], b2[nt >> 1][(nt & 1) + 2]);
        }
        __syncthreads();
        if (it + 3 < T)
            load_chunk_rt(it + 3, s, K, conv, m0, n0, tid, sbase, A, B);
        s = (s == 2) ? 0 : s + 1;
    }

    // ---------------- epilogue ----------------
    const int er = lane >> 2;
    const int ec = (lane & 3) << 1;
    if (mode == 0) {
        // fp32 normal, no bias
#pragma unroll
        for (int mt = 0; mt < 4; ++mt)
#pragma unroll
            for (int nt = 0; nt < 4; ++nt) {
                int r0 = m0 + (wm << 6) + (mt << 4) + er;
                int c0 = n0 + (wn << 5) + (nt << 3) + ec;
                size_t o0 = ((size_t)r0 << 9) + c0;
                size_t o1 = ((size_t)(r0 + 8) << 9) + c0;
                *(float2*)&out_w[o0] = make_float2(acc[mt][nt][0], acc[mt][nt][1]);
                *(float2*)&out_w[o1] = make_float2(acc[mt][nt][2], acc[mt][nt][3]);
            }
    } else if (mode == 3) {
        // fp16 normal, no bias
#pragma unroll
        for (int mt = 0; mt < 4; ++mt)
#pragma unroll
            for (int nt = 0; nt < 4; ++nt) {
                int r0 = m0 + (wm << 6) + (mt << 4) + er;
                int c0 = n0 + (wn << 5) + (nt << 3) + ec;
                *(__half2*)&P[((size_t)r0 << 9) + c0] =
                    __floats2half2_rn(acc[mt][nt][0], acc[mt][nt][1]);
                *(__half2*)&P[((size_t)(r0 + 8) << 9) + c0] =
                    __floats2half2_rn(acc[mt][nt][2], acc[mt][nt][3]);
            }
    } else {
        // fp16 transposed via smem into [B, D, L]
        __half* sth = (__half*)smraw;    // 128 cols x 136-stride halves = 34.8KB
        const float* bias = (mode == 1) ? bq : bk;
        __half* Cout = (mode == 1) ? qT : kT;
#pragma unroll
        for (int mt = 0; mt < 4; ++mt)
#pragma unroll
            for (int nt = 0; nt < 4; ++nt) {
                int r0 = (wm << 6) + (mt << 4) + er;
                int c0 = (wn << 5) + (nt << 3) + ec;
                float b0v = bias[n0 + c0], b1v = bias[n0 + c0 + 1];
                sth[c0 * 136 + r0]            = __float2half_rn(acc[mt][nt][0] + b0v);
                sth[(c0 + 1) * 136 + r0]      = __float2half_rn(acc[mt][nt][1] + b1v);
                sth[c0 * 136 + r0 + 8]        = __float2half_rn(acc[mt][nt][2] + b0v);
                sth[(c0 + 1) * 136 + r0 + 8]  = __float2half_rn(acc[mt][nt][3] + b1v);
            }
        __syncthreads();
        int bb = m0 >> 12, l0 = m0 & 4095;
#pragma unroll
        for (int i = 0; i < 8; ++i) {
            int idx = tid + (i << 8);
            int c = idx >> 4;              // 0..127
            int g8 = (idx & 15) << 3;      // 0..120 step 8
            uint4 v = *(uint4*)&sth[c * 136 + g8];
            *(uint4*)&Cout[(((size_t)(bb << 9) + n0 + c) << 12) + l0 + g8] = v;
        }
    }
}

// ---------------- fused radix-8 FFT (4 passes over 12 radix-2 stages) ----------------
__device__ __forceinline__ float2 cmulf(float2 w, float2 z) {
    return make_float2(w.x * z.x - w.y * z.y, w.x * z.y + w.y * z.x);
}
__device__ __forceinline__ float2 mni(float2 u) {          // -i * u
    return make_float2(u.y, -u.x);
}
__device__ __forceinline__ float2 rot45(float2 u) {        // e^{-i pi/4} * u
    const float r = 0.70710678118654752f;
    return make_float2(r * (u.x + u.y), r * (u.y - u.x));
}
__device__ __forceinline__ float2 cadd(float2 a, float2 b) { return make_float2(a.x + b.x, a.y + b.y); }
__device__ __forceinline__ float2 csub(float2 a, float2 b) { return make_float2(a.x - b.x, a.y - b.y); }

__device__ __forceinline__ void fft_stages_r8(float2* zs, const float2* tw, int tid) {
#pragma unroll
    for (int p = 0; p < 4; ++p) {
        const int h = 1 << (3 * p);
#pragma unroll
        for (int jj = 0; jj < 2; ++jj) {
            int j = tid + (jj << 8);                 // 0..511
            int pos = j & (h - 1);
            int grp = j >> (3 * p);
            int base = (grp << (3 * p + 3)) + pos;
            float2 x0 = zs[base],         x1 = zs[base + h];
            float2 x2 = zs[base + 2 * h], x3 = zs[base + 3 * h];
            float2 x4 = zs[base + 4 * h], x5 = zs[base + 5 * h];
            float2 x6 = zs[base + 6 * h], x7 = zs[base + 7 * h];
            float2 wA = tw[pos << (11 - 3 * p)];
            float2 wB = tw[pos << (10 - 3 * p)];
            float2 wC = tw[pos << (9 - 3 * p)];
            float2 t;
            t = cmulf(wA, x1); float2 a0 = cadd(x0, t), a1 = csub(x0, t);
            t = cmulf(wA, x3); float2 a2 = cadd(x2, t), a3 = csub(x2, t);
            t = cmulf(wA, x5); float2 a4 = cadd(x4, t), a5 = csub(x4, t);
            t = cmulf(wA, x7); float2 a6 = cadd(x6, t), a7 = csub(x6, t);
            t = cmulf(wB, a2);      float2 b0 = cadd(a0, t), b2 = csub(a0, t);
            t = mni(cmulf(wB, a3)); float2 b1 = cadd(a1, t), b3 = csub(a1, t);
            t = cmulf(wB, a6);      float2 b4 = cadd(a4, t), b6 = csub(a4, t);
            t = mni(cmulf(wB, a7)); float2 b5 = cadd(a5, t), b7 = csub(a5, t);
            t = cmulf(wC, b4);             zs[base]         = cadd(b0, t); zs[base + 4 * h] = csub(b0, t);
            t = rot45(cmulf(wC, b5));      zs[base + h]     = cadd(b1, t); zs[base + 5 * h] = csub(b1, t);
            t = mni(cmulf(wC, b6));        zs[base + 2 * h] = cadd(b2, t); zs[base + 6 * h] = csub(b2, t);
            t = mni(rot45(cmulf(wC, b7))); zs[base + 3 * h] = cadd(b3, t); zs[base + 7 * h] = csub(b3, t);
        }
        __syncthreads();
    }
}

// ---------------- cross-spectrum accumulation (Hermitian half) ----------------
__global__ void fft_cross_kernel() {
    extern __shared__ float2 sm[];
    float2* zs  = sm;            // 4096
    float2* tw  = sm + 4096;     // 2048
    float2* acc = sm + 6144;     // 2049

    int tid = threadIdx.x;
    int b = blockIdx.x >> 6;
    int dg = (blockIdx.x & 63) << 3;

    for (int j = tid; j < 2048; j += 256) tw[j] = g_tw[j];
    for (int f = tid; f <= 2048; f += 256) acc[f] = make_float2(0.f, 0.f);

    for (int c = 0; c < 8; ++c) {
        int d = dg + c;
        const __half2* qrow = (const __half2*)(g_qTh + (((size_t)b * DD + d) << 12));
        const __half2* krow = (const __half2*)(g_kTh + (((size_t)b * DD + d) << 12));
        __syncthreads();
#pragma unroll
        for (int k = 0; k < 8; ++k) {
            int idx = tid + (k << 8);            // 0..2047 half2 pairs
            float2 q2 = __half22float2(qrow[idx]);
            float2 k2 = __half22float2(krow[idx]);
            int t0 = idx << 1;
            zs[(int)(__brev((unsigned)t0) >> 20)]       = make_float2(q2.x, k2.x);
            zs[(int)(__brev((unsigned)(t0 + 1)) >> 20)] = make_float2(q2.y, k2.y);
        }
        __syncthreads();
        fft_stages_r8(zs, tw, tid);
        for (int f = tid; f <= 2048; f += 256) {
            float2 Zf = zs[f];
            float2 Zc = zs[(4096 - f) & 4095];
            float Qr = 0.5f * (Zf.x + Zc.x);
            float Qi = 0.5f * (Zf.y - Zc.y);
            float Kr = 0.5f * (Zf.y + Zc.y);
            float Ki = 0.5f * (Zc.x - Zf.x);
            float2 a2 = acc[f];
            a2.x += Qr * Kr + Qi * Ki;
            a2.y += Qi * Kr - Qr * Ki;
            acc[f] = a2;
        }
    }
    __syncthreads();
    for (int f = tid; f <= 2048; f += 256) {
        atomicAdd(&g_S[b * 2049 + f].x, acc[f].x);
        atomicAdd(&g_S[b * 2049 + f].y, acc[f].y);
    }
}

// ---------------- inverse FFT + top-k + softmax ----------------
__global__ void ifft_topk_kernel() {
    extern __shared__ float2 sm[];
    float2* zs = sm;                       // 4096
    float2* tw = sm + 4096;                // 2048
    float*  mv = (float*)(sm + 6144);      // 4096

    __shared__ float red_v[256];
    __shared__ int   red_i[256];
    __shared__ float s_tv[TOPK];
    __shared__ int   s_ti[TOPK];

    int tid = threadIdx.x;
    int b = blockIdx.x;

    for (int j = tid; j < 2048; j += 256) tw[j] = g_tw[j];
    for (int f = tid; f < 4096; f += 256) {
        float2 s;
        if (f <= 2048) {
            s = g_S[b * 2049 + f];
            s.y = -s.y;                    // conj -> IFFT via forward FFT
        } else {
            s = g_S[b * 2049 + (4096 - f)];  // conj(S[N-f]) -> conj applied twice = raw
        }
        zs[(int)(__brev((unsigned)f) >> 20)] = s;
    }
    __syncthreads();
    fft_stages_r8(zs, tw, tid);

    const float scale = 1.0f / (4096.0f * 512.0f);
    for (int n = tid; n < 4096; n += 256) mv[n] = zs[n].x * scale;
    __syncthreads();

    for (int it = 0; it < TOPK; ++it) {
        float bv = -3.402823e38f; int bi = 1 << 30;
        for (int n = tid; n < 4096; n += 256) {
            float v = mv[n];
            if (v > bv || (v == bv && n < bi)) { bv = v; bi = n; }
        }
        red_v[tid] = bv; red_i[tid] = bi;
        __syncthreads();
        for (int s = 128; s > 0; s >>= 1) {
            if (tid < s) {
                float v2 = red_v[tid + s]; int i2 = red_i[tid + s];
                if (v2 > red_v[tid] || (v2 == red_v[tid] && i2 < red_i[tid])) {
                    red_v[tid] = v2; red_i[tid] = i2;
                }
            }
            __syncthreads();
        }
        if (tid == 0) {
            s_tv[it] = red_v[0]; s_ti[it] = red_i[0];
            mv[red_i[0]] = -3.402823e38f;
        }
        __syncthreads();
    }

    if (tid == 0) {
        float mx = s_tv[0];
        float ex[TOPK]; float sum = 0.f;
        for (int i = 0; i < TOPK; ++i) { ex[i] = expf(s_tv[i] - mx); sum += ex[i]; }
        for (int i = 0; i < TOPK; ++i) {
            g_w[b * TOPK + i] = ex[i] / sum;
            g_delay[b * TOPK + i] = s_ti[i];
        }
    }
}

// ---------------- final aggregation: out_s = x_s + sum_i w_i * roll(P, d_i) + bcomb ----------------
__global__ void final_agg(const float* __restrict__ xs, float* __restrict__ out) {
    size_t idx = (size_t)blockIdx.x * 256 + threadIdx.x;   // over B*L rows x 128 float4-groups
    int c = (int)(idx & 127);
    size_t row = idx >> 7;
    int b = (int)(row >> 12);
    int t = (int)(row & 4095);

    float wloc[TOPK]; int dloc[TOPK];
#pragma unroll
    for (int i = 0; i < TOPK; ++i) { wloc[i] = g_w[b * TOPK + i]; dloc[i] = g_delay[b * TOPK + i]; }

    float4 acc = *(const float4*)&g_bcomb[c << 2];
#pragma unroll
    for (int i = 0; i < TOPK; ++i) {
        int ts = (t + dloc[i]) & 4095;
        const uint2 raw = *(const uint2*)(g_P + (((size_t)(b << 12) + ts) << 9) + (c << 2));
        const __half2* p = (const __half2*)&raw;
        float2 f0 = __half22float2(p[0]);
        float2 f1 = __half22float2(p[1]);
        float w = wloc[i];
        acc.x += w * f0.x; acc.y += w * f0.y;
        acc.z += w * f1.x; acc.w += w * f1.y;
    }
    const float4 xv = *(const float4*)&xs[(row << 9) + (c << 2)];
    acc.x += xv.x; acc.y += xv.y; acc.z += xv.z; acc.w += xv.w;
    *(float4*)&out[(row << 9) + (c << 2)] = acc;
}

// ---------------- host launch ----------------
extern "C" void kernel_launch(void* const* d_in, const int* in_sizes, int n_in,
                              void* d_out, int out_size) {
    const float* x_s   = (const float*)d_in[0];
    const float* x_w   = (const float*)d_in[1];
    const float* Wq    = (const float*)d_in[2];
    const float* bq    = (const float*)d_in[3];
    const float* Wk    = (const float*)d_in[4];
    const float* bk    = (const float*)d_in[5];
    const float* Wv    = (const float*)d_in[6];
    const float* bv    = (const float*)d_in[7];
    const float* Wo    = (const float*)d_in[8];
    const float* bo    = (const float*)d_in[9];
    const float* Wconv = (const float*)d_in[10];

    float* out_s = (float*)d_out;
    float* out_w = out_s + BLD;

    void *p_xsf, *p_xwf, *p_P, *p_qTh, *p_kTh, *p_wqf, *p_wkf, *p_wcb, *p_wc;
    cudaGetSymbolAddress(&p_xsf, g_xsf); cudaGetSymbolAddress(&p_xwf, g_xwf);
    cudaGetSymbolAddress(&p_P, g_P);
    cudaGetSymbolAddress(&p_qTh, g_qTh); cudaGetSymbolAddress(&p_kTh, g_kTh);
    cudaGetSymbolAddress(&p_wqf, g_wqf); cudaGetSymbolAddress(&p_wkf, g_wkf);
    cudaGetSymbolAddress(&p_wcb, g_wcb); cudaGetSymbolAddress(&p_wc, g_wc);

    const int SMEM_GEMM = 3 * 16384 + 1024;      // 50176 (epi fp16 transpose fits inside)
    cudaFuncSetAttribute(mega_gemm, cudaFuncAttributeMaxDynamicSharedMemorySize, SMEM_GEMM);
    cudaFuncSetAttribute(fft_cross_kernel, cudaFuncAttributeMaxDynamicSharedMemorySize, 66560);
    cudaFuncSetAttribute(ifft_topk_kernel, cudaFuncAttributeMaxDynamicSharedMemorySize, 65536);

    // 1-4: init + weight combine + fp16 conversions
    init_tw_kernel<<<8, 256>>>();
    zero_S_kernel<<<65, 256>>>();
    wcomb_gemm<<<320, 256>>>(Wo, Wv, bv, bo);
    mega_split_kernel<<<11776, 256>>>((const float4*)x_s, (const float4*)x_w,
                                      (const float4*)Wq, (const float4*)Wk, Wconv);

    // 5: all four GEMMs in one launch (conv CTAs first for load balance)
    mega_gemm<<<4096, 256, SMEM_GEMM>>>(
        (const __half*)p_xsf, (const __half*)p_xwf,
        (const __half*)p_wqf, (const __half*)p_wkf,
        (const __half*)p_wcb, (const __half*)p_wc,
        bq, bk,
        out_w, (__half*)p_qTh, (__half*)p_kTh, (__half*)p_P);

    // 6-7: correlation spectrum + top-k delays
    fft_cross_kernel<<<512, 256, 66560>>>();
    ifft_topk_kernel<<<8, 256, 65536>>>();

    // 8: out_s = x_s + sum_i w_i * roll(P, d_i) + bcomb
    final_agg<<<16384, 256>>>(x_s, out_s);
}

// round 10
// speedup vs baseline: 5.5994x; 1.0733x over previous
#include <cuda_runtime.h>
#include <cuda_fp16.h>
#include <math.h>
#include <stdint.h>

// ---------------- problem constants ----------------
#define BB 8
#define LL 4096
#define DD 512
#define TOPK 8
#define NFFT 4096
static const size_t BLD = (size_t)BB * LL * DD;   // 16,777,216

// ---------------- device scratch ----------------
__device__ __half g_xsf[(size_t)BB * LL * DD];      // fp16 x_s
__device__ __half g_xwf[(size_t)BB * LL * DD];      // fp16 x_w
__device__ __half g_P  [(size_t)BB * LL * DD];      // x_s @ (Wo Wv)^T, fp16
__device__ __half g_qTh[(size_t)BB * DD * LL];      // q transposed [B,D,L] fp16
__device__ __half g_kTh[(size_t)BB * DD * LL];
__device__ __half g_wqf[DD * DD];
__device__ __half g_wkf[DD * DD];
__device__ __half g_wcb[DD * DD];          // fp16(Wo @ Wv)
__device__ __half g_wc [DD * 1536];        // conv weights relaid [n][kk*512+i]
__device__ float g_bcomb[DD];              // Wo @ bv + bo
__device__ float2 g_S[BB * 2049];          // Hermitian half-spectrum per batch
__device__ float2 g_tw[NFFT / 2];
__device__ float g_w[BB * TOPK];
__device__ int   g_delay[BB * TOPK];
__device__ int   g_cnt[BB];                // fft completion counters per batch

// ---------------- helpers ----------------
__device__ __forceinline__ uint32_t smem_u32(const void* p) {
    uint32_t a;
    asm("{ .reg .u64 t; cvta.to.shared.u64 t, %1; cvt.u32.u64 %0, t; }" : "=r"(a) : "l"(p));
    return a;
}

__device__ __forceinline__ void ldmx4(uint32_t* r, uint32_t addr) {
    asm volatile("ldmatrix.sync.aligned.m8n8.x4.shared.b16 {%0,%1,%2,%3}, [%4];"
                 : "=r"(r[0]), "=r"(r[1]), "=r"(r[2]), "=r"(r[3]) : "r"(addr));
}

__device__ __forceinline__ void mma_f16(float* d, const uint32_t* a, uint32_t b0, uint32_t b1) {
    asm volatile(
        "mma.sync.aligned.m16n8k16.row.col.f32.f16.f16.f32 "
        "{%0,%1,%2,%3}, {%4,%5,%6,%7}, {%8,%9}, {%0,%1,%2,%3};"
        : "+f"(d[0]), "+f"(d[1]), "+f"(d[2]), "+f"(d[3])
        : "r"(a[0]), "r"(a[1]), "r"(a[2]), "r"(a[3]), "r"(b0), "r"(b1));
}

#define CP_ASYNC16(dst, src) \
    asm volatile("cp.async.cg.shared.global [%0], [%1], 16;" :: "r"(dst), "l"(src))
#define CP_COMMIT() asm volatile("cp.async.commit_group;")
#define CP_WAIT2()  asm volatile("cp.async.wait_group 2;")
#define CP_WAIT1()  asm volatile("cp.async.wait_group 1;")
#define CP_WAIT0()  asm volatile("cp.async.wait_group 0;")

__device__ __forceinline__ uint32_t sw64(uint32_t off) {
    return off ^ ((off >> 3) & 0x30);
}

// ---------------- setup: twiddles + zero S/counters + Wcomb + bcomb ----------------
__global__ void setup_kernel(const float* __restrict__ Wo, const float* __restrict__ Wv,
                             const float* __restrict__ bv, const float* __restrict__ bo) {
    int blk = blockIdx.x;
    int tid = threadIdx.x;
    if (blk < 256) {
        // Wcomb tile 32x32 (fp32 accumulate, fp16 store)
        __shared__ float As[32][33], Bs[32][33];
        int bi = (blk >> 4) * 32, bj = (blk & 15) * 32;
        int tx = tid & 15, ty = tid >> 4;
        float a00 = 0.f, a01 = 0.f, a10 = 0.f, a11 = 0.f;
        for (int m0 = 0; m0 < 512; m0 += 32) {
            for (int r = ty; r < 32; r += 16) {
                As[r][tx]      = Wo[(bi + r) * 512 + m0 + tx];
                As[r][tx + 16] = Wo[(bi + r) * 512 + m0 + tx + 16];
                Bs[r][tx]      = Wv[(m0 + r) * 512 + bj + tx];
                Bs[r][tx + 16] = Wv[(m0 + r) * 512 + bj + tx + 16];
            }
            __syncthreads();
#pragma unroll
            for (int m = 0; m < 32; ++m) {
                float x0 = As[ty][m], x1 = As[ty + 16][m];
                float y0 = Bs[m][tx], y1 = Bs[m][tx + 16];
                a00 += x0 * y0; a01 += x0 * y1; a10 += x1 * y0; a11 += x1 * y1;
            }
            __syncthreads();
        }
        int i00 = (bi + ty) * 512 + bj + tx;
        int i10 = (bi + ty + 16) * 512 + bj + tx;
        g_wcb[i00] = __float2half_rn(a00);      g_wcb[i00 + 16] = __float2half_rn(a01);
        g_wcb[i10] = __float2half_rn(a10);      g_wcb[i10 + 16] = __float2half_rn(a11);
    } else if (blk < 320) {
        // bcomb: warp-per-output
        int o = (blk - 256) * 8 + (tid >> 5);
        int lane = tid & 31;
        float s = 0.f;
        for (int m = lane; m < 512; m += 32) s += Wo[o * 512 + m] * bv[m];
#pragma unroll
        for (int off = 16; off; off >>= 1) s += __shfl_xor_sync(0xFFFFFFFFu, s, off);
        if (lane == 0) g_bcomb[o] = s + bo[o];
    } else if (blk == 320) {
        for (int j = tid; j < 2048; j += 256) {
            float s, c;
            sincospif(-2.0f * (float)j / (float)NFFT, &s, &c);
            g_tw[j] = make_float2(c, s);
        }
    } else {
        int i = (blk - 321) * 256 + tid;
        if (i < BB * 2049) g_S[i] = make_float2(0.f, 0.f);
        if (blk == 321 && tid < BB) g_cnt[tid] = 0;
    }
}

// ---------------- split: fp32 -> fp16 for xs, xw, Wq, Wk + conv relay ----------------
__device__ __forceinline__ void cvt_one4(const float4* __restrict__ x,
                                         __half2* __restrict__ f, int i) {
    float4 v = x[i];
    f[2 * i]     = __floats2half2_rn(v.x, v.y);
    f[2 * i + 1] = __floats2half2_rn(v.z, v.w);
}

__global__ void mega_split_kernel(const float4* __restrict__ xs,
                                  const float4* __restrict__ xw,
                                  const float4* __restrict__ Wq,
                                  const float4* __restrict__ Wk,
                                  const float* __restrict__ Wconv) {
    int bid = blockIdx.x;
    int tid = threadIdx.x;
    if (bid < 4096) {
        int base = bid * 1024 + tid;
#pragma unroll
        for (int j = 0; j < 4; ++j) cvt_one4(xs, (__half2*)g_xsf, base + j * 256);
    } else if (bid < 8192) {
        int base = (bid - 4096) * 1024 + tid;
#pragma unroll
        for (int j = 0; j < 4; ++j) cvt_one4(xw, (__half2*)g_xwf, base + j * 256);
    } else if (bid < 8448) {
        cvt_one4(Wq, (__half2*)g_wqf, (bid - 8192) * 256 + tid);
    } else if (bid < 8704) {
        cvt_one4(Wk, (__half2*)g_wkf, (bid - 8448) * 256 + tid);
    } else {
        int idx = (bid - 8704) * 256 + tid;         // conv relay; over 512*1536
        int n = idx / 1536;
        int r = idx - n * 1536;
        int kk = r >> 9;
        int i = r & 511;
        g_wc[idx] = __float2half_rn(Wconv[((size_t)n * 512 + i) * 3 + kk]);
    }
}

// ---------------- shared fp16 GEMM mainloop ----------------
__device__ __forceinline__ void load_chunk16(
    int ch, int stage, int rowA, int rowB, bool conv, int m0, int n0, int tid, uint32_t sbase,
    const char* __restrict__ A, const char* __restrict__ B)
{
    uint32_t st = sbase + stage * 16384;
    int r = tid >> 1;
    int seg0 = (tid & 1) << 1;

    size_t abyte;
    if (conv) {
        int k0e = ch << 5;                 // element offset in logical K=1536 (fp16)
        int m = m0 + r;
        int kk = k0e >> 9;
        int ii = k0e & 511;
        int bb = m >> 12;
        int tt = ((m & 4095) + kk + 4095) & 4095;   // t + kk - 1 mod L
        abyte = ((((size_t)(bb << 12) + tt) << 9) + ii) * 2;
    } else {
        abyte = (size_t)(m0 + r) * rowA + (ch << 6);
    }
    size_t bbyte = (size_t)(n0 + r) * rowB + (ch << 6);

#pragma unroll
    for (int s2 = 0; s2 < 2; ++s2) {
        int seg = seg0 + s2;
        uint32_t soff = sw64((r << 6) + (seg << 4));
        CP_ASYNC16(st + soff, A + abyte + (seg << 4));
        CP_ASYNC16(st + 8192 + soff, B + bbyte + (seg << 4));
    }
    CP_COMMIT();
}

__device__ __forceinline__ void gemm_mainloop(
    float acc[4][4][4], const char* __restrict__ A, const char* __restrict__ B,
    int rowA, int rowB, int T, bool conv, int m0, int n0, int tid, uint32_t sbase)
{
    const int wid = tid >> 5;
    const int lane = tid & 31;
    const int wm = wid >> 2;
    const int wn = wid & 3;
    const int lrow = lane & 15;
    const int lseg = lane >> 4;

#pragma unroll
    for (int i = 0; i < 4; ++i)
#pragma unroll
        for (int j = 0; j < 4; ++j)
#pragma unroll
            for (int r = 0; r < 4; ++r) acc[i][j][r] = 0.f;

    load_chunk16(0, 0, rowA, rowB, conv, m0, n0, tid, sbase, A, B);
    load_chunk16(1, 1, rowA, rowB, conv, m0, n0, tid, sbase, A, B);
    load_chunk16(2, 2, rowA, rowB, conv, m0, n0, tid, sbase, A, B);

    int s = 0;
    for (int it = 0; it < T; ++it) {
        int rem = T - 1 - it;
        if (rem >= 2) { CP_WAIT2(); } else if (rem == 1) { CP_WAIT1(); } else { CP_WAIT0(); }
        __syncthreads();

        uint32_t st = sbase + s * 16384;
#pragma unroll
        for (int ks = 0; ks < 2; ++ks) {
            int cseg = (ks << 1) + lseg;
            uint32_t a[4][4], b2[2][4];
#pragma unroll
            for (int mt = 0; mt < 4; ++mt) {
                int row = (wm << 6) + (mt << 4) + lrow;
                ldmx4(a[mt], st + sw64((row << 6) + (cseg << 4)));
            }
#pragma unroll
            for (int bt = 0; bt < 2; ++bt) {
                int row = (wn << 5) + (bt << 4) + lrow;
                ldmx4(b2[bt], st + 8192 + sw64((row << 6) + (cseg << 4)));
            }
#pragma unroll
            for (int mt = 0; mt < 4; ++mt)
#pragma unroll
                for (int nt = 0; nt < 4; ++nt)
                    mma_f16(acc[mt][nt], a[mt],
                            b2[nt >> 1][nt & 1], b2[nt >> 1][(nt & 1) + 2]);
        }
        __syncthreads();
        if (it + 3 < T)
            load_chunk16(it + 3, s, rowA, rowB, conv, m0, n0, tid, sbase, A, B);
        s = (s == 2) ? 0 : s + 1;
    }
}

// ---------------- q/k GEMM (fp16, transposed fp16 output) ----------------
__global__ void __launch_bounds__(256, 2) qk_gemm(
    const float* __restrict__ bq, const float* __restrict__ bk)
{
    extern __shared__ char smraw[];
    uint32_t sbase = (smem_u32(smraw) + 1023u) & ~1023u;

    const int mode = blockIdx.x >> 10;     // 0 = q (x_w @ Wq), 1 = k (x_s @ Wk)
    const int rr = blockIdx.x & 1023;
    const int m0 = (rr >> 2) << 7;
    const int n0 = (rr & 3) << 7;
    const int tid = threadIdx.x;
    const int wid = tid >> 5;
    const int lane = tid & 31;
    const int wm = wid >> 2;
    const int wn = wid & 3;

    const char* A = (const char*)(mode ? g_xsf : g_xwf);
    const char* B = (const char*)(mode ? g_wkf : g_wqf);

    float acc[4][4][4];
    gemm_mainloop(acc, A, B, 1024, 1024, 16, false, m0, n0, tid, sbase);

    // fp16 transposed epilogue via smem into [B, D, L]
    const int er = lane >> 2;
    const int ec = (lane & 3) << 1;
    __half* sth = (__half*)smraw;
    const float* bias = mode ? bk : bq;
    __half* Cout = mode ? g_kTh : g_qTh;
#pragma unroll
    for (int mt = 0; mt < 4; ++mt)
#pragma unroll
        for (int nt = 0; nt < 4; ++nt) {
            int r0 = (wm << 6) + (mt << 4) + er;
            int c0 = (wn << 5) + (nt << 3) + ec;
            float b0v = bias[n0 + c0], b1v = bias[n0 + c0 + 1];
            sth[c0 * 136 + r0]            = __float2half_rn(acc[mt][nt][0] + b0v);
            sth[(c0 + 1) * 136 + r0]      = __float2half_rn(acc[mt][nt][1] + b1v);
            sth[c0 * 136 + r0 + 8]        = __float2half_rn(acc[mt][nt][2] + b0v);
            sth[(c0 + 1) * 136 + r0 + 8]  = __float2half_rn(acc[mt][nt][3] + b1v);
        }
    __syncthreads();
    int bb = m0 >> 12, l0 = m0 & 4095;
#pragma unroll
    for (int i = 0; i < 8; ++i) {
        int idx = tid + (i << 8);
        int c = idx >> 4;
        int g8 = (idx & 15) << 3;
        uint4 v = *(uint4*)&sth[c * 136 + g8];
        *(uint4*)&Cout[(((size_t)(bb << 9) + n0 + c) << 12) + l0 + g8] = v;
    }
}

// ---------------- fused radix-8 FFT (4 passes) ----------------
__device__ __forceinline__ float2 cmulf(float2 w, float2 z) {
    return make_float2(w.x * z.x - w.y * z.y, w.x * z.y + w.y * z.x);
}
__device__ __forceinline__ float2 mni(float2 u) { return make_float2(u.y, -u.x); }
__device__ __forceinline__ float2 rot45(float2 u) {
    const float r = 0.70710678118654752f;
    return make_float2(r * (u.x + u.y), r * (u.y - u.x));
}
__device__ __forceinline__ float2 cadd(float2 a, float2 b) { return make_float2(a.x + b.x, a.y + b.y); }
__device__ __forceinline__ float2 csub(float2 a, float2 b) { return make_float2(a.x - b.x, a.y - b.y); }

__device__ __forceinline__ void fft_stages_r8(float2* zs, const float2* tw, int tid) {
#pragma unroll
    for (int p = 0; p < 4; ++p) {
        const int h = 1 << (3 * p);
#pragma unroll
        for (int jj = 0; jj < 2; ++jj) {
            int j = tid + (jj << 8);
            int pos = j & (h - 1);
            int grp = j >> (3 * p);
            int base = (grp << (3 * p + 3)) + pos;
            float2 x0 = zs[base],         x1 = zs[base + h];
            float2 x2 = zs[base + 2 * h], x3 = zs[base + 3 * h];
            float2 x4 = zs[base + 4 * h], x5 = zs[base + 5 * h];
            float2 x6 = zs[base + 6 * h], x7 = zs[base + 7 * h];
            float2 wA = tw[pos << (11 - 3 * p)];
            float2 wB = tw[pos << (10 - 3 * p)];
            float2 wC = tw[pos << (9 - 3 * p)];
            float2 t;
            t = cmulf(wA, x1); float2 a0 = cadd(x0, t), a1 = csub(x0, t);
            t = cmulf(wA, x3); float2 a2 = cadd(x2, t), a3 = csub(x2, t);
            t = cmulf(wA, x5); float2 a4 = cadd(x4, t), a5 = csub(x4, t);
            t = cmulf(wA, x7); float2 a6 = cadd(x6, t), a7 = csub(x6, t);
            t = cmulf(wB, a2);      float2 b0 = cadd(a0, t), b2 = csub(a0, t);
            t = mni(cmulf(wB, a3)); float2 b1 = cadd(a1, t), b3 = csub(a1, t);
            t = cmulf(wB, a6);      float2 b4 = cadd(a4, t), b6 = csub(a4, t);
            t = mni(cmulf(wB, a7)); float2 b5 = cadd(a5, t), b7 = csub(a5, t);
            t = cmulf(wC, b4);             zs[base]         = cadd(b0, t); zs[base + 4 * h] = csub(b0, t);
            t = rot45(cmulf(wC, b5));      zs[base + h]     = cadd(b1, t); zs[base + 5 * h] = csub(b1, t);
            t = mni(cmulf(wC, b6));        zs[base + 2 * h] = cadd(b2, t); zs[base + 6 * h] = csub(b2, t);
            t = mni(rot45(cmulf(wC, b7))); zs[base + 3 * h] = cadd(b3, t); zs[base + 7 * h] = csub(b3, t);
        }
        __syncthreads();
    }
}

// ---------------- combo: fft_cross (512 CTAs, interleaved) + conv/P GEMM (2048 CTAs) ----------------
// bid < 2048 with (bid & 3) == 3 -> fft CTA (fidx = bid >> 2); otherwise GEMM.
// Last fft CTA per batch runs IFFT + top-k inline.
__global__ void __launch_bounds__(256, 2) combo_kernel(float* __restrict__ out_w)
{
    extern __shared__ char smraw[];
    const int bid = blockIdx.x;
    const int tid = threadIdx.x;

    if (bid < 2048 && (bid & 3) == 3) {
        // ---------------- fft_cross part ----------------
        float2* sm = (float2*)smraw;
        float2* zs  = sm;            // 4096
        float2* tw  = sm + 4096;     // 2048
        float2* acc = sm + 6144;     // 2049

        const int fidx = bid >> 2;
        const int b = fidx >> 6;
        const int dg = (fidx & 63) << 3;

        for (int j = tid; j < 2048; j += 256) tw[j] = g_tw[j];
        for (int f = tid; f <= 2048; f += 256) acc[f] = make_float2(0.f, 0.f);

        for (int c = 0; c < 8; ++c) {
            int d = dg + c;
            const __half2* qrow = (const __half2*)(g_qTh + (((size_t)b * DD + d) << 12));
            const __half2* krow = (const __half2*)(g_kTh + (((size_t)b * DD + d) << 12));
            __syncthreads();
#pragma unroll
            for (int k = 0; k < 8; ++k) {
                int idx = tid + (k << 8);
                float2 q2 = __half22float2(qrow[idx]);
                float2 k2 = __half22float2(krow[idx]);
                int t0 = idx << 1;
                zs[(int)(__brev((unsigned)t0) >> 20)]       = make_float2(q2.x, k2.x);
                zs[(int)(__brev((unsigned)(t0 + 1)) >> 20)] = make_float2(q2.y, k2.y);
            }
            __syncthreads();
            fft_stages_r8(zs, tw, tid);
            for (int f = tid; f <= 2048; f += 256) {
                float2 Zf = zs[f];
                float2 Zc = zs[(4096 - f) & 4095];
                float Qr = 0.5f * (Zf.x + Zc.x);
                float Qi = 0.5f * (Zf.y - Zc.y);
                float Kr = 0.5f * (Zf.y + Zc.y);
                float Ki = 0.5f * (Zc.x - Zf.x);
                float2 a2 = acc[f];
                a2.x += Qr * Kr + Qi * Ki;
                a2.y += Qi * Kr - Qr * Ki;
                acc[f] = a2;
            }
        }
        __syncthreads();
        for (int f = tid; f <= 2048; f += 256) {
            atomicAdd(&g_S[b * 2049 + f].x, acc[f].x);
            atomicAdd(&g_S[b * 2049 + f].y, acc[f].y);
        }

        // ---------------- last-block: inline IFFT + top-k for this batch ----------------
        __shared__ int s_flag;
        __syncthreads();
        if (tid == 0) {
            __threadfence();
            int old = atomicAdd(&g_cnt[b], 1);
            s_flag = (old == 63) ? 1 : 0;
        }
        __syncthreads();
        if (!s_flag) return;
        __threadfence();

        float* mv = (float*)(sm + 6144);   // reuse acc region (4096 floats)

        for (int f = tid; f < 4096; f += 256) {
            float2 sv;
            if (f <= 2048) {
                sv = g_S[b * 2049 + f];
                sv.y = -sv.y;              // conj -> IFFT via forward FFT
            } else {
                sv = g_S[b * 2049 + (4096 - f)];
            }
            zs[(int)(__brev((unsigned)f) >> 20)] = sv;
        }
        __syncthreads();
        fft_stages_r8(zs, tw, tid);

        const float scale = 1.0f / (4096.0f * 512.0f);
        for (int n = tid; n < 4096; n += 256) mv[n] = zs[n].x * scale;
        __syncthreads();

        __shared__ float red_v[256];
        __shared__ int   red_i[256];
        __shared__ float s_tv[TOPK];
        __shared__ int   s_ti[TOPK];

        for (int it = 0; it < TOPK; ++it) {
            float bv = -3.402823e38f; int bi = 1 << 30;
            for (int n = tid; n < 4096; n += 256) {
                float v = mv[n];
                if (v > bv || (v == bv && n < bi)) { bv = v; bi = n; }
            }
            red_v[tid] = bv; red_i[tid] = bi;
            __syncthreads();
            for (int s = 128; s > 0; s >>= 1) {
                if (tid < s) {
                    float v2 = red_v[tid + s]; int i2 = red_i[tid + s];
                    if (v2 > red_v[tid] || (v2 == red_v[tid] && i2 < red_i[tid])) {
                        red_v[tid] = v2; red_i[tid] = i2;
                    }
                }
                __syncthreads();
            }
            if (tid == 0) {
                s_tv[it] = red_v[0]; s_ti[it] = red_i[0];
                mv[red_i[0]] = -3.402823e38f;
            }
            __syncthreads();
        }

        if (tid == 0) {
            float mx = s_tv[0];
            float ex[TOPK]; float sum = 0.f;
            for (int i = 0; i < TOPK; ++i) { ex[i] = expf(s_tv[i] - mx); sum += ex[i]; }
            for (int i = 0; i < TOPK; ++i) {
                g_w[b * TOPK + i] = ex[i] / sum;
                g_delay[b * TOPK + i] = s_ti[i];
            }
        }
        return;
    }

    // ---------------- GEMM part: conv (gidx < 1024) or P ----------------
    uint32_t sbase = (smem_u32(smraw) + 1023u) & ~1023u;
    int gidx = (bid < 2048) ? (bid - (bid >> 2)) : (1536 + (bid - 2048));
    const bool is_conv = (gidx < 1024);
    const int rr = gidx & 1023;
    const int m0 = (rr >> 2) << 7;
    const int n0 = (rr & 3) << 7;
    const int wid = tid >> 5;
    const int lane = tid & 31;
    const int wm = wid >> 2;
    const int wn = wid & 3;

    float acc[4][4][4];
    if (is_conv) {
        gemm_mainloop(acc, (const char*)g_xwf, (const char*)g_wc, 1024, 3072, 48, true,
                      m0, n0, tid, sbase);
    } else {
        gemm_mainloop(acc, (const char*)g_xsf, (const char*)g_wcb, 1024, 1024, 16, false,
                      m0, n0, tid, sbase);
    }

    const int er = lane >> 2;
    const int ec = (lane & 3) << 1;
    if (is_conv) {
#pragma unroll
        for (int mt = 0; mt < 4; ++mt)
#pragma unroll
            for (int nt = 0; nt < 4; ++nt) {
                int r0 = m0 + (wm << 6) + (mt << 4) + er;
                int c0 = n0 + (wn << 5) + (nt << 3) + ec;
                size_t o0 = ((size_t)r0 << 9) + c0;
                size_t o1 = ((size_t)(r0 + 8) << 9) + c0;
                *(float2*)&out_w[o0] = make_float2(acc[mt][nt][0], acc[mt][nt][1]);
                *(float2*)&out_w[o1] = make_float2(acc[mt][nt][2], acc[mt][nt][3]);
            }
    } else {
#pragma unroll
        for (int mt = 0; mt < 4; ++mt)
#pragma unroll
            for (int nt = 0; nt < 4; ++nt) {
                int r0 = m0 + (wm << 6) + (mt << 4) + er;
                int c0 = n0 + (wn << 5) + (nt << 3) + ec;
                *(__half2*)&g_P[((size_t)r0 << 9) + c0] =
                    __floats2half2_rn(acc[mt][nt][0], acc[mt][nt][1]);
                *(__half2*)&g_P[((size_t)(r0 + 8) << 9) + c0] =
                    __floats2half2_rn(acc[mt][nt][2], acc[mt][nt][3]);
            }
    }
}

// ---------------- final aggregation: out_s = x_s + sum_i w_i * roll(P, d_i) + bcomb ----------------
__global__ void final_agg(const float* __restrict__ xs, float* __restrict__ out) {
    size_t idx = (size_t)blockIdx.x * 256 + threadIdx.x;
    int c = (int)(idx & 127);
    size_t row = idx >> 7;
    int b = (int)(row >> 12);
    int t = (int)(row & 4095);

    float wloc[TOPK]; int dloc[TOPK];
#pragma unroll
    for (int i = 0; i < TOPK; ++i) { wloc[i] = g_w[b * TOPK + i]; dloc[i] = g_delay[b * TOPK + i]; }

    float4 acc = *(const float4*)&g_bcomb[c << 2];
#pragma unroll
    for (int i = 0; i < TOPK; ++i) {
        int ts = (t + dloc[i]) & 4095;
        const uint2 raw = *(const uint2*)(g_P + (((size_t)(b << 12) + ts) << 9) + (c << 2));
        const __half2* p = (const __half2*)&raw;
        float2 f0 = __half22float2(p[0]);
        float2 f1 = __half22float2(p[1]);
        float w = wloc[i];
        acc.x += w * f0.x; acc.y += w * f0.y;
        acc.z += w * f1.x; acc.w += w * f1.y;
    }
    const float4 xv = *(const float4*)&xs[(row << 9) + (c << 2)];
    acc.x += xv.x; acc.y += xv.y; acc.z += xv.z; acc.w += xv.w;
    *(float4*)&out[(row << 9) + (c << 2)] = acc;
}

// ---------------- host launch ----------------
extern "C" void kernel_launch(void* const* d_in, const int* in_sizes, int n_in,
                              void* d_out, int out_size) {
    const float* x_s   = (const float*)d_in[0];
    const float* x_w   = (const float*)d_in[1];
    const float* Wq    = (const float*)d_in[2];
    const float* bq    = (const float*)d_in[3];
    const float* Wk    = (const float*)d_in[4];
    const float* bk    = (const float*)d_in[5];
    const float* Wv    = (const float*)d_in[6];
    const float* bv    = (const float*)d_in[7];
    const float* Wo    = (const float*)d_in[8];
    const float* bo    = (const float*)d_in[9];
    const float* Wconv = (const float*)d_in[10];

    float* out_s = (float*)d_out;
    float* out_w = out_s + BLD;

    const int SMEM_GEMM = 3 * 16384 + 1024;      // 50176
    const int SMEM_COMBO = 66560;                // fft path needs (4096+2048+2049)*8
    cudaFuncSetAttribute(qk_gemm, cudaFuncAttributeMaxDynamicSharedMemorySize, SMEM_GEMM);
    cudaFuncSetAttribute(combo_kernel, cudaFuncAttributeMaxDynamicSharedMemorySize, SMEM_COMBO);

    // 1: twiddles + zero spectrum/counters + Wcomb + bcomb
    setup_kernel<<<386, 256>>>(Wo, Wv, bv, bo);
    // 2: fp16 conversions + conv weight relay
    mega_split_kernel<<<11776, 256>>>((const float4*)x_s, (const float4*)x_w,
                                      (const float4*)Wq, (const float4*)Wk, Wconv);
    // 3: q and k projections (transposed fp16 outputs)
    qk_gemm<<<2048, 256, SMEM_GEMM>>>(bq, bk);
    // 4: fft_cross interleaved with conv + P GEMMs; last fft CTA per batch does IFFT+top-k
    combo_kernel<<<2560, 256, SMEM_COMBO>>>(out_w);
    // 5: out_s = x_s + sum_i w_i * roll(P, d_i) + bcomb
    final_agg<<<16384, 256>>>(x_s, out_s);
}